// round 6
// baseline (speedup 1.0000x reference)
#include <cuda_runtime.h>
#include <cuda_bf16.h>
#include <math.h>
#include <stdint.h>

// ---------------- problem constants ----------------
#define TT 256
#define BBATCH 64
#define HH 512
#define RRD 4
#define WWD 32
#define NND 64
#define HC 759          // HID_C
#define G4C 3036        // 4*HID_C
#define G4E 2048        // 4*H
#define KCC 887         // HC + R*W
#define KPAD 896
#define EPSF 1e-6f

// ---------------- device scratch (no allocs allowed) ----------------
__device__ float g_XWe[(size_t)TT * BBATCH * G4E];   // x @ Wih_e^T + b_e
__device__ float g_EWc[(size_t)TT * BBATCH * G4C];   // enc @ Wih_c[:, :H]^T + b_c
__device__ float g_enc[(size_t)TT * BBATCH * HH];    // encoder outputs
__device__ float g_he[2][BBATCH * HH];
__device__ float g_hc[2][BBATCH * HC];
__device__ float g_M[BBATCH * NND * WWD];
__device__ float g_u[BBATCH * NND];
__device__ float g_p[BBATCH * NND];
__device__ float g_ww[BBATCH * NND];
__device__ float g_L[BBATCH * NND * NND];
__device__ float g_wr[BBATCH * RRD * NND];
__device__ float g_rv[BBATCH * RRD * WWD];
__device__ unsigned g_barE;
__device__ unsigned g_barC;

__device__ __forceinline__ float sigmf_(float x) { return 1.f / (1.f + expf(-x)); }
__device__ __forceinline__ float softplusf_(float x) { return fmaxf(x, 0.f) + log1pf(expf(-fabsf(x))); }

// software grid barrier: all blocks co-resident (grid <= #SMs)
__device__ __forceinline__ void gbar(unsigned* ctr, unsigned target) {
    __syncthreads();
    if (threadIdx.x == 0) {
        __threadfence();
        atomicAdd(ctr, 1u);
        while (*(volatile unsigned*)ctr < target) { __nanosleep(32); }
        __threadfence();
    }
    __syncthreads();
}

// ---------------- init: zero all recurrent state ----------------
__global__ void init_states() {
    int i = blockIdx.x * blockDim.x + threadIdx.x;
    if (i == 0) { g_barE = 0u; g_barC = 0u; }
    if (i < 2 * BBATCH * HH) ((float*)g_he)[i] = 0.f;
    if (i < 2 * BBATCH * HC) ((float*)g_hc)[i] = 0.f;
    if (i < BBATCH * NND * WWD) g_M[i] = 0.f;
    if (i < BBATCH * NND) { g_u[i] = 0.f; g_p[i] = 0.f; g_ww[i] = 0.f; }
    if (i < BBATCH * NND * NND) g_L[i] = 0.f;
    if (i < BBATCH * RRD * NND) g_wr[i] = 0.f;
    if (i < BBATCH * RRD * WWD) g_rv[i] = 0.f;
}

// ---------------- big input-projection GEMMs (unchanged) ----------------
__global__ __launch_bounds__(256) void gemm_phase(const float* __restrict__ Ain,
                                                  const float* __restrict__ Wt,
                                                  const float* __restrict__ bias,
                                                  int phase) {
    const int Ncols = phase ? G4C : G4E;
    const int ldw   = phase ? 640 : 512;
    float* C        = phase ? g_EWc : g_XWe;
    const float* A  = phase ? g_enc : Ain;

    __shared__ float As[16][65];
    __shared__ float Bs[16][65];

    int tid = threadIdx.x;
    int m0 = blockIdx.x * 64;
    int n0 = blockIdx.y * 64;
    int tn = tid & 15, tm = tid >> 4;

    float acc[4][4];
#pragma unroll
    for (int i = 0; i < 4; i++)
#pragma unroll
        for (int j = 0; j < 4; j++) acc[i][j] = 0.f;

    for (int k0 = 0; k0 < 512; k0 += 16) {
#pragma unroll
        for (int i = 0; i < 4; i++) {
            int idx = tid + 256 * i;
            int mm = idx >> 4, kk = idx & 15;
            int m = m0 + mm;
            const float* arow;
            if (phase) arow = A + (size_t)m * 512;
            else { int t = m >> 6, b = m & 63; arow = A + ((size_t)b * TT + t) * 512; }
            As[kk][mm] = arow[k0 + kk];
        }
#pragma unroll
        for (int i = 0; i < 4; i++) {
            int idx = tid + 256 * i;
            int nn = idx >> 4, kk = idx & 15;
            int n = n0 + nn;
            Bs[kk][nn] = (n < Ncols) ? Wt[(size_t)n * ldw + k0 + kk] : 0.f;
        }
        __syncthreads();
#pragma unroll
        for (int k = 0; k < 16; k++) {
            float a[4], bv[4];
#pragma unroll
            for (int i = 0; i < 4; i++) { a[i] = As[k][tm * 4 + i]; bv[i] = Bs[k][tn * 4 + i]; }
#pragma unroll
            for (int i = 0; i < 4; i++)
#pragma unroll
                for (int j = 0; j < 4; j++) acc[i][j] += a[i] * bv[j];
        }
        __syncthreads();
    }
#pragma unroll
    for (int i = 0; i < 4; i++) {
        int m = m0 + tm * 4 + i;
#pragma unroll
        for (int j = 0; j < 4; j++) {
            int n = n0 + tn * 4 + j;
            if (n < Ncols) C[(size_t)m * Ncols + n] = acc[i][j] + bias[n];
        }
    }
}

// ---------------- persistent encoder: all 256 steps in one kernel ----------------
// 128 blocks x 256 threads. Block owns j-chunk of 4 (16 gate rows). Weights
// cached in smem once; cell state lives in a register.
__global__ __launch_bounds__(256, 1) void enc_persist(const float* __restrict__ Whh_e) {
    __shared__ float Wc[16][512];
    __shared__ float hs[32][65];
    __shared__ float gs[16][65];

    int tid = threadIdx.x;
    int j0 = blockIdx.x * 4;

    // one-time weight cache load
    for (int i = tid; i < 16 * 512; i += 256) {
        int lr = i >> 9, k = i & 511;
        int gate = lr >> 2, jj = lr & 3;
        Wc[lr][k] = Whh_e[(size_t)(gate * HH + j0 + jj) * HH + k];
    }

    int bb = tid & 31;
    int ry = tid >> 5;
    int lr0 = ry * 2;

    int bidx = tid & 63, jj_e = tid >> 6;   // elementwise mapping (fixed across steps)
    float creg = 0.f;                       // cell state in register
    unsigned target = 0;
    __syncthreads();

    for (int t = 0; t < TT; t++) {
        int par = t & 1;
        const float* hin = g_he[par];
        float* hout = g_he[par ^ 1];

        float acc[2][2];
#pragma unroll
        for (int i = 0; i < 2; i++)
#pragma unroll
            for (int r = 0; r < 2; r++) {
                int lr = lr0 + r;
                int gate = lr >> 2, jj = lr & 3;
                int bx = bb + i * 32;
                acc[i][r] = g_XWe[((size_t)t * BBATCH + bx) * G4E + gate * HH + j0 + jj];
            }

        for (int k0 = 0; k0 < HH; k0 += 32) {
#pragma unroll
            for (int i = 0; i < 8; i++) {
                int idx = tid + 256 * i;
                int bl = idx >> 5, kk = idx & 31;
                hs[kk][bl] = hin[bl * HH + k0 + kk];
            }
            __syncthreads();
#pragma unroll
            for (int k = 0; k < 32; k++) {
                float h0 = hs[k][bb], h1 = hs[k][bb + 32];
                float w0 = Wc[lr0][k0 + k], w1 = Wc[lr0 + 1][k0 + k];
                acc[0][0] += h0 * w0; acc[0][1] += h0 * w1;
                acc[1][0] += h1 * w0; acc[1][1] += h1 * w1;
            }
            __syncthreads();
        }
#pragma unroll
        for (int i = 0; i < 2; i++)
#pragma unroll
            for (int r = 0; r < 2; r++) gs[lr0 + r][bb + 32 * i] = acc[i][r];
        __syncthreads();

        // elementwise LSTM cell, c kept in register
        {
            int j = j0 + jj_e;
            float gi = gs[jj_e][bidx], gf = gs[4 + jj_e][bidx];
            float gg = gs[8 + jj_e][bidx], go = gs[12 + jj_e][bidx];
            float cn = sigmf_(gf) * creg + sigmf_(gi) * tanhf(gg);
            creg = cn;
            float hn = sigmf_(go) * tanhf(cn);
            hout[bidx * HH + j] = hn;
            g_enc[((size_t)t * BBATCH + bidx) * HH + j] = hn;
        }

        target += gridDim.x;
        gbar(&g_barE, target);
    }
}

// ---------------- persistent controller + fused DNC ----------------
// 127 blocks x 256 threads. Block owns j-chunk of 6 (24 gate rows), weights
// (Whh_c slice + Wih_c rv columns) cached in dynamic smem once. Blocks 0..63
// also run the DNC memory step for their batch between two grid barriers.
#define OFF_WC    0
#define OFF_HS    21504
#define OFF_GS    23584
#define OFF_LS    25144
#define OFF_MS    29304
#define OFF_XI    31416
#define OFF_WRS   31672
#define OFF_WRT   31928
#define OFF_US    32184
#define OFF_PS    32248
#define OFF_WWS   32312
#define OFF_AVEC  32376
#define OFF_CW    32440
#define OFF_WWN   32504
#define OFF_SU    32568
#define OFF_RNORM 32632
#define OFF_SIDX  32696
#define OFF_RKN   32760
#define OFF_WKN   32888
#define OFF_MODES 32920
#define OFF_RED   32936
#define OFF_KNORM 33000
#define OFF_SWW   33008
#define SMEM_CTRL_FLOATS 33016
#define SMEM_CTRL_BYTES  (SMEM_CTRL_FLOATS * 4)

__global__ __launch_bounds__(256, 1) void ctrl_persist(const float* __restrict__ Whh_c,
                                                       const float* __restrict__ Wih_c,
                                                       float* __restrict__ out) {
    extern __shared__ float dyn[];
    float* Wc = dyn + OFF_WC;     // [24][896]
    float* hs = dyn + OFF_HS;     // [32][65]
    float* gs = dyn + OFF_GS;     // [24][65]

    int tid = threadIdx.x;
    int j0 = blockIdx.x * 6;

    // one-time weight cache load (zero-padded beyond HC rows / KCC cols)
    for (int i = tid; i < 24 * KPAD; i += 256) {
        int lr = i / KPAD, k = i % KPAD;
        int gate = lr / 6, jj = lr % 6;
        int j = j0 + jj;
        float v = 0.f;
        if (j < HC && k < KCC) {
            int grow = gate * HC + j;
            v = (k < HH + 247) ? 0.f : 0.f;  // placeholder (overwritten below)
            v = (k < HC) ? Whh_c[(size_t)grow * HC + k]
                         : Wih_c[(size_t)grow * 640 + 512 + (k - HC)];
        }
        Wc[lr * KPAD + k] = v;
    }

    int bb = tid & 31;
    int ry = tid >> 5;
    int lr0 = ry * 3;

    float creg0 = 0.f, creg1 = 0.f;   // cell state in registers (e=tid, e=tid+256)
    unsigned target = 0;
    __syncthreads();

    for (int t = 0; t < TT; t++) {
        int par = t & 1;
        const float* hin = g_hc[par];
        float* hout = g_hc[par ^ 1];

        float acc[2][3];
#pragma unroll
        for (int i = 0; i < 2; i++)
#pragma unroll
            for (int r = 0; r < 3; r++) {
                int lr = lr0 + r;
                int gate = lr / 6, jj = lr % 6;
                int j = j0 + jj;
                int bx = bb + i * 32;
                acc[i][r] = (j < HC) ? g_EWc[((size_t)t * BBATCH + bx) * G4C + gate * HC + j] : 0.f;
            }

        for (int k0 = 0; k0 < KCC; k0 += 32) {
#pragma unroll
            for (int i = 0; i < 8; i++) {
                int idx = tid + 256 * i;
                int bl = idx >> 5, kk = idx & 31;
                int k = k0 + kk;
                float v = 0.f;
                if (k < HC) v = hin[bl * HC + k];
                else if (k < KCC) v = g_rv[bl * (RRD * WWD) + (k - HC)];
                hs[kk * 65 + bl] = v;
            }
            __syncthreads();
#pragma unroll
            for (int k = 0; k < 32; k++) {
                float h0 = hs[k * 65 + bb], h1 = hs[k * 65 + bb + 32];
#pragma unroll
                for (int r = 0; r < 3; r++) {
                    float w = Wc[(lr0 + r) * KPAD + k0 + k];
                    acc[0][r] += h0 * w;
                    acc[1][r] += h1 * w;
                }
            }
            __syncthreads();
        }
#pragma unroll
        for (int i = 0; i < 2; i++)
#pragma unroll
            for (int r = 0; r < 3; r++) gs[(lr0 + r) * 65 + bb + 32 * i] = acc[i][r];
        __syncthreads();

        // elementwise: 64 b x 6 j = 384 elems, cell state in registers
        {
            int e = tid;
            int bx = e & 63, jj = e >> 6;
            int j = j0 + jj;
            if (j < HC) {
                float gi = gs[jj * 65 + bx], gf = gs[(6 + jj) * 65 + bx];
                float gg = gs[(12 + jj) * 65 + bx], go = gs[(18 + jj) * 65 + bx];
                float cn = sigmf_(gf) * creg0 + sigmf_(gi) * tanhf(gg);
                creg0 = cn;
                float hn = sigmf_(go) * tanhf(cn);
                hout[bx * HC + j] = hn;
                if (j < HH) out[((size_t)bx * TT + t) * HH + j] = hn;
            }
            e = tid + 256;
            if (e < 384) {
                bx = e & 63; jj = e >> 6;
                j = j0 + jj;
                if (j < HC) {
                    float gi = gs[jj * 65 + bx], gf = gs[(6 + jj) * 65 + bx];
                    float gg = gs[(12 + jj) * 65 + bx], go = gs[(18 + jj) * 65 + bx];
                    float cn = sigmf_(gf) * creg1 + sigmf_(gi) * tanhf(gg);
                    creg1 = cn;
                    float hn = sigmf_(go) * tanhf(cn);
                    hout[bx * HC + j] = hn;
                    if (j < HH) out[((size_t)bx * TT + t) * HH + j] = hn;
                }
            }
        }

        target += gridDim.x;
        gbar(&g_barC, target);            // h fully written & visible

        // -------- fused DNC memory step (blocks 0..63, one per batch) --------
        if (blockIdx.x < 64) {
            int b = blockIdx.x;
            const float* h = g_hc[par ^ 1] + b * HC;
            float* Ls    = dyn + OFF_LS;      // [64][65]
            float* Ms    = dyn + OFF_MS;      // [64][33]
            float* xi    = dyn + OFF_XI;
            float* wrs   = dyn + OFF_WRS;     // [4][64]
            float* wrtmp = dyn + OFF_WRT;     // [4][64]
            float* us    = dyn + OFF_US;
            float* ps    = dyn + OFF_PS;
            float* wws   = dyn + OFF_WWS;
            float* avec  = dyn + OFF_AVEC;
            float* cwv   = dyn + OFF_CW;
            float* wwn   = dyn + OFF_WWN;
            float* su    = dyn + OFF_SU;
            float* rnorm = dyn + OFF_RNORM;
            int*   sidx  = (int*)(dyn + OFF_SIDX);
            float* rkn   = dyn + OFF_RKN;     // [4][32]
            float* wkn   = dyn + OFF_WKN;
            float* modes = dyn + OFF_MODES;   // [4][4] (stride 4)
            float* red   = dyn + OFF_RED;
            float* knorm = dyn + OFF_KNORM;
            float* sww   = dyn + OFF_SWW;

            for (int i = tid; i < 4096; i += 256) Ls[(i >> 6) * 65 + (i & 63)] = g_L[b * 4096 + i];
            for (int i = tid; i < 2048; i += 256) Ms[(i >> 5) * 33 + (i & 31)] = g_M[b * 2048 + i];
            wrs[tid] = g_wr[b * 256 + tid];
            if (tid < 64) { us[tid] = g_u[b * 64 + tid]; ps[tid] = g_p[b * 64 + tid]; wws[tid] = g_ww[b * 64 + tid]; }
            if (tid < 247) {
                float v = h[HH + tid];
                float a;
                if (tid < 128)      a = tanhf(v);
                else if (tid < 132) a = softplusf_(v);
                else if (tid < 164) a = tanhf(v);
                else if (tid < 165) a = softplusf_(v);
                else if (tid < 197) a = sigmf_(v);
                else if (tid < 229) a = tanhf(v);
                else if (tid < 235) a = sigmf_(v);
                else                a = v;
                xi[tid] = a;
            }
            __syncthreads();

            if (tid < 4) {
                float s = EPSF;
                for (int w = 0; w < 32; w++) { float k = xi[tid * 32 + w]; s += k * k; }
                knorm[tid] = rsqrtf(s);
            } else if (tid == 4) {
                float s = EPSF;
                for (int w = 0; w < 32; w++) { float k = xi[132 + w]; s += k * k; }
                knorm[4] = rsqrtf(s);
            } else if (tid >= 8 && tid < 12) {
                int r = tid - 8;
                float m0 = xi[235 + 3 * r], m1 = xi[236 + 3 * r], m2 = xi[237 + 3 * r];
                float mx = fmaxf(m0, fmaxf(m1, m2));
                float e0 = expf(m0 - mx), e1 = expf(m1 - mx), e2 = expf(m2 - mx);
                float inv = 1.f / (e0 + e1 + e2);
                modes[r * 4 + 0] = e0 * inv; modes[r * 4 + 1] = e1 * inv; modes[r * 4 + 2] = e2 * inv;
            }
            __syncthreads();
            if (tid < 128)      { int r = tid >> 5, w = tid & 31; rkn[r * 32 + w] = xi[r * 32 + w] * knorm[r]; }
            else if (tid < 160) { int w = tid - 128; wkn[w] = xi[132 + w] * knorm[4]; }

            if (tid < 64) {
                float psi = 1.f;
#pragma unroll
                for (int r = 0; r < 4; r++) psi *= (1.f - xi[229 + r] * wrs[r * 64 + tid]);
                float un = (us[tid] + wws[tid] - us[tid] * wws[tid]) * psi;
                us[tid] = un; su[tid] = un; sidx[tid] = tid;
            }
            __syncthreads();

            for (int k = 2; k <= 64; k <<= 1)
                for (int j = k >> 1; j > 0; j >>= 1) {
                    if (tid < 64) {
                        int ixj = tid ^ j;
                        if (ixj > tid) {
                            float av = su[tid], bv = su[ixj];
                            int ai = sidx[tid], bi = sidx[ixj];
                            bool up = ((tid & k) == 0);
                            bool gt = (av > bv) || (av == bv && ai > bi);
                            if (gt == up) { su[tid] = bv; su[ixj] = av; sidx[tid] = bi; sidx[ixj] = ai; }
                        }
                    }
                    __syncthreads();
                }

            if (tid == 0) {
                float cp = 1.f;
                for (int k = 0; k < 64; k++) { avec[sidx[k]] = (1.f - su[k]) * cp; cp *= su[k]; }
            }
            if (tid >= 64 && tid < 128) {
                int n = tid - 64;
                float s = EPSF;
                for (int w = 0; w < 32; w++) { float m = Ms[n * 33 + w]; s += m * m; }
                rnorm[n] = rsqrtf(s);
            }
            __syncthreads();

            float wstr = xi[164];
            if (tid < 64) {
                float d = 0.f;
                for (int w = 0; w < 32; w++) d += wkn[w] * Ms[tid * 33 + w];
                cwv[tid] = d * rnorm[tid] * wstr;
            }
            __syncthreads();
            if (tid < 64) red[tid] = cwv[tid];
            __syncthreads();
            if (tid < 32) {
                float x = fmaxf(red[tid], red[tid + 32]);
                for (int s = 16; s; s >>= 1) x = fmaxf(x, __shfl_xor_sync(0xffffffffu, x, s));
                if (tid == 0) red[0] = x;
            }
            __syncthreads();
            float cmx = red[0];
            __syncthreads();
            float ev = (tid < 64) ? expf(cwv[tid] - cmx) : 0.f;
            if (tid < 64) red[tid] = ev;
            __syncthreads();
            if (tid < 32) {
                float x = red[tid] + red[tid + 32];
                for (int s = 16; s; s >>= 1) x += __shfl_xor_sync(0xffffffffu, x, s);
                if (tid == 0) red[0] = x;
            }
            __syncthreads();
            if (tid < 64) cwv[tid] = ev / red[0];
            __syncthreads();

            float ag = xi[233], wg = xi[234];
            if (tid < 64) wwn[tid] = wg * (ag * avec[tid] + (1.f - ag) * cwv[tid]);
            __syncthreads();

            if (tid < 64) red[tid] = wwn[tid];
            __syncthreads();
            if (tid < 32) {
                float x = red[tid] + red[tid + 32];
                for (int s = 16; s; s >>= 1) x += __shfl_xor_sync(0xffffffffu, x, s);
                if (tid == 0) sww[0] = x;
            }

            for (int i = tid; i < 2048; i += 256) {
                int n = i >> 5, w = i & 31;
                float m = Ms[n * 33 + w];
                m = m * (1.f - wwn[n] * xi[165 + w]) + wwn[n] * xi[197 + w];
                Ms[n * 33 + w] = m;
                g_M[b * 2048 + i] = m;
            }
            for (int i = tid; i < 4096; i += 256) {
                int ii = i >> 6, jj = i & 63;
                float lv = (ii == jj) ? 0.f
                         : ((1.f - wwn[ii] - wwn[jj]) * Ls[ii * 65 + jj] + wwn[ii] * ps[jj]);
                Ls[ii * 65 + jj] = lv;
                g_L[b * 4096 + i] = lv;
            }
            __syncthreads();

            if (tid < 64) {
                float pn = (1.f - sww[0]) * ps[tid] + wwn[tid];
                ps[tid] = pn;
                g_p[b * 64 + tid] = pn;
                g_u[b * 64 + tid] = us[tid];
                g_ww[b * 64 + tid] = wwn[tid];
            }
            if (tid >= 64 && tid < 128) {
                int n = tid - 64;
                float s = EPSF;
                for (int w = 0; w < 32; w++) { float m = Ms[n * 33 + w]; s += m * m; }
                rnorm[n] = rsqrtf(s);
            }
            __syncthreads();

            int rr = tid >> 6, nn = tid & 63;
            float pre;
            {
                float d = 0.f;
                for (int w = 0; w < 32; w++) d += rkn[rr * 32 + w] * Ms[nn * 33 + w];
                pre = d * rnorm[nn] * xi[128 + rr];
            }
            float x = pre;
            for (int s = 16; s; s >>= 1) x = fmaxf(x, __shfl_xor_sync(0xffffffffu, x, s));
            if ((tid & 31) == 0) red[tid >> 5] = x;
            __syncthreads();
            float gmx = fmaxf(red[rr * 2], red[rr * 2 + 1]);
            float e = expf(pre - gmx);
            __syncthreads();
            x = e;
            for (int s = 16; s; s >>= 1) x += __shfl_xor_sync(0xffffffffu, x, s);
            if ((tid & 31) == 0) red[tid >> 5] = x;
            __syncthreads();
            float crv = e / (red[rr * 2] + red[rr * 2 + 1]);

            {
                float fwv = 0.f, bwv = 0.f;
                const float* wrow = wrs + rr * 64;
                for (int m = 0; m < 64; m++) {
                    float wv = wrow[m];
                    fwv += Ls[nn * 65 + m] * wv;
                    bwv += Ls[m * 65 + nn] * wv;
                }
                wrtmp[rr * 64 + nn] = modes[rr * 4 + 0] * bwv + modes[rr * 4 + 1] * crv + modes[rr * 4 + 2] * fwv;
            }
            __syncthreads();

            g_wr[b * 256 + tid] = wrtmp[tid];
            if (tid < 128) {
                int r = tid >> 5, w = tid & 31;
                float s = 0.f;
                for (int n = 0; n < 64; n++) s += wrtmp[r * 64 + n] * Ms[n * 33 + w];
                g_rv[b * (RRD * WWD) + r * 32 + w] = s;
            }
        }

        target += gridDim.x;
        gbar(&g_barC, target);            // rv / DNC state visible to all
    }
}

// ---------------- launch ----------------
extern "C" void kernel_launch(void* const* d_in, const int* in_sizes, int n_in,
                              void* d_out, int out_size) {
    (void)in_sizes; (void)n_in; (void)out_size;
    const float* x     = (const float*)d_in[0];
    const float* Wih_e = (const float*)d_in[1];
    const float* Whh_e = (const float*)d_in[2];
    const float* b_e   = (const float*)d_in[3];
    const float* Wih_c = (const float*)d_in[4];
    const float* Whh_c = (const float*)d_in[5];
    const float* b_c   = (const float*)d_in[6];
    float* out = (float*)d_out;

    static int smem_set = 0;
    if (!smem_set) {
        cudaFuncSetAttribute(ctrl_persist, cudaFuncAttributeMaxDynamicSharedMemorySize,
                             SMEM_CTRL_BYTES);
        smem_set = 1;
    }

    init_states<<<1024, 256>>>();

    // Phase A: x @ Wih_e^T + b_e for all (t,b)
    gemm_phase<<<dim3(256, 32), 256>>>(x, Wih_e, b_e, 0);

    // Encoder recurrence — one persistent kernel
    enc_persist<<<128, 256>>>(Whh_e);

    // Phase C: enc @ Wih_c[:, :512]^T + b_c for all (t,b)
    gemm_phase<<<dim3(256, 48), 256>>>(nullptr, Wih_c, b_c, 1);

    // Controller + DNC recurrence — one persistent kernel
    ctrl_persist<<<127, 256, SMEM_CTRL_BYTES>>>(Whh_c, Wih_c, out);
}

// round 7
// speedup vs baseline: 2.4067x; 2.4067x over previous
#include <cuda_runtime.h>
#include <math.h>
#include <stdint.h>

// ---------------- problem constants ----------------
#define TT 256
#define BBATCH 64
#define HH 512
#define HC 759          // HID_C
#define G4C 3036        // 4*HID_C
#define G4E 2048        // 4*H
#define KCC 887         // HC + R*W
#define KPAD 896        // 14 * 64
#define EPSF 1e-6f

// ---------------- device scratch ----------------
__device__ float g_XWe[(size_t)TT * BBATCH * G4E];
__device__ float g_EWc[(size_t)TT * BBATCH * G4C];
__device__ float g_enc[(size_t)TT * BBATCH * HH];
__device__ float g_he[2][BBATCH * HH];
__device__ float g_hc[2][BBATCH * HC];
__device__ float g_rv[BBATCH * 128];
__device__ unsigned g_barE;
__device__ unsigned g_barC;

__device__ __forceinline__ float sigmf_(float x) { return 1.f / (1.f + expf(-x)); }
__device__ __forceinline__ float softplusf_(float x) { return fmaxf(x, 0.f) + log1pf(expf(-fabsf(x))); }

// software grid barrier (all blocks co-resident, grid <= #SMs)
__device__ __forceinline__ void gbar(unsigned* ctr, unsigned target) {
    __syncthreads();
    if (threadIdx.x == 0) {
        __threadfence();
        atomicAdd(ctr, 1u);
        while (*(volatile unsigned*)ctr < target) { __nanosleep(32); }
        __threadfence();
    }
    __syncthreads();
}

// ---------------- init ----------------
__global__ void init_states() {
    int i = blockIdx.x * blockDim.x + threadIdx.x;
    if (i == 0) { g_barE = 0u; g_barC = 0u; }
    if (i < 2 * BBATCH * HH) ((float*)g_he)[i] = 0.f;
    if (i < 2 * BBATCH * HC) ((float*)g_hc)[i] = 0.f;
    if (i < BBATCH * 128)    g_rv[i] = 0.f;
}

// ---------------- big input-projection GEMMs ----------------
__global__ __launch_bounds__(256) void gemm_phase(const float* __restrict__ Ain,
                                                  const float* __restrict__ Wt,
                                                  const float* __restrict__ bias,
                                                  int phase) {
    const int Ncols = phase ? G4C : G4E;
    const int ldw   = phase ? 640 : 512;
    float* C        = phase ? g_EWc : g_XWe;
    const float* A  = phase ? g_enc : Ain;

    __shared__ float As[16 * 68];
    __shared__ float Bs[16 * 68];

    int tid = threadIdx.x;
    int m0 = blockIdx.x * 64;
    int n0 = blockIdx.y * 64;
    int tn = tid & 15, tm = tid >> 4;

    float acc[4][4];
#pragma unroll
    for (int i = 0; i < 4; i++)
#pragma unroll
        for (int j = 0; j < 4; j++) acc[i][j] = 0.f;

    for (int k0 = 0; k0 < 512; k0 += 16) {
#pragma unroll
        for (int i = 0; i < 4; i++) {
            int idx = tid + 256 * i;
            int mm = idx >> 4, kk = idx & 15;
            int m = m0 + mm;
            const float* arow;
            if (phase) arow = A + (size_t)m * 512;
            else { int t = m >> 6, b = m & 63; arow = A + ((size_t)b * TT + t) * 512; }
            As[kk * 68 + mm] = arow[k0 + kk];
        }
#pragma unroll
        for (int i = 0; i < 4; i++) {
            int idx = tid + 256 * i;
            int nn = idx >> 4, kk = idx & 15;
            int n = n0 + nn;
            Bs[kk * 68 + nn] = (n < Ncols) ? Wt[(size_t)n * ldw + k0 + kk] : 0.f;
        }
        __syncthreads();
#pragma unroll
        for (int k = 0; k < 16; k++) {
            float4 a4 = *(const float4*)&As[k * 68 + tm * 4];
            float4 b4 = *(const float4*)&Bs[k * 68 + tn * 4];
            float a[4] = {a4.x, a4.y, a4.z, a4.w};
            float bv[4] = {b4.x, b4.y, b4.z, b4.w};
#pragma unroll
            for (int i = 0; i < 4; i++)
#pragma unroll
                for (int j = 0; j < 4; j++) acc[i][j] += a[i] * bv[j];
        }
        __syncthreads();
    }
#pragma unroll
    for (int i = 0; i < 4; i++) {
        int m = m0 + tm * 4 + i;
#pragma unroll
        for (int j = 0; j < 4; j++) {
            int n = n0 + tn * 4 + j;
            if (n < Ncols) C[(size_t)m * Ncols + n] = acc[i][j] + bias[n];
        }
    }
}

// ---------------- persistent encoder: 128 blocks x 512 threads ----------------
#define E_WC 0                 // 16*512
#define E_HS 8192              // 2*64*66
#define E_GS 16640             // 2*16*65
#define E_FLOATS 18720
#define E_BYTES (E_FLOATS * 4)

__global__ __launch_bounds__(512, 1) void enc_persist(const float* __restrict__ Whh_e) {
    extern __shared__ float dyn[];
    float* Wc = dyn + E_WC;
    float* hs = dyn + E_HS;
    float* gs = dyn + E_GS;

    int tid = threadIdx.x;
    int j0 = blockIdx.x * 4;

    for (int i = tid; i < 16 * 512; i += 512) {
        int lr = i >> 9, k = i & 511;
        int gate = lr >> 2, jj = lr & 3;
        Wc[i] = Whh_e[(size_t)(gate * HH + j0 + jj) * HH + k];
    }

    int g = tid >> 8;          // k-split group
    int t256 = tid & 255;
    int bb = t256 & 31;        // batches 2bb, 2bb+1
    int ry = t256 >> 5;        // 0..7
    int lr0 = ry * 2;
    int kbase = g * 32;
    int kkr = tid & 63, blr = tid >> 6;      // staging mapping
    int ebx = tid & 63, ejj = tid >> 6;      // elementwise (tid<256)
    float creg = 0.f;
    unsigned target = 0;
    __syncthreads();

    for (int t = 0; t < TT; t++) {
        int par = t & 1;
        const float* hin = g_he[par];
        float* hout = g_he[par ^ 1];

        float acc[2][2] = {{0.f, 0.f}, {0.f, 0.f}};
        if (g == 0) {
#pragma unroll
            for (int i2 = 0; i2 < 2; i2++)
#pragma unroll
                for (int r = 0; r < 2; r++) {
                    int lr = lr0 + r;
                    int gate = lr >> 2, jj = lr & 3;
                    acc[i2][r] = g_XWe[((size_t)t * BBATCH + 2 * bb + i2) * G4E + gate * HH + j0 + jj];
                }
        }

        float rg[8];
#pragma unroll
        for (int i = 0; i < 8; i++) rg[i] = hin[(blr + 8 * i) * HH + kkr];
#pragma unroll
        for (int i = 0; i < 8; i++) hs[kkr * 66 + blr + 8 * i] = rg[i];
        __syncthreads();

        for (int c = 0; c < 8; c++) {
            if (c < 7) {
#pragma unroll
                for (int i = 0; i < 8; i++)
                    rg[i] = hin[(blr + 8 * i) * HH + (c + 1) * 64 + kkr];
            }
            const float* hsb = hs + (c & 1) * 4224;
            const float* wp0 = Wc + lr0 * 512 + c * 64 + kbase;
            const float* wp1 = wp0 + 512;
#pragma unroll
            for (int k4 = 0; k4 < 32; k4 += 4) {
                float4 w0 = *(const float4*)(wp0 + k4);
                float4 w1 = *(const float4*)(wp1 + k4);
                float wa0[4] = {w0.x, w0.y, w0.z, w0.w};
                float wa1[4] = {w1.x, w1.y, w1.z, w1.w};
#pragma unroll
                for (int jq = 0; jq < 4; jq++) {
                    float2 h2 = *(const float2*)(hsb + (kbase + k4 + jq) * 66 + 2 * bb);
                    acc[0][0] += h2.x * wa0[jq]; acc[0][1] += h2.x * wa1[jq];
                    acc[1][0] += h2.y * wa0[jq]; acc[1][1] += h2.y * wa1[jq];
                }
            }
            if (c < 7) {
                float* hsn = hs + ((c + 1) & 1) * 4224;
#pragma unroll
                for (int i = 0; i < 8; i++) hsn[kkr * 66 + blr + 8 * i] = rg[i];
            }
            __syncthreads();
        }

#pragma unroll
        for (int i2 = 0; i2 < 2; i2++)
#pragma unroll
            for (int r = 0; r < 2; r++)
                gs[g * 1040 + (lr0 + r) * 65 + 2 * bb + i2] = acc[i2][r];
        __syncthreads();

        if (tid < 256) {
            int j = j0 + ejj;
            float gi = gs[ejj * 65 + ebx]        + gs[1040 + ejj * 65 + ebx];
            float gf = gs[(4 + ejj) * 65 + ebx]  + gs[1040 + (4 + ejj) * 65 + ebx];
            float gg = gs[(8 + ejj) * 65 + ebx]  + gs[1040 + (8 + ejj) * 65 + ebx];
            float go = gs[(12 + ejj) * 65 + ebx] + gs[1040 + (12 + ejj) * 65 + ebx];
            float cn = sigmf_(gf) * creg + sigmf_(gi) * tanhf(gg);
            creg = cn;
            float hn = sigmf_(go) * tanhf(cn);
            hout[ebx * HH + j] = hn;
            g_enc[((size_t)t * BBATCH + ebx) * HH + j] = hn;
        }

        target += gridDim.x;
        gbar(&g_barE, target);
    }
}

// ---------------- persistent controller + fused DNC: 127 blocks x 512 threads ----------------
#define C_WC    0        // 24*896
#define C_HS    21504    // 2*64*66
#define C_GS    29952    // 2*24*65
#define C_LS    33072    // 64*65
#define C_MS    37232    // 64*33
#define C_WRS   39344    // 256
#define C_WRT   39600    // 256
#define C_US    39856
#define C_PS    39920
#define C_WWS   39984
#define C_XI    40048    // 256
#define C_AVEC  40304
#define C_CWV   40368
#define C_WWN   40432
#define C_SU    40496
#define C_RNORM 40560
#define C_SIDX  40624
#define C_RKN   40688    // 128
#define C_WKN   40816    // 32
#define C_MODES 40848    // 16
#define C_RED   40864    // 64
#define C_KNORM 40928
#define C_SWW   40936
#define C_FLOATS 40944
#define C_BYTES (C_FLOATS * 4)

__global__ __launch_bounds__(512, 1) void ctrl_persist(const float* __restrict__ Whh_c,
                                                       const float* __restrict__ Wih_c,
                                                       float* __restrict__ out) {
    extern __shared__ float dyn[];
    float* Wc    = dyn + C_WC;
    float* hs    = dyn + C_HS;
    float* gsv   = dyn + C_GS;
    float* Ls    = dyn + C_LS;
    float* Ms    = dyn + C_MS;
    float* wrs   = dyn + C_WRS;
    float* wrtmp = dyn + C_WRT;
    float* us    = dyn + C_US;
    float* ps    = dyn + C_PS;
    float* wws   = dyn + C_WWS;
    float* xi    = dyn + C_XI;
    float* avec  = dyn + C_AVEC;
    float* cwv   = dyn + C_CWV;
    float* wwn   = dyn + C_WWN;
    float* su    = dyn + C_SU;
    float* rnorm = dyn + C_RNORM;
    int*   sidx  = (int*)(dyn + C_SIDX);
    float* rkn   = dyn + C_RKN;
    float* wkn   = dyn + C_WKN;
    float* modes = dyn + C_MODES;
    float* red   = dyn + C_RED;
    float* knorm = dyn + C_KNORM;
    float* sww   = dyn + C_SWW;

    int tid = threadIdx.x;
    int j0 = blockIdx.x * 6;

    // one-time weight cache (zero-padded beyond HC rows / KCC cols)
    for (int i = tid; i < 24 * KPAD; i += 512) {
        int lr = i / KPAD, k = i - lr * KPAD;
        int gate = lr / 6, jj = lr - gate * 6;
        int j = j0 + jj;
        float v = 0.f;
        if (j < HC && k < KCC) {
            int grow = gate * HC + j;
            v = (k < HC) ? Whh_c[(size_t)grow * HC + k]
                         : Wih_c[(size_t)grow * 640 + 512 + (k - HC)];
        }
        Wc[i] = v;
    }
    // DNC state init (resident in smem for whole kernel)
    if (blockIdx.x < 64) {
        for (int i = tid; i < 64 * 65; i += 512) Ls[i] = 0.f;
        for (int i = tid; i < 64 * 33; i += 512) Ms[i] = 0.f;
        if (tid < 256) wrs[tid] = 0.f;
        if (tid < 64) { us[tid] = 0.f; ps[tid] = 0.f; wws[tid] = 0.f; }
    }

    int g = tid >> 8, t256 = tid & 255;
    int bb = t256 & 31, ry = t256 >> 5, lr0 = ry * 3;
    int kbase = g * 32;
    int kkr = tid & 63, blr = tid >> 6;
    int ebx = tid & 63, ejj = tid >> 6;      // elementwise (tid<384)
    float creg = 0.f;
    unsigned target = 0;

    int growA[3], jA[3];
#pragma unroll
    for (int r = 0; r < 3; r++) {
        int lr = lr0 + r;
        int gate = lr / 6, jj = lr - gate * 6;
        jA[r] = j0 + jj;
        growA[r] = gate * HC + jA[r];
    }
    __syncthreads();

    for (int t = 0; t < TT; t++) {
        int par = t & 1;
        const float* hin = g_hc[par];
        float* hout = g_hc[par ^ 1];

        float acc[2][3] = {{0.f,0.f,0.f},{0.f,0.f,0.f}};
        if (g == 0) {
#pragma unroll
            for (int i2 = 0; i2 < 2; i2++)
#pragma unroll
                for (int r = 0; r < 3; r++)
                    if (jA[r] < HC)
                        acc[i2][r] = g_EWc[((size_t)t * BBATCH + 2 * bb + i2) * G4C + growA[r]];
        }

        float rg[8];
        {
            int k = kkr;           // chunk 0
#pragma unroll
            for (int i = 0; i < 8; i++) {
                int bl = blr + 8 * i;
                rg[i] = (k < HC) ? hin[bl * HC + k] : g_rv[bl * 128 + (k - HC)];
            }
        }
#pragma unroll
        for (int i = 0; i < 8; i++) hs[kkr * 66 + blr + 8 * i] = rg[i];
        __syncthreads();

        for (int c = 0; c < 14; c++) {
            if (c < 13) {
                int k = (c + 1) * 64 + kkr;
#pragma unroll
                for (int i = 0; i < 8; i++) {
                    int bl = blr + 8 * i;
                    float v;
                    if (k < HC) v = hin[bl * HC + k];
                    else if (k < KCC) v = g_rv[bl * 128 + (k - HC)];
                    else v = 0.f;
                    rg[i] = v;
                }
            }
            const float* hsb = hs + (c & 1) * 4224;
            const float* wp0 = Wc + (lr0 + 0) * KPAD + c * 64 + kbase;
            const float* wp1 = Wc + (lr0 + 1) * KPAD + c * 64 + kbase;
            const float* wp2 = Wc + (lr0 + 2) * KPAD + c * 64 + kbase;
#pragma unroll
            for (int k4 = 0; k4 < 32; k4 += 4) {
                float4 w0 = *(const float4*)(wp0 + k4);
                float4 w1 = *(const float4*)(wp1 + k4);
                float4 w2 = *(const float4*)(wp2 + k4);
                float wa0[4] = {w0.x, w0.y, w0.z, w0.w};
                float wa1[4] = {w1.x, w1.y, w1.z, w1.w};
                float wa2[4] = {w2.x, w2.y, w2.z, w2.w};
#pragma unroll
                for (int jq = 0; jq < 4; jq++) {
                    float2 h2 = *(const float2*)(hsb + (kbase + k4 + jq) * 66 + 2 * bb);
                    acc[0][0] += h2.x * wa0[jq]; acc[0][1] += h2.x * wa1[jq]; acc[0][2] += h2.x * wa2[jq];
                    acc[1][0] += h2.y * wa0[jq]; acc[1][1] += h2.y * wa1[jq]; acc[1][2] += h2.y * wa2[jq];
                }
            }
            if (c < 13) {
                float* hsn = hs + ((c + 1) & 1) * 4224;
#pragma unroll
                for (int i = 0; i < 8; i++) hsn[kkr * 66 + blr + 8 * i] = rg[i];
            }
            __syncthreads();
        }

#pragma unroll
        for (int i2 = 0; i2 < 2; i2++)
#pragma unroll
            for (int r = 0; r < 3; r++)
                gsv[g * 1560 + (lr0 + r) * 65 + 2 * bb + i2] = acc[i2][r];
        __syncthreads();

        if (tid < 384) {
            int j = j0 + ejj;
            if (j < HC) {
                float gi = gsv[ejj * 65 + ebx]        + gsv[1560 + ejj * 65 + ebx];
                float gf = gsv[(6 + ejj) * 65 + ebx]  + gsv[1560 + (6 + ejj) * 65 + ebx];
                float gg = gsv[(12 + ejj) * 65 + ebx] + gsv[1560 + (12 + ejj) * 65 + ebx];
                float go = gsv[(18 + ejj) * 65 + ebx] + gsv[1560 + (18 + ejj) * 65 + ebx];
                float cn = sigmf_(gf) * creg + sigmf_(gi) * tanhf(gg);
                creg = cn;
                float hn = sigmf_(go) * tanhf(cn);
                hout[ebx * HC + j] = hn;
                if (j < HH) out[((size_t)ebx * TT + t) * HH + j] = hn;
            }
        }

        target += gridDim.x;
        gbar(&g_barC, target);              // h_t fully visible

        // ---------------- fused DNC memory step (blocks 0..63) ----------------
        if (blockIdx.x < 64) {
            int b = blockIdx.x;
            const float* h = g_hc[par ^ 1] + b * HC;

            if (tid < 247) {
                float v = h[HH + tid];
                float a;
                if (tid < 128)      a = tanhf(v);
                else if (tid < 132) a = softplusf_(v);
                else if (tid < 164) a = tanhf(v);
                else if (tid < 165) a = softplusf_(v);
                else if (tid < 197) a = sigmf_(v);
                else if (tid < 229) a = tanhf(v);
                else if (tid < 235) a = sigmf_(v);
                else                a = v;
                xi[tid] = a;
            }
            __syncthreads();

            if (tid < 4) {
                float s = EPSF;
                for (int w = 0; w < 32; w++) { float k = xi[tid * 32 + w]; s += k * k; }
                knorm[tid] = rsqrtf(s);
            } else if (tid == 4) {
                float s = EPSF;
                for (int w = 0; w < 32; w++) { float k = xi[132 + w]; s += k * k; }
                knorm[4] = rsqrtf(s);
            } else if (tid >= 8 && tid < 12) {
                int r = tid - 8;
                float m0 = xi[235 + 3 * r], m1 = xi[236 + 3 * r], m2 = xi[237 + 3 * r];
                float mx = fmaxf(m0, fmaxf(m1, m2));
                float e0 = expf(m0 - mx), e1 = expf(m1 - mx), e2 = expf(m2 - mx);
                float inv = 1.f / (e0 + e1 + e2);
                modes[r * 4 + 0] = e0 * inv; modes[r * 4 + 1] = e1 * inv; modes[r * 4 + 2] = e2 * inv;
            }
            if (tid >= 64 && tid < 128) {   // old-M row norms (overlapped)
                int n = tid - 64;
                float s = EPSF;
                for (int w = 0; w < 32; w++) { float m = Ms[n * 33 + w]; s += m * m; }
                rnorm[n] = rsqrtf(s);
            }
            __syncthreads();
            if (tid < 128)      { int r = tid >> 5, w = tid & 31; rkn[r * 32 + w] = xi[r * 32 + w] * knorm[r]; }
            else if (tid < 160) { int w = tid - 128; wkn[w] = xi[132 + w] * knorm[4]; }

            if (tid < 64) {
                float psi = 1.f;
#pragma unroll
                for (int r = 0; r < 4; r++) psi *= (1.f - xi[229 + r] * wrs[r * 64 + tid]);
                float un = (us[tid] + wws[tid] - us[tid] * wws[tid]) * psi;
                us[tid] = un; su[tid] = un; sidx[tid] = tid;
            }
            __syncthreads();

            // stable bitonic sort ascending on (u, idx)
            for (int k = 2; k <= 64; k <<= 1)
                for (int j = k >> 1; j > 0; j >>= 1) {
                    if (tid < 64) {
                        int ixj = tid ^ j;
                        if (ixj > tid) {
                            float av = su[tid], bv = su[ixj];
                            int ai = sidx[tid], bi = sidx[ixj];
                            bool up = ((tid & k) == 0);
                            bool gt = (av > bv) || (av == bv && ai > bi);
                            if (gt == up) { su[tid] = bv; su[ixj] = av; sidx[tid] = bi; sidx[ixj] = ai; }
                        }
                    }
                    __syncthreads();
                }

            // exclusive cumprod via warp scan (warps 0,1)
            if (tid < 64) {
                float v = su[tid];
                float incl = v;
#pragma unroll
                for (int s = 1; s < 32; s <<= 1) {
                    float o = __shfl_up_sync(0xffffffffu, incl, s);
                    if ((tid & 31) >= s) incl *= o;
                }
                red[tid] = incl;
            }
            __syncthreads();
            if (tid < 64) {
                float excl = (tid & 31) ? red[tid - 1] : 1.f;
                if (tid >= 32) excl *= red[31];
                avec[sidx[tid]] = (1.f - su[tid]) * excl;
            }
            // content write scores (uses old-M rnorm computed above)
            float wstr = xi[164];
            if (tid >= 128 && tid < 192) {
                int n = tid - 128;
                float d = 0.f;
                for (int w = 0; w < 32; w++) d += wkn[w] * Ms[n * 33 + w];
                cwv[n] = d * rnorm[n] * wstr;
            }
            __syncthreads();

            // softmax over 64 (write content weights)
            if (tid < 32) {
                float x = fmaxf(cwv[tid], cwv[tid + 32]);
                for (int s = 16; s; s >>= 1) x = fmaxf(x, __shfl_xor_sync(0xffffffffu, x, s));
                if (tid == 0) red[0] = x;
            }
            __syncthreads();
            float cmx = red[0];
            __syncthreads();
            float ev = (tid < 64) ? expf(cwv[tid] - cmx) : 0.f;
            if (tid < 64) red[tid] = ev;
            __syncthreads();
            if (tid < 32) {
                float x = red[tid] + red[tid + 32];
                for (int s = 16; s; s >>= 1) x += __shfl_xor_sync(0xffffffffu, x, s);
                if (tid == 0) red[0] = x;
            }
            __syncthreads();
            if (tid < 64) cwv[tid] = ev / red[0];
            __syncthreads();

            float ag = xi[233], wg = xi[234];
            if (tid < 64) wwn[tid] = wg * (ag * avec[tid] + (1.f - ag) * cwv[tid]);
            __syncthreads();

            if (tid < 32) {
                float x = wwn[tid] + wwn[tid + 32];
                for (int s = 16; s; s >>= 1) x += __shfl_xor_sync(0xffffffffu, x, s);
                if (tid == 0) sww[0] = x;
            }

            // memory write + link matrix update (in smem)
            for (int i = tid; i < 2048; i += 512) {
                int n = i >> 5, w = i & 31;
                float m = Ms[n * 33 + w];
                Ms[n * 33 + w] = m * (1.f - wwn[n] * xi[165 + w]) + wwn[n] * xi[197 + w];
            }
            for (int i = tid; i < 4096; i += 512) {
                int ii = i >> 6, jj = i & 63;
                float lv = (ii == jj) ? 0.f
                         : ((1.f - wwn[ii] - wwn[jj]) * Ls[ii * 65 + jj] + wwn[ii] * ps[jj]);
                Ls[ii * 65 + jj] = lv;
            }
            __syncthreads();

            if (tid < 64) ps[tid] = (1.f - sww[0]) * ps[tid] + wwn[tid];
            if (tid >= 64 && tid < 128) {       // new-M row norms
                int n = tid - 64;
                float s = EPSF;
                for (int w = 0; w < 32; w++) { float m = Ms[n * 33 + w]; s += m * m; }
                rnorm[n] = rsqrtf(s);
            }
            if (tid < 64) wws[tid] = 0.f;       // placeholder; real update below
            __syncthreads();

            // content read weights (4 groups of 64; warps 0..7)
            int rr = (tid >> 6) & 3, nn = tid & 63;
            float pre = 0.f;
            {
                float d = 0.f;
                for (int w = 0; w < 32; w++) d += rkn[rr * 32 + w] * Ms[nn * 33 + w];
                pre = d * rnorm[nn] * xi[128 + rr];
            }
            float x = pre;
            for (int s = 16; s; s >>= 1) x = fmaxf(x, __shfl_xor_sync(0xffffffffu, x, s));
            if (tid < 256 && (tid & 31) == 0) red[tid >> 5] = x;
            __syncthreads();
            float gmx = fmaxf(red[rr * 2], red[rr * 2 + 1]);
            float e = expf(pre - gmx);
            __syncthreads();
            x = e;
            for (int s = 16; s; s >>= 1) x += __shfl_xor_sync(0xffffffffu, x, s);
            if (tid < 256 && (tid & 31) == 0) red[tid >> 5] = x;
            __syncthreads();
            float crv = e / (red[rr * 2] + red[rr * 2 + 1]);

            // forward/backward weights + read-weight mix
            if (tid < 256) {
                float fwv = 0.f, bwv = 0.f;
                const float* wrow = wrs + rr * 64;
                for (int m = 0; m < 64; m++) {
                    float wv = wrow[m];
                    fwv += Ls[nn * 65 + m] * wv;
                    bwv += Ls[m * 65 + nn] * wv;
                }
                wrtmp[rr * 64 + nn] = modes[rr * 4 + 0] * bwv + modes[rr * 4 + 1] * crv + modes[rr * 4 + 2] * fwv;
            }
            __syncthreads();

            if (tid < 256) wrs[tid] = wrtmp[tid];
            if (tid < 64) wws[tid] = wwn[tid];
            if (tid >= 256 && tid < 384) {
                int r = (tid - 256) >> 5, w = tid & 31;
                float s = 0.f;
                for (int n = 0; n < 64; n++) s += wrtmp[r * 64 + n] * Ms[n * 33 + w];
                g_rv[b * 128 + r * 32 + w] = s;
            }
        }

        target += gridDim.x;
        gbar(&g_barC, target);              // rv visible to all
    }
}

// ---------------- launch ----------------
extern "C" void kernel_launch(void* const* d_in, const int* in_sizes, int n_in,
                              void* d_out, int out_size) {
    (void)in_sizes; (void)n_in; (void)out_size;
    const float* x     = (const float*)d_in[0];
    const float* Wih_e = (const float*)d_in[1];
    const float* Whh_e = (const float*)d_in[2];
    const float* b_e   = (const float*)d_in[3];
    const float* Wih_c = (const float*)d_in[4];
    const float* Whh_c = (const float*)d_in[5];
    const float* b_c   = (const float*)d_in[6];
    float* out = (float*)d_out;

    static int smem_set = 0;
    if (!smem_set) {
        cudaFuncSetAttribute(enc_persist, cudaFuncAttributeMaxDynamicSharedMemorySize, E_BYTES);
        cudaFuncSetAttribute(ctrl_persist, cudaFuncAttributeMaxDynamicSharedMemorySize, C_BYTES);
        smem_set = 1;
    }

    init_states<<<1024, 256>>>();

    // Phase A: x @ Wih_e^T + b_e for all (t,b)
    gemm_phase<<<dim3(256, 32), 256>>>(x, Wih_e, b_e, 0);

    // Encoder recurrence — one persistent kernel
    enc_persist<<<128, 512, E_BYTES>>>(Whh_e);

    // Phase C: enc @ Wih_c[:, :512]^T + b_c for all (t,b)
    gemm_phase<<<dim3(256, 48), 256>>>(nullptr, Wih_c, b_c, 1);

    // Controller + DNC recurrence — one persistent kernel
    ctrl_persist<<<127, 512, C_BYTES>>>(Whh_c, Wih_c, out);
}

// round 8
// speedup vs baseline: 2.6362x; 1.0953x over previous
#include <cuda_runtime.h>
#include <math.h>
#include <stdint.h>

// ---------------- problem constants ----------------
#define TT 256
#define BBATCH 64
#define HH 512
#define HC 759          // HID_C
#define G4C 3036        // 4*HID_C
#define G4E 2048        // 4*H
#define KCC 887         // HC + R*W
#define KPAD 896        // 14 * 64
#define EPSF 1e-6f

// ---------------- device scratch ----------------
__device__ float g_XWe[(size_t)TT * BBATCH * G4E];
__device__ float g_EWc[(size_t)TT * BBATCH * G4C];
__device__ float g_enc[(size_t)TT * BBATCH * HH];
__device__ float g_he[2][BBATCH * HH];
__device__ float g_hc[2][BBATCH * HC];
__device__ float g_rv[BBATCH * 128];
__device__ unsigned g_barE;
__device__ unsigned g_barC;

__device__ __forceinline__ float sigmf_(float x) { return 1.f / (1.f + expf(-x)); }
__device__ __forceinline__ float softplusf_(float x) { return fmaxf(x, 0.f) + log1pf(expf(-fabsf(x))); }

__device__ __forceinline__ void gbar(unsigned* ctr, unsigned target) {
    __syncthreads();
    if (threadIdx.x == 0) {
        __threadfence();
        atomicAdd(ctr, 1u);
        while (*(volatile unsigned*)ctr < target) { __nanosleep(32); }
        __threadfence();
    }
    __syncthreads();
}

// ---------------- init ----------------
__global__ void init_states() {
    int i = blockIdx.x * blockDim.x + threadIdx.x;
    if (i == 0) { g_barE = 0u; g_barC = 0u; }
    if (i < 2 * BBATCH * HH) ((float*)g_he)[i] = 0.f;
    if (i < 2 * BBATCH * HC) ((float*)g_hc)[i] = 0.f;
    if (i < BBATCH * 128)    g_rv[i] = 0.f;
}

// ---------------- tf32 helpers ----------------
__device__ __forceinline__ uint32_t f2tf32(float x) {
    uint32_t r;
    asm("cvt.rna.tf32.f32 %0, %1;" : "=r"(r) : "f"(x));
    return r;
}
__device__ __forceinline__ void split_tf32(float x, uint32_t& hi, uint32_t& lo) {
    hi = f2tf32(x);
    lo = f2tf32(x - __uint_as_float(hi));
}
__device__ __forceinline__ void mma_tf32(float& c0, float& c1, float& c2, float& c3,
                                         uint32_t a0, uint32_t a1, uint32_t a2, uint32_t a3,
                                         uint32_t b0, uint32_t b1) {
    asm volatile(
        "mma.sync.aligned.m16n8k8.row.col.f32.tf32.tf32.f32 "
        "{%0,%1,%2,%3}, {%4,%5,%6,%7}, {%8,%9}, {%0,%1,%2,%3};"
        : "+f"(c0), "+f"(c1), "+f"(c2), "+f"(c3)
        : "r"(a0), "r"(a1), "r"(a2), "r"(a3), "r"(b0), "r"(b1));
}

// ---------------- tensor-core input-projection GEMM (3xTF32) ----------------
// C[m, n] = A_row(m) . Wt[n, 0:512] + bias[n]
// phase 0: A = x (B,T,H) with m=t*64+b -> row (b*TT+t); N=2048, ldw=512; C=g_XWe
// phase 1: A = g_enc (m-major);                          N=3036, ldw=640; C=g_EWc
// block tile 128x64, 8 warps (4x2) of 32x32 warp tiles, k-chunk 32.
#define GA_STRIDE 36
__global__ __launch_bounds__(256) void gemm_tc(const float* __restrict__ Ain,
                                               const float* __restrict__ Wt,
                                               const float* __restrict__ bias,
                                               int phase) {
    const int Ncols = phase ? G4C : G4E;
    const int ldw   = phase ? 640 : 512;
    float* C        = phase ? g_EWc : g_XWe;
    const float* A  = phase ? g_enc : Ain;

    __shared__ float As[128 * GA_STRIDE];
    __shared__ float Bs[64 * GA_STRIDE];

    int tid = threadIdx.x;
    int m0 = blockIdx.x * 128;
    int n0 = blockIdx.y * 64;
    int warp = tid >> 5, lane = tid & 31;
    int wm = warp & 3, wn = warp >> 2;

    // staging pointers (row fixed, k advances)
    const float* aptr[4];
    float* asmem[4];
#pragma unroll
    for (int i = 0; i < 4; i++) {
        int idx = tid + 256 * i;          // 0..1023
        int row = idx >> 3, c4 = (idx & 7) * 4;
        int m = m0 + row;
        const float* arow;
        if (phase) arow = A + (size_t)m * 512;
        else { int t = m >> 6, b = m & 63; arow = A + ((size_t)b * TT + t) * 512; }
        aptr[i] = arow + c4;
        asmem[i] = As + row * GA_STRIDE + c4;
    }
    const float* bptr[2];
    float* bsmem[2];
    bool bok[2];
#pragma unroll
    for (int i = 0; i < 2; i++) {
        int idx = tid + 256 * i;          // 0..511
        int row = idx >> 3, c4 = (idx & 7) * 4;
        int n = n0 + row;
        bok[i] = (n < Ncols);
        bptr[i] = Wt + (size_t)(bok[i] ? n : 0) * ldw + c4;
        bsmem[i] = Bs + row * GA_STRIDE + c4;
    }

    float acc[2][4][4];
#pragma unroll
    for (int mf = 0; mf < 2; mf++)
#pragma unroll
        for (int nf = 0; nf < 4; nf++)
#pragma unroll
            for (int q = 0; q < 4; q++) acc[mf][nf][q] = 0.f;

    float4 ra[4], rb[2];
#pragma unroll
    for (int i = 0; i < 4; i++) ra[i] = *(const float4*)(aptr[i]);
#pragma unroll
    for (int i = 0; i < 2; i++)
        rb[i] = bok[i] ? *(const float4*)(bptr[i]) : make_float4(0.f, 0.f, 0.f, 0.f);

    int la = (lane >> 2);     // group id 0..7
    int lk = (lane & 3);      // thread-in-group 0..3

    for (int kc = 0; kc < 16; kc++) {
#pragma unroll
        for (int i = 0; i < 4; i++) *(float4*)(asmem[i]) = ra[i];
#pragma unroll
        for (int i = 0; i < 2; i++) *(float4*)(bsmem[i]) = rb[i];
        __syncthreads();

        if (kc < 15) {
            int k0 = (kc + 1) * 32;
#pragma unroll
            for (int i = 0; i < 4; i++) ra[i] = *(const float4*)(aptr[i] + k0);
#pragma unroll
            for (int i = 0; i < 2; i++)
                rb[i] = bok[i] ? *(const float4*)(bptr[i] + k0) : make_float4(0.f, 0.f, 0.f, 0.f);
        }

#pragma unroll
        for (int k8 = 0; k8 < 4; k8++) {
            int kcol = k8 * 8 + lk;
            // A fragments (2 m-frags), split hi/lo
            uint32_t ah[2][4], al[2][4];
#pragma unroll
            for (int mf = 0; mf < 2; mf++) {
                int r = wm * 32 + mf * 16 + la;
                float v0 = As[r * GA_STRIDE + kcol];
                float v1 = As[(r + 8) * GA_STRIDE + kcol];
                float v2 = As[r * GA_STRIDE + kcol + 4];
                float v3 = As[(r + 8) * GA_STRIDE + kcol + 4];
                split_tf32(v0, ah[mf][0], al[mf][0]);
                split_tf32(v1, ah[mf][1], al[mf][1]);
                split_tf32(v2, ah[mf][2], al[mf][2]);
                split_tf32(v3, ah[mf][3], al[mf][3]);
            }
            // B fragments (4 n-frags), split hi/lo
            uint32_t bh[4][2], bl[4][2];
#pragma unroll
            for (int nf = 0; nf < 4; nf++) {
                int bn = wn * 32 + nf * 8 + la;
                float v0 = Bs[bn * GA_STRIDE + k8 * 8 + lk];
                float v1 = Bs[bn * GA_STRIDE + k8 * 8 + lk + 4];
                split_tf32(v0, bh[nf][0], bl[nf][0]);
                split_tf32(v1, bh[nf][1], bl[nf][1]);
            }
#pragma unroll
            for (int mf = 0; mf < 2; mf++)
#pragma unroll
                for (int nf = 0; nf < 4; nf++) {
                    float* c = acc[mf][nf];
                    mma_tf32(c[0], c[1], c[2], c[3],
                             ah[mf][0], ah[mf][1], ah[mf][2], ah[mf][3],
                             bh[nf][0], bh[nf][1]);
                    mma_tf32(c[0], c[1], c[2], c[3],
                             ah[mf][0], ah[mf][1], ah[mf][2], ah[mf][3],
                             bl[nf][0], bl[nf][1]);
                    mma_tf32(c[0], c[1], c[2], c[3],
                             al[mf][0], al[mf][1], al[mf][2], al[mf][3],
                             bh[nf][0], bh[nf][1]);
                }
        }
        __syncthreads();
    }

    // epilogue: bias add + store (float2 per c-pair)
#pragma unroll
    for (int mf = 0; mf < 2; mf++) {
        int r0 = m0 + wm * 32 + mf * 16 + la;
#pragma unroll
        for (int nf = 0; nf < 4; nf++) {
            int cb = n0 + wn * 32 + nf * 8 + lk * 2;
            float* c = acc[mf][nf];
            if (cb + 1 < Ncols) {
                float2 v0 = make_float2(c[0] + bias[cb], c[1] + bias[cb + 1]);
                float2 v1 = make_float2(c[2] + bias[cb], c[3] + bias[cb + 1]);
                *(float2*)&C[(size_t)r0 * Ncols + cb] = v0;
                *(float2*)&C[(size_t)(r0 + 8) * Ncols + cb] = v1;
            } else if (cb < Ncols) {
                C[(size_t)r0 * Ncols + cb] = c[0] + bias[cb];
                C[(size_t)(r0 + 8) * Ncols + cb] = c[2] + bias[cb];
            }
        }
    }
}

// ---------------- persistent encoder: 128 blocks x 512 threads ----------------
#define E_WC 0                 // 16*512
#define E_HS 8192              // 2*64*66
#define E_GS 16640             // 2*16*65
#define E_FLOATS 18720
#define E_BYTES (E_FLOATS * 4)

__global__ __launch_bounds__(512, 1) void enc_persist(const float* __restrict__ Whh_e) {
    extern __shared__ float dyn[];
    float* Wc = dyn + E_WC;
    float* hs = dyn + E_HS;
    float* gs = dyn + E_GS;

    int tid = threadIdx.x;
    int j0 = blockIdx.x * 4;

    for (int i = tid; i < 16 * 512; i += 512) {
        int lr = i >> 9, k = i & 511;
        int gate = lr >> 2, jj = lr & 3;
        Wc[i] = Whh_e[(size_t)(gate * HH + j0 + jj) * HH + k];
    }

    int g = tid >> 8;
    int t256 = tid & 255;
    int bb = t256 & 31;
    int ry = t256 >> 5;
    int lr0 = ry * 2;
    int kbase = g * 32;
    int kkr = tid & 63, blr = tid >> 6;
    int ebx = tid & 63, ejj = tid >> 6;
    float creg = 0.f;
    unsigned target = 0;
    __syncthreads();

    for (int t = 0; t < TT; t++) {
        int par = t & 1;
        const float* hin = g_he[par];
        float* hout = g_he[par ^ 1];

        float acc[2][2] = {{0.f, 0.f}, {0.f, 0.f}};
        if (g == 0) {
#pragma unroll
            for (int i2 = 0; i2 < 2; i2++)
#pragma unroll
                for (int r = 0; r < 2; r++) {
                    int lr = lr0 + r;
                    int gate = lr >> 2, jj = lr & 3;
                    acc[i2][r] = g_XWe[((size_t)t * BBATCH + 2 * bb + i2) * G4E + gate * HH + j0 + jj];
                }
        }

        float rg[8];
#pragma unroll
        for (int i = 0; i < 8; i++) rg[i] = hin[(blr + 8 * i) * HH + kkr];
#pragma unroll
        for (int i = 0; i < 8; i++) hs[kkr * 66 + blr + 8 * i] = rg[i];
        __syncthreads();

        for (int c = 0; c < 8; c++) {
            if (c < 7) {
#pragma unroll
                for (int i = 0; i < 8; i++)
                    rg[i] = hin[(blr + 8 * i) * HH + (c + 1) * 64 + kkr];
            }
            const float* hsb = hs + (c & 1) * 4224;
            const float* wp0 = Wc + lr0 * 512 + c * 64 + kbase;
            const float* wp1 = wp0 + 512;
#pragma unroll
            for (int k4 = 0; k4 < 32; k4 += 4) {
                float4 w0 = *(const float4*)(wp0 + k4);
                float4 w1 = *(const float4*)(wp1 + k4);
                float wa0[4] = {w0.x, w0.y, w0.z, w0.w};
                float wa1[4] = {w1.x, w1.y, w1.z, w1.w};
#pragma unroll
                for (int jq = 0; jq < 4; jq++) {
                    float2 h2 = *(const float2*)(hsb + (kbase + k4 + jq) * 66 + 2 * bb);
                    acc[0][0] += h2.x * wa0[jq]; acc[0][1] += h2.x * wa1[jq];
                    acc[1][0] += h2.y * wa0[jq]; acc[1][1] += h2.y * wa1[jq];
                }
            }
            if (c < 7) {
                float* hsn = hs + ((c + 1) & 1) * 4224;
#pragma unroll
                for (int i = 0; i < 8; i++) hsn[kkr * 66 + blr + 8 * i] = rg[i];
            }
            __syncthreads();
        }

#pragma unroll
        for (int i2 = 0; i2 < 2; i2++)
#pragma unroll
            for (int r = 0; r < 2; r++)
                gs[g * 1040 + (lr0 + r) * 65 + 2 * bb + i2] = acc[i2][r];
        __syncthreads();

        if (tid < 256) {
            int j = j0 + ejj;
            float gi = gs[ejj * 65 + ebx]        + gs[1040 + ejj * 65 + ebx];
            float gf = gs[(4 + ejj) * 65 + ebx]  + gs[1040 + (4 + ejj) * 65 + ebx];
            float gg = gs[(8 + ejj) * 65 + ebx]  + gs[1040 + (8 + ejj) * 65 + ebx];
            float go = gs[(12 + ejj) * 65 + ebx] + gs[1040 + (12 + ejj) * 65 + ebx];
            float cn = sigmf_(gf) * creg + sigmf_(gi) * tanhf(gg);
            creg = cn;
            float hn = sigmf_(go) * tanhf(cn);
            hout[ebx * HH + j] = hn;
            g_enc[((size_t)t * BBATCH + ebx) * HH + j] = hn;
        }

        target += gridDim.x;
        gbar(&g_barE, target);
    }
}

// ---------------- persistent controller + fused DNC: 127 blocks x 512 threads ----------------
#define C_WC    0
#define C_HS    21504
#define C_GS    29952
#define C_LS    33072
#define C_MS    37232
#define C_WRS   39344
#define C_WRT   39600
#define C_US    39856
#define C_PS    39920
#define C_WWS   39984
#define C_XI    40048
#define C_AVEC  40304
#define C_CWV   40368
#define C_WWN   40432
#define C_SU    40496
#define C_RNORM 40560
#define C_SIDX  40624
#define C_RKN   40688
#define C_WKN   40816
#define C_MODES 40848
#define C_RED   40864
#define C_KNORM 40928
#define C_SWW   40936
#define C_FLOATS 40944
#define C_BYTES (C_FLOATS * 4)

__global__ __launch_bounds__(512, 1) void ctrl_persist(const float* __restrict__ Whh_c,
                                                       const float* __restrict__ Wih_c,
                                                       float* __restrict__ out) {
    extern __shared__ float dyn[];
    float* Wc    = dyn + C_WC;
    float* hs    = dyn + C_HS;
    float* gsv   = dyn + C_GS;
    float* Ls    = dyn + C_LS;
    float* Ms    = dyn + C_MS;
    float* wrs   = dyn + C_WRS;
    float* wrtmp = dyn + C_WRT;
    float* us    = dyn + C_US;
    float* ps    = dyn + C_PS;
    float* wws   = dyn + C_WWS;
    float* xi    = dyn + C_XI;
    float* avec  = dyn + C_AVEC;
    float* cwv   = dyn + C_CWV;
    float* wwn   = dyn + C_WWN;
    float* su    = dyn + C_SU;
    float* rnorm = dyn + C_RNORM;
    int*   sidx  = (int*)(dyn + C_SIDX);
    float* rkn   = dyn + C_RKN;
    float* wkn   = dyn + C_WKN;
    float* modes = dyn + C_MODES;
    float* red   = dyn + C_RED;
    float* knorm = dyn + C_KNORM;
    float* sww   = dyn + C_SWW;

    int tid = threadIdx.x;
    int j0 = blockIdx.x * 6;

    for (int i = tid; i < 24 * KPAD; i += 512) {
        int lr = i / KPAD, k = i - lr * KPAD;
        int gate = lr / 6, jj = lr - gate * 6;
        int j = j0 + jj;
        float v = 0.f;
        if (j < HC && k < KCC) {
            int grow = gate * HC + j;
            v = (k < HC) ? Whh_c[(size_t)grow * HC + k]
                         : Wih_c[(size_t)grow * 640 + 512 + (k - HC)];
        }
        Wc[i] = v;
    }
    if (blockIdx.x < 64) {
        for (int i = tid; i < 64 * 65; i += 512) Ls[i] = 0.f;
        for (int i = tid; i < 64 * 33; i += 512) Ms[i] = 0.f;
        if (tid < 256) wrs[tid] = 0.f;
        if (tid < 64) { us[tid] = 0.f; ps[tid] = 0.f; wws[tid] = 0.f; }
    }

    int g = tid >> 8, t256 = tid & 255;
    int bb = t256 & 31, ry = t256 >> 5, lr0 = ry * 3;
    int kbase = g * 32;
    int kkr = tid & 63, blr = tid >> 6;
    int ebx = tid & 63, ejj = tid >> 6;
    float creg = 0.f;
    unsigned target = 0;

    int growA[3], jA[3];
#pragma unroll
    for (int r = 0; r < 3; r++) {
        int lr = lr0 + r;
        int gate = lr / 6, jj = lr - gate * 6;
        jA[r] = j0 + jj;
        growA[r] = gate * HC + jA[r];
    }
    __syncthreads();

    for (int t = 0; t < TT; t++) {
        int par = t & 1;
        const float* hin = g_hc[par];
        float* hout = g_hc[par ^ 1];

        float acc[2][3] = {{0.f,0.f,0.f},{0.f,0.f,0.f}};
        if (g == 0) {
#pragma unroll
            for (int i2 = 0; i2 < 2; i2++)
#pragma unroll
                for (int r = 0; r < 3; r++)
                    if (jA[r] < HC)
                        acc[i2][r] = g_EWc[((size_t)t * BBATCH + 2 * bb + i2) * G4C + growA[r]];
        }

        float rg[8];
        {
            int k = kkr;
#pragma unroll
            for (int i = 0; i < 8; i++) {
                int bl = blr + 8 * i;
                rg[i] = (k < HC) ? hin[bl * HC + k] : g_rv[bl * 128 + (k - HC)];
            }
        }
#pragma unroll
        for (int i = 0; i < 8; i++) hs[kkr * 66 + blr + 8 * i] = rg[i];
        __syncthreads();

        for (int c = 0; c < 14; c++) {
            if (c < 13) {
                int k = (c + 1) * 64 + kkr;
#pragma unroll
                for (int i = 0; i < 8; i++) {
                    int bl = blr + 8 * i;
                    float v;
                    if (k < HC) v = hin[bl * HC + k];
                    else if (k < KCC) v = g_rv[bl * 128 + (k - HC)];
                    else v = 0.f;
                    rg[i] = v;
                }
            }
            const float* hsb = hs + (c & 1) * 4224;
            const float* wp0 = Wc + (lr0 + 0) * KPAD + c * 64 + kbase;
            const float* wp1 = Wc + (lr0 + 1) * KPAD + c * 64 + kbase;
            const float* wp2 = Wc + (lr0 + 2) * KPAD + c * 64 + kbase;
#pragma unroll
            for (int k4 = 0; k4 < 32; k4 += 4) {
                float4 w0 = *(const float4*)(wp0 + k4);
                float4 w1 = *(const float4*)(wp1 + k4);
                float4 w2 = *(const float4*)(wp2 + k4);
                float wa0[4] = {w0.x, w0.y, w0.z, w0.w};
                float wa1[4] = {w1.x, w1.y, w1.z, w1.w};
                float wa2[4] = {w2.x, w2.y, w2.z, w2.w};
#pragma unroll
                for (int jq = 0; jq < 4; jq++) {
                    float2 h2 = *(const float2*)(hsb + (kbase + k4 + jq) * 66 + 2 * bb);
                    acc[0][0] += h2.x * wa0[jq]; acc[0][1] += h2.x * wa1[jq]; acc[0][2] += h2.x * wa2[jq];
                    acc[1][0] += h2.y * wa0[jq]; acc[1][1] += h2.y * wa1[jq]; acc[1][2] += h2.y * wa2[jq];
                }
            }
            if (c < 13) {
                float* hsn = hs + ((c + 1) & 1) * 4224;
#pragma unroll
                for (int i = 0; i < 8; i++) hsn[kkr * 66 + blr + 8 * i] = rg[i];
            }
            __syncthreads();
        }

#pragma unroll
        for (int i2 = 0; i2 < 2; i2++)
#pragma unroll
            for (int r = 0; r < 3; r++)
                gsv[g * 1560 + (lr0 + r) * 65 + 2 * bb + i2] = acc[i2][r];
        __syncthreads();

        if (tid < 384) {
            int j = j0 + ejj;
            if (j < HC) {
                float gi = gsv[ejj * 65 + ebx]        + gsv[1560 + ejj * 65 + ebx];
                float gf = gsv[(6 + ejj) * 65 + ebx]  + gsv[1560 + (6 + ejj) * 65 + ebx];
                float gg = gsv[(12 + ejj) * 65 + ebx] + gsv[1560 + (12 + ejj) * 65 + ebx];
                float go = gsv[(18 + ejj) * 65 + ebx] + gsv[1560 + (18 + ejj) * 65 + ebx];
                float cn = sigmf_(gf) * creg + sigmf_(gi) * tanhf(gg);
                creg = cn;
                float hn = sigmf_(go) * tanhf(cn);
                hout[ebx * HC + j] = hn;
                if (j < HH) out[((size_t)ebx * TT + t) * HH + j] = hn;
            }
        }

        target += gridDim.x;
        gbar(&g_barC, target);

        if (blockIdx.x < 64) {
            int b = blockIdx.x;
            const float* h = g_hc[par ^ 1] + b * HC;

            if (tid < 247) {
                float v = h[HH + tid];
                float a;
                if (tid < 128)      a = tanhf(v);
                else if (tid < 132) a = softplusf_(v);
                else if (tid < 164) a = tanhf(v);
                else if (tid < 165) a = softplusf_(v);
                else if (tid < 197) a = sigmf_(v);
                else if (tid < 229) a = tanhf(v);
                else if (tid < 235) a = sigmf_(v);
                else                a = v;
                xi[tid] = a;
            }
            __syncthreads();

            if (tid < 4) {
                float s = EPSF;
                for (int w = 0; w < 32; w++) { float k = xi[tid * 32 + w]; s += k * k; }
                knorm[tid] = rsqrtf(s);
            } else if (tid == 4) {
                float s = EPSF;
                for (int w = 0; w < 32; w++) { float k = xi[132 + w]; s += k * k; }
                knorm[4] = rsqrtf(s);
            } else if (tid >= 8 && tid < 12) {
                int r = tid - 8;
                float m0 = xi[235 + 3 * r], m1 = xi[236 + 3 * r], m2 = xi[237 + 3 * r];
                float mx = fmaxf(m0, fmaxf(m1, m2));
                float e0 = expf(m0 - mx), e1 = expf(m1 - mx), e2 = expf(m2 - mx);
                float inv = 1.f / (e0 + e1 + e2);
                modes[r * 4 + 0] = e0 * inv; modes[r * 4 + 1] = e1 * inv; modes[r * 4 + 2] = e2 * inv;
            }
            if (tid >= 64 && tid < 128) {
                int n = tid - 64;
                float s = EPSF;
                for (int w = 0; w < 32; w++) { float m = Ms[n * 33 + w]; s += m * m; }
                rnorm[n] = rsqrtf(s);
            }
            __syncthreads();
            if (tid < 128)      { int r = tid >> 5, w = tid & 31; rkn[r * 32 + w] = xi[r * 32 + w] * knorm[r]; }
            else if (tid < 160) { int w = tid - 128; wkn[w] = xi[132 + w] * knorm[4]; }

            if (tid < 64) {
                float psi = 1.f;
#pragma unroll
                for (int r = 0; r < 4; r++) psi *= (1.f - xi[229 + r] * wrs[r * 64 + tid]);
                float un = (us[tid] + wws[tid] - us[tid] * wws[tid]) * psi;
                us[tid] = un; su[tid] = un; sidx[tid] = tid;
            }
            __syncthreads();

            for (int k = 2; k <= 64; k <<= 1)
                for (int j = k >> 1; j > 0; j >>= 1) {
                    if (tid < 64) {
                        int ixj = tid ^ j;
                        if (ixj > tid) {
                            float av = su[tid], bv = su[ixj];
                            int ai = sidx[tid], bi = sidx[ixj];
                            bool up = ((tid & k) == 0);
                            bool gt = (av > bv) || (av == bv && ai > bi);
                            if (gt == up) { su[tid] = bv; su[ixj] = av; sidx[tid] = bi; sidx[ixj] = ai; }
                        }
                    }
                    __syncthreads();
                }

            if (tid < 64) {
                float v = su[tid];
                float incl = v;
#pragma unroll
                for (int s = 1; s < 32; s <<= 1) {
                    float o = __shfl_up_sync(0xffffffffu, incl, s);
                    if ((tid & 31) >= s) incl *= o;
                }
                red[tid] = incl;
            }
            __syncthreads();
            if (tid < 64) {
                float excl = (tid & 31) ? red[tid - 1] : 1.f;
                if (tid >= 32) excl *= red[31];
                avec[sidx[tid]] = (1.f - su[tid]) * excl;
            }
            float wstr = xi[164];
            if (tid >= 128 && tid < 192) {
                int n = tid - 128;
                float d = 0.f;
                for (int w = 0; w < 32; w++) d += wkn[w] * Ms[n * 33 + w];
                cwv[n] = d * rnorm[n] * wstr;
            }
            __syncthreads();

            if (tid < 32) {
                float x = fmaxf(cwv[tid], cwv[tid + 32]);
                for (int s = 16; s; s >>= 1) x = fmaxf(x, __shfl_xor_sync(0xffffffffu, x, s));
                if (tid == 0) red[0] = x;
            }
            __syncthreads();
            float cmx = red[0];
            __syncthreads();
            float ev = (tid < 64) ? expf(cwv[tid] - cmx) : 0.f;
            if (tid < 64) red[tid] = ev;
            __syncthreads();
            if (tid < 32) {
                float x = red[tid] + red[tid + 32];
                for (int s = 16; s; s >>= 1) x += __shfl_xor_sync(0xffffffffu, x, s);
                if (tid == 0) red[0] = x;
            }
            __syncthreads();
            if (tid < 64) cwv[tid] = ev / red[0];
            __syncthreads();

            float ag = xi[233], wg = xi[234];
            if (tid < 64) wwn[tid] = wg * (ag * avec[tid] + (1.f - ag) * cwv[tid]);
            __syncthreads();

            if (tid < 32) {
                float x = wwn[tid] + wwn[tid + 32];
                for (int s = 16; s; s >>= 1) x += __shfl_xor_sync(0xffffffffu, x, s);
                if (tid == 0) sww[0] = x;
            }

            for (int i = tid; i < 2048; i += 512) {
                int n = i >> 5, w = i & 31;
                float m = Ms[n * 33 + w];
                Ms[n * 33 + w] = m * (1.f - wwn[n] * xi[165 + w]) + wwn[n] * xi[197 + w];
            }
            for (int i = tid; i < 4096; i += 512) {
                int ii = i >> 6, jj = i & 63;
                float lv = (ii == jj) ? 0.f
                         : ((1.f - wwn[ii] - wwn[jj]) * Ls[ii * 65 + jj] + wwn[ii] * ps[jj]);
                Ls[ii * 65 + jj] = lv;
            }
            __syncthreads();

            if (tid < 64) ps[tid] = (1.f - sww[0]) * ps[tid] + wwn[tid];
            if (tid >= 64 && tid < 128) {
                int n = tid - 64;
                float s = EPSF;
                for (int w = 0; w < 32; w++) { float m = Ms[n * 33 + w]; s += m * m; }
                rnorm[n] = rsqrtf(s);
            }
            if (tid < 64) wws[tid] = 0.f;
            __syncthreads();

            int rr = (tid >> 6) & 3, nn = tid & 63;
            float pre = 0.f;
            {
                float d = 0.f;
                for (int w = 0; w < 32; w++) d += rkn[rr * 32 + w] * Ms[nn * 33 + w];
                pre = d * rnorm[nn] * xi[128 + rr];
            }
            float x = pre;
            for (int s = 16; s; s >>= 1) x = fmaxf(x, __shfl_xor_sync(0xffffffffu, x, s));
            if (tid < 256 && (tid & 31) == 0) red[tid >> 5] = x;
            __syncthreads();
            float gmx = fmaxf(red[rr * 2], red[rr * 2 + 1]);
            float e = expf(pre - gmx);
            __syncthreads();
            x = e;
            for (int s = 16; s; s >>= 1) x += __shfl_xor_sync(0xffffffffu, x, s);
            if (tid < 256 && (tid & 31) == 0) red[tid >> 5] = x;
            __syncthreads();
            float crv = e / (red[rr * 2] + red[rr * 2 + 1]);

            if (tid < 256) {
                float fwv = 0.f, bwv = 0.f;
                const float* wrow = wrs + rr * 64;
                for (int m = 0; m < 64; m++) {
                    float wv = wrow[m];
                    fwv += Ls[nn * 65 + m] * wv;
                    bwv += Ls[m * 65 + nn] * wv;
                }
                wrtmp[rr * 64 + nn] = modes[rr * 4 + 0] * bwv + modes[rr * 4 + 1] * crv + modes[rr * 4 + 2] * fwv;
            }
            __syncthreads();

            if (tid < 256) wrs[tid] = wrtmp[tid];
            if (tid < 64) wws[tid] = wwn[tid];
            if (tid >= 256 && tid < 384) {
                int r = (tid - 256) >> 5, w = tid & 31;
                float s = 0.f;
                for (int n = 0; n < 64; n++) s += wrtmp[r * 64 + n] * Ms[n * 33 + w];
                g_rv[b * 128 + r * 32 + w] = s;
            }
        }

        target += gridDim.x;
        gbar(&g_barC, target);
    }
}

// ---------------- launch ----------------
extern "C" void kernel_launch(void* const* d_in, const int* in_sizes, int n_in,
                              void* d_out, int out_size) {
    (void)in_sizes; (void)n_in; (void)out_size;
    const float* x     = (const float*)d_in[0];
    const float* Wih_e = (const float*)d_in[1];
    const float* Whh_e = (const float*)d_in[2];
    const float* b_e   = (const float*)d_in[3];
    const float* Wih_c = (const float*)d_in[4];
    const float* Whh_c = (const float*)d_in[5];
    const float* b_c   = (const float*)d_in[6];
    float* out = (float*)d_out;

    static int smem_set = 0;
    if (!smem_set) {
        cudaFuncSetAttribute(enc_persist, cudaFuncAttributeMaxDynamicSharedMemorySize, E_BYTES);
        cudaFuncSetAttribute(ctrl_persist, cudaFuncAttributeMaxDynamicSharedMemorySize, C_BYTES);
        smem_set = 1;
    }

    init_states<<<1024, 256>>>();

    // Phase A: x @ Wih_e^T + b_e for all (t,b) — tensor cores (3xTF32)
    gemm_tc<<<dim3(128, 32), 256>>>(x, Wih_e, b_e, 0);

    // Encoder recurrence — one persistent kernel
    enc_persist<<<128, 512, E_BYTES>>>(Whh_e);

    // Phase C: enc @ Wih_c[:, :512]^T + b_c for all (t,b) — tensor cores (3xTF32)
    gemm_tc<<<dim3(128, 48), 256>>>(nullptr, Wih_c, b_c, 1);

    // Controller + DNC recurrence — one persistent kernel
    ctrl_persist<<<127, 512, C_BYTES>>>(Whh_c, Wih_c, out);
}

// round 10
// speedup vs baseline: 2.8741x; 1.0903x over previous
#include <cuda_runtime.h>
#include <math.h>
#include <stdint.h>

// ---------------- problem constants ----------------
#define TT 256
#define BBATCH 64
#define HH 512
#define HC 759          // HID_C
#define G4C 3036        // 4*HID_C
#define G4E 2048        // 4*H
#define KCC 887         // HC + R*W
#define KPAD 896        // 14 * 64 ; layout: [rv(128) | h(759) | pad]
#define EPSF 1e-6f

// ---------------- device scratch ----------------
__device__ float g_XWe[(size_t)TT * BBATCH * G4E];
__device__ float g_EWc[(size_t)TT * BBATCH * G4C];
__device__ float g_enc[(size_t)TT * BBATCH * HH];
__device__ float g_he[2][BBATCH * HH];
__device__ float g_hc[2][BBATCH * HC];
__device__ float g_rv[BBATCH * 128];
__device__ unsigned g_barE;
__device__ unsigned g_barC;

__device__ __forceinline__ float sigmf_(float x) { return 1.f / (1.f + expf(-x)); }
__device__ __forceinline__ float softplusf_(float x) { return fmaxf(x, 0.f) + log1pf(expf(-fabsf(x))); }

__device__ __forceinline__ void gbar(unsigned* ctr, unsigned target) {
    __syncthreads();
    if (threadIdx.x == 0) {
        __threadfence();
        atomicAdd(ctr, 1u);
        while (*(volatile unsigned*)ctr < target) { __nanosleep(32); }
        __threadfence();
    }
    __syncthreads();
}

// ---------------- init ----------------
__global__ void init_states() {
    int i = blockIdx.x * blockDim.x + threadIdx.x;
    if (i == 0) { g_barE = 0u; g_barC = 0u; }
    if (i < 2 * BBATCH * HH) ((float*)g_he)[i] = 0.f;
    if (i < 2 * BBATCH * HC) ((float*)g_hc)[i] = 0.f;
    if (i < BBATCH * 128)    g_rv[i] = 0.f;
}

// ---------------- tf32 helpers ----------------
__device__ __forceinline__ uint32_t f2tf32(float x) {
    uint32_t r;
    asm("cvt.rna.tf32.f32 %0, %1;" : "=r"(r) : "f"(x));
    return r;
}
__device__ __forceinline__ void split_tf32(float x, uint32_t& hi, uint32_t& lo) {
    hi = f2tf32(x);
    lo = f2tf32(x - __uint_as_float(hi));
}
__device__ __forceinline__ void mma_tf32(float& c0, float& c1, float& c2, float& c3,
                                         uint32_t a0, uint32_t a1, uint32_t a2, uint32_t a3,
                                         uint32_t b0, uint32_t b1) {
    asm volatile(
        "mma.sync.aligned.m16n8k8.row.col.f32.tf32.tf32.f32 "
        "{%0,%1,%2,%3}, {%4,%5,%6,%7}, {%8,%9}, {%0,%1,%2,%3};"
        : "+f"(c0), "+f"(c1), "+f"(c2), "+f"(c3)
        : "r"(a0), "r"(a1), "r"(a2), "r"(a3), "r"(b0), "r"(b1));
}

// ---------------- tensor-core input-projection GEMM (3xTF32) ----------------
#define GA_STRIDE 36
__global__ __launch_bounds__(256) void gemm_tc(const float* __restrict__ Ain,
                                               const float* __restrict__ Wt,
                                               const float* __restrict__ bias,
                                               int phase) {
    const int Ncols = phase ? G4C : G4E;
    const int ldw   = phase ? 640 : 512;
    float* C        = phase ? g_EWc : g_XWe;
    const float* A  = phase ? g_enc : Ain;

    __shared__ float As[128 * GA_STRIDE];
    __shared__ float Bs[64 * GA_STRIDE];

    int tid = threadIdx.x;
    int m0 = blockIdx.x * 128;
    int n0 = blockIdx.y * 64;
    int warp = tid >> 5, lane = tid & 31;
    int wm = warp & 3, wn = warp >> 2;

    const float* aptr[4];
    float* asmem[4];
#pragma unroll
    for (int i = 0; i < 4; i++) {
        int idx = tid + 256 * i;
        int row = idx >> 3, c4 = (idx & 7) * 4;
        int m = m0 + row;
        const float* arow;
        if (phase) arow = A + (size_t)m * 512;
        else { int t = m >> 6, b = m & 63; arow = A + ((size_t)b * TT + t) * 512; }
        aptr[i] = arow + c4;
        asmem[i] = As + row * GA_STRIDE + c4;
    }
    const float* bptr[2];
    float* bsmem[2];
    bool bok[2];
#pragma unroll
    for (int i = 0; i < 2; i++) {
        int idx = tid + 256 * i;
        int row = idx >> 3, c4 = (idx & 7) * 4;
        int n = n0 + row;
        bok[i] = (n < Ncols);
        bptr[i] = Wt + (size_t)(bok[i] ? n : 0) * ldw + c4;
        bsmem[i] = Bs + row * GA_STRIDE + c4;
    }

    float acc[2][4][4];
#pragma unroll
    for (int mf = 0; mf < 2; mf++)
#pragma unroll
        for (int nf = 0; nf < 4; nf++)
#pragma unroll
            for (int q = 0; q < 4; q++) acc[mf][nf][q] = 0.f;

    float4 ra[4], rb[2];
#pragma unroll
    for (int i = 0; i < 4; i++) ra[i] = *(const float4*)(aptr[i]);
#pragma unroll
    for (int i = 0; i < 2; i++)
        rb[i] = bok[i] ? *(const float4*)(bptr[i]) : make_float4(0.f, 0.f, 0.f, 0.f);

    int la = (lane >> 2);
    int lk = (lane & 3);

    for (int kc = 0; kc < 16; kc++) {
#pragma unroll
        for (int i = 0; i < 4; i++) *(float4*)(asmem[i]) = ra[i];
#pragma unroll
        for (int i = 0; i < 2; i++) *(float4*)(bsmem[i]) = rb[i];
        __syncthreads();

        if (kc < 15) {
            int k0 = (kc + 1) * 32;
#pragma unroll
            for (int i = 0; i < 4; i++) ra[i] = *(const float4*)(aptr[i] + k0);
#pragma unroll
            for (int i = 0; i < 2; i++)
                rb[i] = bok[i] ? *(const float4*)(bptr[i] + k0) : make_float4(0.f, 0.f, 0.f, 0.f);
        }

#pragma unroll
        for (int k8 = 0; k8 < 4; k8++) {
            int kcol = k8 * 8 + lk;
            uint32_t ah[2][4], al[2][4];
#pragma unroll
            for (int mf = 0; mf < 2; mf++) {
                int r = wm * 32 + mf * 16 + la;
                float v0 = As[r * GA_STRIDE + kcol];
                float v1 = As[(r + 8) * GA_STRIDE + kcol];
                float v2 = As[r * GA_STRIDE + kcol + 4];
                float v3 = As[(r + 8) * GA_STRIDE + kcol + 4];
                split_tf32(v0, ah[mf][0], al[mf][0]);
                split_tf32(v1, ah[mf][1], al[mf][1]);
                split_tf32(v2, ah[mf][2], al[mf][2]);
                split_tf32(v3, ah[mf][3], al[mf][3]);
            }
            uint32_t bh[4][2], bl[4][2];
#pragma unroll
            for (int nf = 0; nf < 4; nf++) {
                int bn = wn * 32 + nf * 8 + la;
                float v0 = Bs[bn * GA_STRIDE + k8 * 8 + lk];
                float v1 = Bs[bn * GA_STRIDE + k8 * 8 + lk + 4];
                split_tf32(v0, bh[nf][0], bl[nf][0]);
                split_tf32(v1, bh[nf][1], bl[nf][1]);
            }
#pragma unroll
            for (int mf = 0; mf < 2; mf++)
#pragma unroll
                for (int nf = 0; nf < 4; nf++) {
                    float* c = acc[mf][nf];
                    mma_tf32(c[0], c[1], c[2], c[3],
                             ah[mf][0], ah[mf][1], ah[mf][2], ah[mf][3],
                             bh[nf][0], bh[nf][1]);
                    mma_tf32(c[0], c[1], c[2], c[3],
                             ah[mf][0], ah[mf][1], ah[mf][2], ah[mf][3],
                             bl[nf][0], bl[nf][1]);
                    mma_tf32(c[0], c[1], c[2], c[3],
                             al[mf][0], al[mf][1], al[mf][2], al[mf][3],
                             bh[nf][0], bh[nf][1]);
                }
        }
        __syncthreads();
    }

#pragma unroll
    for (int mf = 0; mf < 2; mf++) {
        int r0 = m0 + wm * 32 + mf * 16 + la;
#pragma unroll
        for (int nf = 0; nf < 4; nf++) {
            int cb = n0 + wn * 32 + nf * 8 + lk * 2;
            float* c = acc[mf][nf];
            if (cb + 1 < Ncols) {
                float2 v0 = make_float2(c[0] + bias[cb], c[1] + bias[cb + 1]);
                float2 v1 = make_float2(c[2] + bias[cb], c[3] + bias[cb + 1]);
                *(float2*)&C[(size_t)r0 * Ncols + cb] = v0;
                *(float2*)&C[(size_t)(r0 + 8) * Ncols + cb] = v1;
            } else if (cb < Ncols) {
                C[(size_t)r0 * Ncols + cb] = c[0] + bias[cb];
                C[(size_t)(r0 + 8) * Ncols + cb] = c[2] + bias[cb];
            }
        }
    }
}

// ---------------- persistent encoder: 128 blocks x 512 threads (unchanged) ----------------
#define E_WC 0
#define E_HS 8192
#define E_GS 16640
#define E_FLOATS 18720
#define E_BYTES (E_FLOATS * 4)

__global__ __launch_bounds__(512, 1) void enc_persist(const float* __restrict__ Whh_e) {
    extern __shared__ float dyn[];
    float* Wc = dyn + E_WC;
    float* hs = dyn + E_HS;
    float* gs = dyn + E_GS;

    int tid = threadIdx.x;
    int j0 = blockIdx.x * 4;

    for (int i = tid; i < 16 * 512; i += 512) {
        int lr = i >> 9, k = i & 511;
        int gate = lr >> 2, jj = lr & 3;
        Wc[i] = Whh_e[(size_t)(gate * HH + j0 + jj) * HH + k];
    }

    int g = tid >> 8;
    int t256 = tid & 255;
    int bb = t256 & 31;
    int ry = t256 >> 5;
    int lr0 = ry * 2;
    int kbase = g * 32;
    int kkr = tid & 63, blr = tid >> 6;
    int ebx = tid & 63, ejj = tid >> 6;
    float creg = 0.f;
    unsigned target = 0;
    __syncthreads();

    for (int t = 0; t < TT; t++) {
        int par = t & 1;
        const float* hin = g_he[par];
        float* hout = g_he[par ^ 1];

        float acc[2][2] = {{0.f, 0.f}, {0.f, 0.f}};
        if (g == 0) {
#pragma unroll
            for (int i2 = 0; i2 < 2; i2++)
#pragma unroll
                for (int r = 0; r < 2; r++) {
                    int lr = lr0 + r;
                    int gate = lr >> 2, jj = lr & 3;
                    acc[i2][r] = g_XWe[((size_t)t * BBATCH + 2 * bb + i2) * G4E + gate * HH + j0 + jj];
                }
        }

        float rg[8];
#pragma unroll
        for (int i = 0; i < 8; i++) rg[i] = hin[(blr + 8 * i) * HH + kkr];
#pragma unroll
        for (int i = 0; i < 8; i++) hs[kkr * 66 + blr + 8 * i] = rg[i];
        __syncthreads();

        for (int c = 0; c < 8; c++) {
            if (c < 7) {
#pragma unroll
                for (int i = 0; i < 8; i++)
                    rg[i] = hin[(blr + 8 * i) * HH + (c + 1) * 64 + kkr];
            }
            const float* hsb = hs + (c & 1) * 4224;
            const float* wp0 = Wc + lr0 * 512 + c * 64 + kbase;
            const float* wp1 = wp0 + 512;
#pragma unroll
            for (int k4 = 0; k4 < 32; k4 += 4) {
                float4 w0 = *(const float4*)(wp0 + k4);
                float4 w1 = *(const float4*)(wp1 + k4);
                float wa0[4] = {w0.x, w0.y, w0.z, w0.w};
                float wa1[4] = {w1.x, w1.y, w1.z, w1.w};
#pragma unroll
                for (int jq = 0; jq < 4; jq++) {
                    float2 h2 = *(const float2*)(hsb + (kbase + k4 + jq) * 66 + 2 * bb);
                    acc[0][0] += h2.x * wa0[jq]; acc[0][1] += h2.x * wa1[jq];
                    acc[1][0] += h2.y * wa0[jq]; acc[1][1] += h2.y * wa1[jq];
                }
            }
            if (c < 7) {
                float* hsn = hs + ((c + 1) & 1) * 4224;
#pragma unroll
                for (int i = 0; i < 8; i++) hsn[kkr * 66 + blr + 8 * i] = rg[i];
            }
            __syncthreads();
        }

#pragma unroll
        for (int i2 = 0; i2 < 2; i2++)
#pragma unroll
            for (int r = 0; r < 2; r++)
                gs[g * 1040 + (lr0 + r) * 65 + 2 * bb + i2] = acc[i2][r];
        __syncthreads();

        if (tid < 256) {
            int j = j0 + ejj;
            float gi = gs[ejj * 65 + ebx]        + gs[1040 + ejj * 65 + ebx];
            float gf = gs[(4 + ejj) * 65 + ebx]  + gs[1040 + (4 + ejj) * 65 + ebx];
            float gg = gs[(8 + ejj) * 65 + ebx]  + gs[1040 + (8 + ejj) * 65 + ebx];
            float go = gs[(12 + ejj) * 65 + ebx] + gs[1040 + (12 + ejj) * 65 + ebx];
            float cn = sigmf_(gf) * creg + sigmf_(gi) * tanhf(gg);
            creg = cn;
            float hn = sigmf_(go) * tanhf(cn);
            hout[ebx * HH + j] = hn;
            g_enc[((size_t)t * BBATCH + ebx) * HH + j] = hn;
        }

        target += gridDim.x;
        gbar(&g_barE, target);
    }
}

// ---------------- persistent controller + overlapped DNC: 127 blocks x 512 threads ----------------
// K layout: [rv(128) | h(759) | pad] -> chunks 0-1 = rv, 2-13 = h.
// Blocks 0-63 (DNC blocks): j-chunk of 4.  Blocks 64-126: j-chunk of 8.
#define C_WC    0        // 32*896 = 28672
#define C_HS    28672    // 2*64*66 = 8448
#define C_GS    37120    // 2*32*65 = 4160
#define C_LS    41280    // 64*65 = 4160
#define C_MS    45440    // 64*33 = 2112
#define C_WRS   47552    // 256
#define C_WRT   47808    // 256
#define C_US    48064
#define C_PS    48128
#define C_WWS   48192
#define C_XI    48256    // 256
#define C_AVEC  48512
#define C_CWV   48576
#define C_WWN   48640
#define C_SU    48704
#define C_RNORM 48768
#define C_SIDX  48832
#define C_RKN   48896    // 128
#define C_WKN   49024    // 32
#define C_MODES 49056    // 16
#define C_RED   49072    // 64
#define C_KNORM 49136
#define C_SWW   49144
#define C_FLOATS 49152
#define C_BYTES (C_FLOATS * 4)

template<int NR>
__device__ __forceinline__ void compute_chunk(const float* __restrict__ Wc,
                                              const float* __restrict__ hsb,
                                              int lr0, int coff, int kbase, int bb,
                                              float (&acc)[2][4]) {
#pragma unroll
    for (int k4 = 0; k4 < 32; k4 += 4) {
        float wa[NR][4];
#pragma unroll
        for (int r = 0; r < NR; r++) {
            float4 w = *(const float4*)(Wc + (lr0 + r) * KPAD + coff + k4);
            wa[r][0] = w.x; wa[r][1] = w.y; wa[r][2] = w.z; wa[r][3] = w.w;
        }
#pragma unroll
        for (int jq = 0; jq < 4; jq++) {
            float2 h2 = *(const float2*)(hsb + (kbase + k4 + jq) * 66 + 2 * bb);
#pragma unroll
            for (int r = 0; r < NR; r++) {
                acc[0][r] += h2.x * wa[r][jq];
                acc[1][r] += h2.y * wa[r][jq];
            }
        }
    }
}

__global__ __launch_bounds__(512, 1) void ctrl_persist(const float* __restrict__ Whh_c,
                                                       const float* __restrict__ Wih_c,
                                                       float* __restrict__ out) {
    extern __shared__ float dyn[];
    float* Wc    = dyn + C_WC;
    float* hs    = dyn + C_HS;
    float* gsv   = dyn + C_GS;
    float* Ls    = dyn + C_LS;
    float* Ms    = dyn + C_MS;
    float* wrs   = dyn + C_WRS;
    float* wrtmp = dyn + C_WRT;
    float* us    = dyn + C_US;
    float* ps    = dyn + C_PS;
    float* wws   = dyn + C_WWS;
    float* xi    = dyn + C_XI;
    float* avec  = dyn + C_AVEC;
    float* cwv   = dyn + C_CWV;
    float* wwn   = dyn + C_WWN;
    float* su    = dyn + C_SU;
    float* rnorm = dyn + C_RNORM;
    int*   sidx  = (int*)(dyn + C_SIDX);
    float* rkn   = dyn + C_RKN;
    float* wkn   = dyn + C_WKN;
    float* modes = dyn + C_MODES;
    float* red   = dyn + C_RED;
    float* knorm = dyn + C_KNORM;
    float* sww   = dyn + C_SWW;

    int tid = threadIdx.x;
    bool isDnc = blockIdx.x < 64;
    int NJ = isDnc ? 4 : 8;
    int njlog = isDnc ? 2 : 3;
    int j0 = isDnc ? blockIdx.x * 4 : 256 + (int)(blockIdx.x - 64) * 8;
    int rows = 4 * NJ;

    // one-time weight cache: k<128 -> Wih_c rv cols; k>=128 -> Whh_c
    for (int i = tid; i < rows * KPAD; i += 512) {
        int lr = i / KPAD, k = i - lr * KPAD;
        int gate = lr >> njlog, jj = lr & (NJ - 1);
        int j = j0 + jj;
        float v = 0.f;
        if (j < HC) {
            int grow = gate * HC + j;
            if (k < 128) v = Wih_c[(size_t)grow * 640 + 512 + k];
            else { int kh = k - 128; if (kh < HC) v = Whh_c[(size_t)grow * HC + kh]; }
        }
        Wc[i] = v;
    }
    if (isDnc) {
        for (int i = tid; i < 64 * 65; i += 512) Ls[i] = 0.f;
        for (int i = tid; i < 64 * 33; i += 512) Ms[i] = 0.f;
        if (tid < 256) wrs[tid] = 0.f;
        if (tid < 64) { us[tid] = 0.f; ps[tid] = 0.f; wws[tid] = 0.f; }
    }

    int g = tid >> 8, t256 = tid & 255;
    int bb = t256 & 31, ry = t256 >> 5;
    int NRv = NJ >> 1;                 // rows per ry: 2 or 4
    int lr0 = ry * NRv;
    int kbase = g * 32;
    int kkr = tid & 63, blr = tid >> 6;
    int ebx = tid & 63, ejj = tid >> 6;
    float creg = 0.f;
    unsigned target = 0;

    int growA[4], jA[4];
#pragma unroll
    for (int r = 0; r < 4; r++) {
        int lr = lr0 + r;
        int gate = lr >> njlog, jj = lr & (NJ - 1);
        jA[r] = j0 + jj;
        growA[r] = gate * HC + jA[r];
    }
    __syncthreads();

    for (int t = 0; t < TT; t++) {
        int par = t & 1;
        const float* hin = g_hc[par];       // h_{t-1}
        float* hout = g_hc[par ^ 1];

        // ---------------- DNC(t-1) on blocks 0..63 (overlapped with others' GEMM) ----------------
        if (isDnc && t > 0) {
            int b = blockIdx.x;
            const float* h = hin + b * HC;

            if (tid < 247) {
                float v = h[HH + tid];
                float a;
                if (tid < 128)      a = tanhf(v);
                else if (tid < 132) a = softplusf_(v);
                else if (tid < 164) a = tanhf(v);
                else if (tid < 165) a = softplusf_(v);
                else if (tid < 197) a = sigmf_(v);
                else if (tid < 229) a = tanhf(v);
                else if (tid < 235) a = sigmf_(v);
                else                a = v;
                xi[tid] = a;
            }
            __syncthreads();

            if (tid < 4) {
                float s = EPSF;
                for (int w = 0; w < 32; w++) { float k = xi[tid * 32 + w]; s += k * k; }
                knorm[tid] = rsqrtf(s);
            } else if (tid == 4) {
                float s = EPSF;
                for (int w = 0; w < 32; w++) { float k = xi[132 + w]; s += k * k; }
                knorm[4] = rsqrtf(s);
            } else if (tid >= 8 && tid < 12) {
                int r = tid - 8;
                float m0 = xi[235 + 3 * r], m1 = xi[236 + 3 * r], m2 = xi[237 + 3 * r];
                float mx = fmaxf(m0, fmaxf(m1, m2));
                float e0 = expf(m0 - mx), e1 = expf(m1 - mx), e2 = expf(m2 - mx);
                float inv = 1.f / (e0 + e1 + e2);
                modes[r * 4 + 0] = e0 * inv; modes[r * 4 + 1] = e1 * inv; modes[r * 4 + 2] = e2 * inv;
            }
            if (tid >= 64 && tid < 128) {
                int n = tid - 64;
                float s = EPSF;
                for (int w = 0; w < 32; w++) { float m = Ms[n * 33 + w]; s += m * m; }
                rnorm[n] = rsqrtf(s);
            }
            __syncthreads();
            if (tid < 128)      { int r = tid >> 5, w = tid & 31; rkn[r * 32 + w] = xi[r * 32 + w] * knorm[r]; }
            else if (tid < 160) { int w = tid - 128; wkn[w] = xi[132 + w] * knorm[4]; }

            if (tid < 64) {
                float psi = 1.f;
#pragma unroll
                for (int r = 0; r < 4; r++) psi *= (1.f - xi[229 + r] * wrs[r * 64 + tid]);
                float un = (us[tid] + wws[tid] - us[tid] * wws[tid]) * psi;
                us[tid] = un; su[tid] = un; sidx[tid] = tid;
            }
            __syncthreads();

            for (int k = 2; k <= 64; k <<= 1)
                for (int j = k >> 1; j > 0; j >>= 1) {
                    if (tid < 64) {
                        int ixj = tid ^ j;
                        if (ixj > tid) {
                            float av = su[tid], bv = su[ixj];
                            int ai = sidx[tid], bi = sidx[ixj];
                            bool up = ((tid & k) == 0);
                            bool gt = (av > bv) || (av == bv && ai > bi);
                            if (gt == up) { su[tid] = bv; su[ixj] = av; sidx[tid] = bi; sidx[ixj] = ai; }
                        }
                    }
                    __syncthreads();
                }

            if (tid < 64) {
                float v = su[tid];
                float incl = v;
#pragma unroll
                for (int s = 1; s < 32; s <<= 1) {
                    float o = __shfl_up_sync(0xffffffffu, incl, s);
                    if ((tid & 31) >= s) incl *= o;
                }
                red[tid] = incl;
            }
            __syncthreads();
            if (tid < 64) {
                float excl = (tid & 31) ? red[tid - 1] : 1.f;
                if (tid >= 32) excl *= red[31];
                avec[sidx[tid]] = (1.f - su[tid]) * excl;
            }
            float wstr = xi[164];
            if (tid >= 128 && tid < 192) {
                int n = tid - 128;
                float d = 0.f;
                for (int w = 0; w < 32; w++) d += wkn[w] * Ms[n * 33 + w];
                cwv[n] = d * rnorm[n] * wstr;
            }
            __syncthreads();

            if (tid < 32) {
                float x = fmaxf(cwv[tid], cwv[tid + 32]);
                for (int s = 16; s; s >>= 1) x = fmaxf(x, __shfl_xor_sync(0xffffffffu, x, s));
                if (tid == 0) red[0] = x;
            }
            __syncthreads();
            float cmx = red[0];
            __syncthreads();
            float ev = (tid < 64) ? expf(cwv[tid] - cmx) : 0.f;
            if (tid < 64) red[tid] = ev;
            __syncthreads();
            if (tid < 32) {
                float x = red[tid] + red[tid + 32];
                for (int s = 16; s; s >>= 1) x += __shfl_xor_sync(0xffffffffu, x, s);
                if (tid == 0) red[0] = x;
            }
            __syncthreads();
            if (tid < 64) cwv[tid] = ev / red[0];
            __syncthreads();

            float ag = xi[233], wg = xi[234];
            if (tid < 64) wwn[tid] = wg * (ag * avec[tid] + (1.f - ag) * cwv[tid]);
            __syncthreads();

            if (tid < 32) {
                float x = wwn[tid] + wwn[tid + 32];
                for (int s = 16; s; s >>= 1) x += __shfl_xor_sync(0xffffffffu, x, s);
                if (tid == 0) sww[0] = x;
            }

            for (int i = tid; i < 2048; i += 512) {
                int n = i >> 5, w = i & 31;
                float m = Ms[n * 33 + w];
                Ms[n * 33 + w] = m * (1.f - wwn[n] * xi[165 + w]) + wwn[n] * xi[197 + w];
            }
            for (int i = tid; i < 4096; i += 512) {
                int ii = i >> 6, jj = i & 63;
                float lv = (ii == jj) ? 0.f
                         : ((1.f - wwn[ii] - wwn[jj]) * Ls[ii * 65 + jj] + wwn[ii] * ps[jj]);
                Ls[ii * 65 + jj] = lv;
            }
            __syncthreads();

            if (tid < 64) ps[tid] = (1.f - sww[0]) * ps[tid] + wwn[tid];
            if (tid >= 64 && tid < 128) {
                int n = tid - 64;
                float s = EPSF;
                for (int w = 0; w < 32; w++) { float m = Ms[n * 33 + w]; s += m * m; }
                rnorm[n] = rsqrtf(s);
            }
            __syncthreads();

            int rr = (tid >> 6) & 3, nn = tid & 63;
            float pre = 0.f;
            {
                float d = 0.f;
                for (int w = 0; w < 32; w++) d += rkn[rr * 32 + w] * Ms[nn * 33 + w];
                pre = d * rnorm[nn] * xi[128 + rr];
            }
            float x = pre;
            for (int s = 16; s; s >>= 1) x = fmaxf(x, __shfl_xor_sync(0xffffffffu, x, s));
            if (tid < 256 && (tid & 31) == 0) red[tid >> 5] = x;
            __syncthreads();
            float gmx = fmaxf(red[rr * 2], red[rr * 2 + 1]);
            float e = expf(pre - gmx);
            __syncthreads();
            x = e;
            for (int s = 16; s; s >>= 1) x += __shfl_xor_sync(0xffffffffu, x, s);
            if (tid < 256 && (tid & 31) == 0) red[tid >> 5] = x;
            __syncthreads();
            float crv = e / (red[rr * 2] + red[rr * 2 + 1]);

            if (tid < 256) {
                float fwv = 0.f, bwv = 0.f;
                const float* wrow = wrs + rr * 64;
                for (int m = 0; m < 64; m++) {
                    float wv = wrow[m];
                    fwv += Ls[nn * 65 + m] * wv;
                    bwv += Ls[m * 65 + nn] * wv;
                }
                wrtmp[rr * 64 + nn] = modes[rr * 4 + 0] * bwv + modes[rr * 4 + 1] * crv + modes[rr * 4 + 2] * fwv;
            }
            __syncthreads();

            if (tid < 256) wrs[tid] = wrtmp[tid];
            if (tid < 64) wws[tid] = wwn[tid];
            if (tid >= 256 && tid < 384) {
                int r = (tid - 256) >> 5, w = tid & 31;
                float s = 0.f;
                for (int n = 0; n < 64; n++) s += wrtmp[r * 64 + n] * Ms[n * 33 + w];
                g_rv[b * 128 + r * 32 + w] = s;   // rv_{t-1}
            }
            __syncthreads();
        }

        // ---------------- phase H: chunks 2..13 (h part, needs only h_{t-1}) ----------------
        float acc[2][4] = {{0.f,0.f,0.f,0.f},{0.f,0.f,0.f,0.f}};
        if (g == 0) {
#pragma unroll
            for (int i2 = 0; i2 < 2; i2++)
#pragma unroll
                for (int r = 0; r < 4; r++)
                    if (r < NRv && jA[r] < HC)
                        acc[i2][r] = g_EWc[((size_t)t * BBATCH + 2 * bb + i2) * G4C + growA[r]];
        }

        float rg[8];
        {
            int kh = kkr;                        // chunk 2: k=128+kkr -> h[kkr]
#pragma unroll
            for (int i = 0; i < 8; i++) rg[i] = hin[(blr + 8 * i) * HC + kh];
        }
#pragma unroll
        for (int i = 0; i < 8; i++) hs[kkr * 66 + blr + 8 * i] = rg[i];
        __syncthreads();

        for (int c = 2; c < 14; c++) {
            if (c < 13) {
                int kh = (c - 1) * 64 + kkr;     // next chunk's h index
#pragma unroll
                for (int i = 0; i < 8; i++) {
                    int bl = blr + 8 * i;
                    rg[i] = (kh < HC) ? hin[bl * HC + kh] : 0.f;
                }
            }
            const float* hsb = hs + (c & 1) * 4224;
            if (isDnc) compute_chunk<2>(Wc, hsb, lr0, c * 64 + kbase, kbase, bb, acc);
            else       compute_chunk<4>(Wc, hsb, lr0, c * 64 + kbase, kbase, bb, acc);
            if (c < 13) {
                float* hsn = hs + ((c + 1) & 1) * 4224;
#pragma unroll
                for (int i = 0; i < 8; i++) hsn[kkr * 66 + blr + 8 * i] = rg[i];
                __syncthreads();
            }
        }

        target += gridDim.x;
        gbar(&g_barC, target);                  // rv_{t-1} visible

        // ---------------- phase RV: chunks 0..1 ----------------
#pragma unroll
        for (int i = 0; i < 8; i++) rg[i] = g_rv[(blr + 8 * i) * 128 + kkr];
#pragma unroll
        for (int i = 0; i < 8; i++) hs[kkr * 66 + blr + 8 * i] = rg[i];
        __syncthreads();
#pragma unroll
        for (int i = 0; i < 8; i++) rg[i] = g_rv[(blr + 8 * i) * 128 + 64 + kkr];
        if (isDnc) compute_chunk<2>(Wc, hs, lr0, kbase, kbase, bb, acc);
        else       compute_chunk<4>(Wc, hs, lr0, kbase, kbase, bb, acc);
#pragma unroll
        for (int i = 0; i < 8; i++) hs[4224 + kkr * 66 + blr + 8 * i] = rg[i];
        __syncthreads();
        if (isDnc) compute_chunk<2>(Wc, hs + 4224, lr0, 64 + kbase, kbase, bb, acc);
        else       compute_chunk<4>(Wc, hs + 4224, lr0, 64 + kbase, kbase, bb, acc);

#pragma unroll
        for (int i2 = 0; i2 < 2; i2++)
#pragma unroll
            for (int r = 0; r < 4; r++)
                if (r < NRv)
                    gsv[g * 2080 + (lr0 + r) * 65 + 2 * bb + i2] = acc[i2][r];
        __syncthreads();

        // ---------------- elementwise LSTM cell ----------------
        {
            int nelem = 64 * NJ;                 // 256 or 512
            if (tid < nelem) {
                int j = j0 + ejj;
                if (j < HC) {
                    float gi = gsv[(0 * NJ + ejj) * 65 + ebx] + gsv[2080 + (0 * NJ + ejj) * 65 + ebx];
                    float gf = gsv[(1 * NJ + ejj) * 65 + ebx] + gsv[2080 + (1 * NJ + ejj) * 65 + ebx];
                    float gg = gsv[(2 * NJ + ejj) * 65 + ebx] + gsv[2080 + (2 * NJ + ejj) * 65 + ebx];
                    float go = gsv[(3 * NJ + ejj) * 65 + ebx] + gsv[2080 + (3 * NJ + ejj) * 65 + ebx];
                    float cn = sigmf_(gf) * creg + sigmf_(gi) * tanhf(gg);
                    creg = cn;
                    float hn = sigmf_(go) * tanhf(cn);
                    hout[ebx * HC + j] = hn;
                    if (j < HH) out[((size_t)ebx * TT + t) * HH + j] = hn;
                }
            }
        }

        target += gridDim.x;
        gbar(&g_barC, target);                  // h_t visible
    }
}

// ---------------- launch ----------------
extern "C" void kernel_launch(void* const* d_in, const int* in_sizes, int n_in,
                              void* d_out, int out_size) {
    (void)in_sizes; (void)n_in; (void)out_size;
    const float* x     = (const float*)d_in[0];
    const float* Wih_e = (const float*)d_in[1];
    const float* Whh_e = (const float*)d_in[2];
    const float* b_e   = (const float*)d_in[3];
    const float* Wih_c = (const float*)d_in[4];
    const float* Whh_c = (const float*)d_in[5];
    const float* b_c   = (const float*)d_in[6];
    float* out = (float*)d_out;

    static int smem_set = 0;
    if (!smem_set) {
        cudaFuncSetAttribute(enc_persist, cudaFuncAttributeMaxDynamicSharedMemorySize, E_BYTES);
        cudaFuncSetAttribute(ctrl_persist, cudaFuncAttributeMaxDynamicSharedMemorySize, C_BYTES);
        smem_set = 1;
    }

    init_states<<<1024, 256>>>();

    // Phase A: x @ Wih_e^T + b_e — tensor cores (3xTF32)
    gemm_tc<<<dim3(128, 32), 256>>>(x, Wih_e, b_e, 0);

    // Encoder recurrence
    enc_persist<<<128, 512, E_BYTES>>>(Whh_e);

    // Phase C: enc @ Wih_c[:, :512]^T + b_c — tensor cores (3xTF32)
    gemm_tc<<<dim3(128, 48), 256>>>(nullptr, Wih_c, b_c, 1);

    // Controller + overlapped DNC recurrence
    ctrl_persist<<<127, 512, C_BYTES>>>(Whh_c, Wih_c, out);
}

// round 11
// speedup vs baseline: 2.9891x; 1.0400x over previous
#include <cuda_runtime.h>
#include <math.h>
#include <stdint.h>

// ---------------- problem constants ----------------
#define TT 256
#define BBATCH 64
#define HH 512
#define HC 759          // HID_C
#define G4C 3036        // 4*HID_C
#define G4E 2048        // 4*H
#define KCC 887         // HC + R*W
#define KPAD 896        // 14 * 64 ; K layout: [rv(128) | h(759) | pad]
#define EPSF 1e-6f

// ---------------- device scratch ----------------
__device__ float g_XWe[(size_t)TT * BBATCH * G4E];
__device__ float g_EWc[(size_t)TT * BBATCH * G4C];
__device__ float g_enc[(size_t)TT * BBATCH * HH];
__device__ float g_he[2][BBATCH * HH];
__device__ float g_hc[2][BBATCH * HC];
__device__ float g_rv[BBATCH * 128];
__device__ unsigned g_ctrE;
__device__ volatile unsigned g_relE;
__device__ unsigned g_ctrC;
__device__ volatile unsigned g_relC;
__device__ unsigned g_rvCtr;

__device__ __forceinline__ float sigmf_(float x) { return 1.f / (1.f + expf(-x)); }
__device__ __forceinline__ float softplusf_(float x) { return fmaxf(x, 0.f) + log1pf(expf(-fabsf(x))); }

// flag-release grid barrier (all blocks co-resident)
__device__ __forceinline__ void gbarF(unsigned* ctr, volatile unsigned* rel,
                                      unsigned nblk, unsigned epoch) {
    __syncthreads();
    if (threadIdx.x == 0) {
        __threadfence();
        unsigned a = atomicAdd(ctr, 1u);
        if (a == epoch * nblk + (nblk - 1u)) {
            *rel = epoch + 1u;
        } else {
            while (*rel < epoch + 1u) { }
        }
        __threadfence();
    }
    __syncthreads();
}

// ---------------- init ----------------
__global__ void init_states() {
    int i = blockIdx.x * blockDim.x + threadIdx.x;
    if (i == 0) { g_ctrE = 0u; g_relE = 0u; g_ctrC = 0u; g_relC = 0u; g_rvCtr = 0u; }
    if (i < 2 * BBATCH * HH) ((float*)g_he)[i] = 0.f;
    if (i < 2 * BBATCH * HC) ((float*)g_hc)[i] = 0.f;
    if (i < BBATCH * 128)    g_rv[i] = 0.f;
}

// ---------------- tf32 helpers ----------------
__device__ __forceinline__ uint32_t f2tf32(float x) {
    uint32_t r;
    asm("cvt.rna.tf32.f32 %0, %1;" : "=r"(r) : "f"(x));
    return r;
}
__device__ __forceinline__ void split_tf32(float x, uint32_t& hi, uint32_t& lo) {
    hi = f2tf32(x);
    lo = f2tf32(x - __uint_as_float(hi));
}
__device__ __forceinline__ void mma_tf32(float& c0, float& c1, float& c2, float& c3,
                                         uint32_t a0, uint32_t a1, uint32_t a2, uint32_t a3,
                                         uint32_t b0, uint32_t b1) {
    asm volatile(
        "mma.sync.aligned.m16n8k8.row.col.f32.tf32.tf32.f32 "
        "{%0,%1,%2,%3}, {%4,%5,%6,%7}, {%8,%9}, {%0,%1,%2,%3};"
        : "+f"(c0), "+f"(c1), "+f"(c2), "+f"(c3)
        : "r"(a0), "r"(a1), "r"(a2), "r"(a3), "r"(b0), "r"(b1));
}

// ---------------- tensor-core input-projection GEMM (3xTF32, unchanged) ----------------
#define GA_STRIDE 36
__global__ __launch_bounds__(256) void gemm_tc(const float* __restrict__ Ain,
                                               const float* __restrict__ Wt,
                                               const float* __restrict__ bias,
                                               int phase) {
    const int Ncols = phase ? G4C : G4E;
    const int ldw   = phase ? 640 : 512;
    float* C        = phase ? g_EWc : g_XWe;
    const float* A  = phase ? g_enc : Ain;

    __shared__ float As[128 * GA_STRIDE];
    __shared__ float Bs[64 * GA_STRIDE];

    int tid = threadIdx.x;
    int m0 = blockIdx.x * 128;
    int n0 = blockIdx.y * 64;
    int warp = tid >> 5, lane = tid & 31;
    int wm = warp & 3, wn = warp >> 2;

    const float* aptr[4];
    float* asmem[4];
#pragma unroll
    for (int i = 0; i < 4; i++) {
        int idx = tid + 256 * i;
        int row = idx >> 3, c4 = (idx & 7) * 4;
        int m = m0 + row;
        const float* arow;
        if (phase) arow = A + (size_t)m * 512;
        else { int t = m >> 6, b = m & 63; arow = A + ((size_t)b * TT + t) * 512; }
        aptr[i] = arow + c4;
        asmem[i] = As + row * GA_STRIDE + c4;
    }
    const float* bptr[2];
    float* bsmem[2];
    bool bok[2];
#pragma unroll
    for (int i = 0; i < 2; i++) {
        int idx = tid + 256 * i;
        int row = idx >> 3, c4 = (idx & 7) * 4;
        int n = n0 + row;
        bok[i] = (n < Ncols);
        bptr[i] = Wt + (size_t)(bok[i] ? n : 0) * ldw + c4;
        bsmem[i] = Bs + row * GA_STRIDE + c4;
    }

    float acc[2][4][4];
#pragma unroll
    for (int mf = 0; mf < 2; mf++)
#pragma unroll
        for (int nf = 0; nf < 4; nf++)
#pragma unroll
            for (int q = 0; q < 4; q++) acc[mf][nf][q] = 0.f;

    float4 ra[4], rb[2];
#pragma unroll
    for (int i = 0; i < 4; i++) ra[i] = *(const float4*)(aptr[i]);
#pragma unroll
    for (int i = 0; i < 2; i++)
        rb[i] = bok[i] ? *(const float4*)(bptr[i]) : make_float4(0.f, 0.f, 0.f, 0.f);

    int la = (lane >> 2);
    int lk = (lane & 3);

    for (int kc = 0; kc < 16; kc++) {
#pragma unroll
        for (int i = 0; i < 4; i++) *(float4*)(asmem[i]) = ra[i];
#pragma unroll
        for (int i = 0; i < 2; i++) *(float4*)(bsmem[i]) = rb[i];
        __syncthreads();

        if (kc < 15) {
            int k0 = (kc + 1) * 32;
#pragma unroll
            for (int i = 0; i < 4; i++) ra[i] = *(const float4*)(aptr[i] + k0);
#pragma unroll
            for (int i = 0; i < 2; i++)
                rb[i] = bok[i] ? *(const float4*)(bptr[i] + k0) : make_float4(0.f, 0.f, 0.f, 0.f);
        }

#pragma unroll
        for (int k8 = 0; k8 < 4; k8++) {
            int kcol = k8 * 8 + lk;
            uint32_t ah[2][4], al[2][4];
#pragma unroll
            for (int mf = 0; mf < 2; mf++) {
                int r = wm * 32 + mf * 16 + la;
                float v0 = As[r * GA_STRIDE + kcol];
                float v1 = As[(r + 8) * GA_STRIDE + kcol];
                float v2 = As[r * GA_STRIDE + kcol + 4];
                float v3 = As[(r + 8) * GA_STRIDE + kcol + 4];
                split_tf32(v0, ah[mf][0], al[mf][0]);
                split_tf32(v1, ah[mf][1], al[mf][1]);
                split_tf32(v2, ah[mf][2], al[mf][2]);
                split_tf32(v3, ah[mf][3], al[mf][3]);
            }
            uint32_t bh[4][2], bl[4][2];
#pragma unroll
            for (int nf = 0; nf < 4; nf++) {
                int bn = wn * 32 + nf * 8 + la;
                float v0 = Bs[bn * GA_STRIDE + k8 * 8 + lk];
                float v1 = Bs[bn * GA_STRIDE + k8 * 8 + lk + 4];
                split_tf32(v0, bh[nf][0], bl[nf][0]);
                split_tf32(v1, bh[nf][1], bl[nf][1]);
            }
#pragma unroll
            for (int mf = 0; mf < 2; mf++)
#pragma unroll
                for (int nf = 0; nf < 4; nf++) {
                    float* c = acc[mf][nf];
                    mma_tf32(c[0], c[1], c[2], c[3],
                             ah[mf][0], ah[mf][1], ah[mf][2], ah[mf][3],
                             bh[nf][0], bh[nf][1]);
                    mma_tf32(c[0], c[1], c[2], c[3],
                             ah[mf][0], ah[mf][1], ah[mf][2], ah[mf][3],
                             bl[nf][0], bl[nf][1]);
                    mma_tf32(c[0], c[1], c[2], c[3],
                             al[mf][0], al[mf][1], al[mf][2], al[mf][3],
                             bh[nf][0], bh[nf][1]);
                }
        }
        __syncthreads();
    }

#pragma unroll
    for (int mf = 0; mf < 2; mf++) {
        int r0 = m0 + wm * 32 + mf * 16 + la;
#pragma unroll
        for (int nf = 0; nf < 4; nf++) {
            int cb = n0 + wn * 32 + nf * 8 + lk * 2;
            float* c = acc[mf][nf];
            if (cb + 1 < Ncols) {
                float2 v0 = make_float2(c[0] + bias[cb], c[1] + bias[cb + 1]);
                float2 v1 = make_float2(c[2] + bias[cb], c[3] + bias[cb + 1]);
                *(float2*)&C[(size_t)r0 * Ncols + cb] = v0;
                *(float2*)&C[(size_t)(r0 + 8) * Ncols + cb] = v1;
            } else if (cb < Ncols) {
                C[(size_t)r0 * Ncols + cb] = c[0] + bias[cb];
                C[(size_t)(r0 + 8) * Ncols + cb] = c[2] + bias[cb];
            }
        }
    }
}

// ---------------- persistent encoder: 128 blocks x 512 threads ----------------
#define E_WC 0
#define E_HS 8192
#define E_GS 16640
#define E_FLOATS 18720
#define E_BYTES (E_FLOATS * 4)

__global__ __launch_bounds__(512, 1) void enc_persist(const float* __restrict__ Whh_e) {
    extern __shared__ float dyn[];
    float* Wc = dyn + E_WC;
    float* hs = dyn + E_HS;
    float* gs = dyn + E_GS;

    int tid = threadIdx.x;
    int j0 = blockIdx.x * 4;

    for (int i = tid; i < 16 * 512; i += 512) {
        int lr = i >> 9, k = i & 511;
        int gate = lr >> 2, jj = lr & 3;
        Wc[i] = Whh_e[(size_t)(gate * HH + j0 + jj) * HH + k];
    }

    int g = tid >> 8;
    int t256 = tid & 255;
    int bb = t256 & 31;
    int ry = t256 >> 5;
    int lr0 = ry * 2;
    int kbase = g * 32;
    int kkr = tid & 63, blr = tid >> 6;
    int ebx = tid & 63, ejj = tid >> 6;
    float creg = 0.f;
    __syncthreads();

    for (int t = 0; t < TT; t++) {
        int par = t & 1;
        const float* hin = g_he[par];
        float* hout = g_he[par ^ 1];

        float acc[2][2] = {{0.f, 0.f}, {0.f, 0.f}};
        if (g == 0) {
#pragma unroll
            for (int i2 = 0; i2 < 2; i2++)
#pragma unroll
                for (int r = 0; r < 2; r++) {
                    int lr = lr0 + r;
                    int gate = lr >> 2, jj = lr & 3;
                    acc[i2][r] = g_XWe[((size_t)t * BBATCH + 2 * bb + i2) * G4E + gate * HH + j0 + jj];
                }
        }

        float rg[8];
#pragma unroll
        for (int i = 0; i < 8; i++) rg[i] = hin[(blr + 8 * i) * HH + kkr];
#pragma unroll
        for (int i = 0; i < 8; i++) hs[kkr * 66 + blr + 8 * i] = rg[i];
        __syncthreads();

        for (int c = 0; c < 8; c++) {
            if (c < 7) {
#pragma unroll
                for (int i = 0; i < 8; i++)
                    rg[i] = hin[(blr + 8 * i) * HH + (c + 1) * 64 + kkr];
            }
            const float* hsb = hs + (c & 1) * 4224;
            const float* wp0 = Wc + lr0 * 512 + c * 64 + kbase;
            const float* wp1 = wp0 + 512;
#pragma unroll
            for (int k4 = 0; k4 < 32; k4 += 4) {
                float4 w0 = *(const float4*)(wp0 + k4);
                float4 w1 = *(const float4*)(wp1 + k4);
                float wa0[4] = {w0.x, w0.y, w0.z, w0.w};
                float wa1[4] = {w1.x, w1.y, w1.z, w1.w};
#pragma unroll
                for (int jq = 0; jq < 4; jq++) {
                    float2 h2 = *(const float2*)(hsb + (kbase + k4 + jq) * 66 + 2 * bb);
                    acc[0][0] += h2.x * wa0[jq]; acc[0][1] += h2.x * wa1[jq];
                    acc[1][0] += h2.y * wa0[jq]; acc[1][1] += h2.y * wa1[jq];
                }
            }
            if (c < 7) {
                float* hsn = hs + ((c + 1) & 1) * 4224;
#pragma unroll
                for (int i = 0; i < 8; i++) hsn[kkr * 66 + blr + 8 * i] = rg[i];
            }
            __syncthreads();
        }

#pragma unroll
        for (int i2 = 0; i2 < 2; i2++)
#pragma unroll
            for (int r = 0; r < 2; r++)
                gs[g * 1040 + (lr0 + r) * 65 + 2 * bb + i2] = acc[i2][r];
        __syncthreads();

        if (tid < 256) {
            int j = j0 + ejj;
            float gi = gs[ejj * 65 + ebx]        + gs[1040 + ejj * 65 + ebx];
            float gf = gs[(4 + ejj) * 65 + ebx]  + gs[1040 + (4 + ejj) * 65 + ebx];
            float gg = gs[(8 + ejj) * 65 + ebx]  + gs[1040 + (8 + ejj) * 65 + ebx];
            float go = gs[(12 + ejj) * 65 + ebx] + gs[1040 + (12 + ejj) * 65 + ebx];
            float cn = sigmf_(gf) * creg + sigmf_(gi) * tanhf(gg);
            creg = cn;
            float hn = sigmf_(go) * tanhf(cn);
            hout[ebx * HH + j] = hn;
            g_enc[((size_t)t * BBATCH + ebx) * HH + j] = hn;
        }

        gbarF(&g_ctrE, &g_relE, gridDim.x, (unsigned)t);
    }
}

// ---------------- persistent controller + overlapped DNC: 148 blocks x 512 threads ----------------
// Blocks 0-63 (DNC): NJ=4 (j0 = bid*4).  Blocks 64-147: NJ=6 (j0 = 256 + (bid-64)*6).
#define C_WC    0        // 24*896 = 21504 (max)
#define C_HS    21504    // 2*64*66 = 8448
#define C_GS    29952    // 2*24*65 = 3120
#define C_LS    33072    // 64*65 = 4160
#define C_MS    37232    // 64*33 = 2112
#define C_WRS   39344
#define C_WRT   39600
#define C_US    39856
#define C_PS    39920
#define C_WWS   39984
#define C_XI    40048
#define C_AVEC  40304
#define C_CWV   40368
#define C_WWN   40432
#define C_SU    40496
#define C_RNORM 40560
#define C_SIDX  40624
#define C_RKN   40688
#define C_WKN   40816
#define C_MODES 40848
#define C_RED   40864
#define C_KNORM 40928
#define C_SWW   40936
#define C_FLOATS 40944
#define C_BYTES (C_FLOATS * 4)
#define GS_STRIDE 1560   // 24*65

template<int NR>
__device__ __forceinline__ void compute_chunk(const float* __restrict__ Wc,
                                              const float* __restrict__ hsb,
                                              int lr0, int coff, int kbase, int bb,
                                              float (&acc)[2][3]) {
#pragma unroll
    for (int k4 = 0; k4 < 32; k4 += 4) {
        float wa[NR][4];
#pragma unroll
        for (int r = 0; r < NR; r++) {
            float4 w = *(const float4*)(Wc + (lr0 + r) * KPAD + coff + k4);
            wa[r][0] = w.x; wa[r][1] = w.y; wa[r][2] = w.z; wa[r][3] = w.w;
        }
#pragma unroll
        for (int jq = 0; jq < 4; jq++) {
            float2 h2 = *(const float2*)(hsb + (kbase + k4 + jq) * 66 + 2 * bb);
#pragma unroll
            for (int r = 0; r < NR; r++) {
                acc[0][r] += h2.x * wa[r][jq];
                acc[1][r] += h2.y * wa[r][jq];
            }
        }
    }
}

__global__ __launch_bounds__(512, 1) void ctrl_persist(const float* __restrict__ Whh_c,
                                                       const float* __restrict__ Wih_c,
                                                       float* __restrict__ out) {
    extern __shared__ float dyn[];
    float* Wc    = dyn + C_WC;
    float* hs    = dyn + C_HS;
    float* gsv   = dyn + C_GS;
    float* Ls    = dyn + C_LS;
    float* Ms    = dyn + C_MS;
    float* wrs   = dyn + C_WRS;
    float* wrtmp = dyn + C_WRT;
    float* us    = dyn + C_US;
    float* ps    = dyn + C_PS;
    float* wws   = dyn + C_WWS;
    float* xi    = dyn + C_XI;
    float* avec  = dyn + C_AVEC;
    float* cwv   = dyn + C_CWV;
    float* wwn   = dyn + C_WWN;
    float* su    = dyn + C_SU;
    float* rnorm = dyn + C_RNORM;
    int*   sidx  = (int*)(dyn + C_SIDX);
    float* rkn   = dyn + C_RKN;
    float* wkn   = dyn + C_WKN;
    float* modes = dyn + C_MODES;
    float* red   = dyn + C_RED;
    float* knorm = dyn + C_KNORM;
    float* sww   = dyn + C_SWW;

    int tid = threadIdx.x;
    bool isDnc = blockIdx.x < 64;
    int NJ = isDnc ? 4 : 6;
    int j0 = isDnc ? (int)blockIdx.x * 4 : 256 + ((int)blockIdx.x - 64) * 6;
    int rows = 4 * NJ;

    // one-time weight cache: k<128 -> Wih_c rv cols; k>=128 -> Whh_c (zero-padded)
    for (int i = tid; i < rows * KPAD; i += 512) {
        int lr = i / KPAD, k = i - lr * KPAD;
        int gate = lr / NJ, jj = lr - gate * NJ;
        int j = j0 + jj;
        float v = 0.f;
        if (j < HC) {
            int grow = gate * HC + j;
            if (k < 128) v = Wih_c[(size_t)grow * 640 + 512 + k];
            else { int kh = k - 128; if (kh < HC) v = Whh_c[(size_t)grow * HC + kh]; }
        }
        Wc[i] = v;
    }
    if (isDnc) {
        for (int i = tid; i < 64 * 65; i += 512) Ls[i] = 0.f;
        for (int i = tid; i < 64 * 33; i += 512) Ms[i] = 0.f;
        if (tid < 256) wrs[tid] = 0.f;
        if (tid < 64) { us[tid] = 0.f; ps[tid] = 0.f; wws[tid] = 0.f; }
    }

    int g = tid >> 8, t256 = tid & 255;
    int bb = t256 & 31, ry = t256 >> 5;
    int NRv = NJ >> 1;                 // 2 or 3 rows per ry
    int lr0 = ry * NRv;
    int kbase = g * 32;
    int kkr = tid & 63, blr = tid >> 6;
    int ebx = tid & 63, ejj = tid >> 6;
    float creg = 0.f;

    int growA[3], jA[3];
#pragma unroll
    for (int r = 0; r < 3; r++) {
        int lr = lr0 + r;
        int gate = lr / NJ, jj = lr - gate * NJ;
        jA[r] = j0 + jj;
        growA[r] = gate * HC + jA[r];
    }
    __syncthreads();

    for (int t = 0; t < TT; t++) {
        int par = t & 1;
        const float* hin = g_hc[par];       // h_{t-1}
        float* hout = g_hc[par ^ 1];

        // ---------------- DNC(t-1) on blocks 0..63 (overlapped with others' GEMM) ----------------
        if (isDnc && t > 0) {
            int b = blockIdx.x;
            const float* h = hin + b * HC;

            if (tid < 247) {
                float v = h[HH + tid];
                float a;
                if (tid < 128)      a = tanhf(v);
                else if (tid < 132) a = softplusf_(v);
                else if (tid < 164) a = tanhf(v);
                else if (tid < 165) a = softplusf_(v);
                else if (tid < 197) a = sigmf_(v);
                else if (tid < 229) a = tanhf(v);
                else if (tid < 235) a = sigmf_(v);
                else                a = v;
                xi[tid] = a;
            }
            __syncthreads();

            if (tid < 4) {
                float s = EPSF;
                for (int w = 0; w < 32; w++) { float k = xi[tid * 32 + w]; s += k * k; }
                knorm[tid] = rsqrtf(s);
            } else if (tid == 4) {
                float s = EPSF;
                for (int w = 0; w < 32; w++) { float k = xi[132 + w]; s += k * k; }
                knorm[4] = rsqrtf(s);
            } else if (tid >= 8 && tid < 12) {
                int r = tid - 8;
                float m0 = xi[235 + 3 * r], m1 = xi[236 + 3 * r], m2 = xi[237 + 3 * r];
                float mx = fmaxf(m0, fmaxf(m1, m2));
                float e0 = expf(m0 - mx), e1 = expf(m1 - mx), e2 = expf(m2 - mx);
                float inv = 1.f / (e0 + e1 + e2);
                modes[r * 4 + 0] = e0 * inv; modes[r * 4 + 1] = e1 * inv; modes[r * 4 + 2] = e2 * inv;
            }
            if (tid >= 64 && tid < 128) {
                int n = tid - 64;
                float s = EPSF;
                for (int w = 0; w < 32; w++) { float m = Ms[n * 33 + w]; s += m * m; }
                rnorm[n] = rsqrtf(s);
            }
            __syncthreads();
            if (tid < 128)      { int r = tid >> 5, w = tid & 31; rkn[r * 32 + w] = xi[r * 32 + w] * knorm[r]; }
            else if (tid < 160) { int w = tid - 128; wkn[w] = xi[132 + w] * knorm[4]; }

            if (tid < 64) {
                float psi = 1.f;
#pragma unroll
                for (int r = 0; r < 4; r++) psi *= (1.f - xi[229 + r] * wrs[r * 64 + tid]);
                float un = (us[tid] + wws[tid] - us[tid] * wws[tid]) * psi;
                us[tid] = un; su[tid] = un; sidx[tid] = tid;
            }
            __syncthreads();

            for (int k = 2; k <= 64; k <<= 1)
                for (int j = k >> 1; j > 0; j >>= 1) {
                    if (tid < 64) {
                        int ixj = tid ^ j;
                        if (ixj > tid) {
                            float av = su[tid], bv = su[ixj];
                            int ai = sidx[tid], bi = sidx[ixj];
                            bool up = ((tid & k) == 0);
                            bool gt = (av > bv) || (av == bv && ai > bi);
                            if (gt == up) { su[tid] = bv; su[ixj] = av; sidx[tid] = bi; sidx[ixj] = ai; }
                        }
                    }
                    __syncthreads();
                }

            if (tid < 64) {
                float v = su[tid];
                float incl = v;
#pragma unroll
                for (int s = 1; s < 32; s <<= 1) {
                    float o = __shfl_up_sync(0xffffffffu, incl, s);
                    if ((tid & 31) >= s) incl *= o;
                }
                red[tid] = incl;
            }
            __syncthreads();
            if (tid < 64) {
                float excl = (tid & 31) ? red[tid - 1] : 1.f;
                if (tid >= 32) excl *= red[31];
                avec[sidx[tid]] = (1.f - su[tid]) * excl;
            }
            float wstr = xi[164];
            if (tid >= 128 && tid < 192) {
                int n = tid - 128;
                float d = 0.f;
                for (int w = 0; w < 32; w++) d += wkn[w] * Ms[n * 33 + w];
                cwv[n] = d * rnorm[n] * wstr;
            }
            __syncthreads();

            if (tid < 32) {
                float x = fmaxf(cwv[tid], cwv[tid + 32]);
                for (int s = 16; s; s >>= 1) x = fmaxf(x, __shfl_xor_sync(0xffffffffu, x, s));
                if (tid == 0) red[0] = x;
            }
            __syncthreads();
            float cmx = red[0];
            __syncthreads();
            float ev = (tid < 64) ? expf(cwv[tid] - cmx) : 0.f;
            if (tid < 64) red[tid] = ev;
            __syncthreads();
            if (tid < 32) {
                float x = red[tid] + red[tid + 32];
                for (int s = 16; s; s >>= 1) x += __shfl_xor_sync(0xffffffffu, x, s);
                if (tid == 0) red[0] = x;
            }
            __syncthreads();
            if (tid < 64) cwv[tid] = ev / red[0];
            __syncthreads();

            float ag = xi[233], wg = xi[234];
            if (tid < 64) wwn[tid] = wg * (ag * avec[tid] + (1.f - ag) * cwv[tid]);
            __syncthreads();

            if (tid < 32) {
                float x = wwn[tid] + wwn[tid + 32];
                for (int s = 16; s; s >>= 1) x += __shfl_xor_sync(0xffffffffu, x, s);
                if (tid == 0) sww[0] = x;
            }

            for (int i = tid; i < 2048; i += 512) {
                int n = i >> 5, w = i & 31;
                float m = Ms[n * 33 + w];
                Ms[n * 33 + w] = m * (1.f - wwn[n] * xi[165 + w]) + wwn[n] * xi[197 + w];
            }
            for (int i = tid; i < 4096; i += 512) {
                int ii = i >> 6, jj = i & 63;
                float lv = (ii == jj) ? 0.f
                         : ((1.f - wwn[ii] - wwn[jj]) * Ls[ii * 65 + jj] + wwn[ii] * ps[jj]);
                Ls[ii * 65 + jj] = lv;
            }
            __syncthreads();

            if (tid < 64) ps[tid] = (1.f - sww[0]) * ps[tid] + wwn[tid];
            if (tid >= 64 && tid < 128) {
                int n = tid - 64;
                float s = EPSF;
                for (int w = 0; w < 32; w++) { float m = Ms[n * 33 + w]; s += m * m; }
                rnorm[n] = rsqrtf(s);
            }
            __syncthreads();

            int rr = (tid >> 6) & 3, nn = tid & 63;
            float pre = 0.f;
            {
                float d = 0.f;
                for (int w = 0; w < 32; w++) d += rkn[rr * 32 + w] * Ms[nn * 33 + w];
                pre = d * rnorm[nn] * xi[128 + rr];
            }
            float x = pre;
            for (int s = 16; s; s >>= 1) x = fmaxf(x, __shfl_xor_sync(0xffffffffu, x, s));
            if (tid < 256 && (tid & 31) == 0) red[tid >> 5] = x;
            __syncthreads();
            float gmx = fmaxf(red[rr * 2], red[rr * 2 + 1]);
            float e = expf(pre - gmx);
            __syncthreads();
            x = e;
            for (int s = 16; s; s >>= 1) x += __shfl_xor_sync(0xffffffffu, x, s);
            if (tid < 256 && (tid & 31) == 0) red[tid >> 5] = x;
            __syncthreads();
            float crv = e / (red[rr * 2] + red[rr * 2 + 1]);

            if (tid < 256) {
                float fwv = 0.f, bwv = 0.f;
                const float* wrow = wrs + rr * 64;
                for (int m = 0; m < 64; m++) {
                    float wv = wrow[m];
                    fwv += Ls[nn * 65 + m] * wv;
                    bwv += Ls[m * 65 + nn] * wv;
                }
                wrtmp[rr * 64 + nn] = modes[rr * 4 + 0] * bwv + modes[rr * 4 + 1] * crv + modes[rr * 4 + 2] * fwv;
            }
            __syncthreads();

            if (tid < 256) wrs[tid] = wrtmp[tid];
            if (tid < 64) wws[tid] = wwn[tid];
            if (tid >= 256 && tid < 384) {
                int r = (tid - 256) >> 5, w = tid & 31;
                float s = 0.f;
                for (int n = 0; n < 64; n++) s += wrtmp[r * 64 + n] * Ms[n * 33 + w];
                g_rv[b * 128 + r * 32 + w] = s;   // rv_{t-1}
            }
            __syncthreads();
            if (tid == 0) { __threadfence(); atomicAdd(&g_rvCtr, 1u); }  // rv publish
        }

        // ---------------- phase H: chunks 2..13 (needs only h_{t-1}) ----------------
        float acc[2][3] = {{0.f,0.f,0.f},{0.f,0.f,0.f}};
        if (g == 0) {
#pragma unroll
            for (int i2 = 0; i2 < 2; i2++)
#pragma unroll
                for (int r = 0; r < 3; r++)
                    if (r < NRv && jA[r] < HC)
                        acc[i2][r] = g_EWc[((size_t)t * BBATCH + 2 * bb + i2) * G4C + growA[r]];
        }

        float rg[8];
        {
            int kh = kkr;
#pragma unroll
            for (int i = 0; i < 8; i++) rg[i] = hin[(blr + 8 * i) * HC + kh];
        }
#pragma unroll
        for (int i = 0; i < 8; i++) hs[kkr * 66 + blr + 8 * i] = rg[i];
        __syncthreads();

        for (int c = 2; c < 14; c++) {
            if (c < 13) {
                int kh = (c - 1) * 64 + kkr;
#pragma unroll
                for (int i = 0; i < 8; i++) {
                    int bl = blr + 8 * i;
                    rg[i] = (kh < HC) ? hin[bl * HC + kh] : 0.f;
                }
            }
            const float* hsb = hs + (c & 1) * 4224;
            if (isDnc) compute_chunk<2>(Wc, hsb, lr0, c * 64 + kbase, kbase, bb, acc);
            else       compute_chunk<3>(Wc, hsb, lr0, c * 64 + kbase, kbase, bb, acc);
            if (c < 13) {
                float* hsn = hs + ((c + 1) & 1) * 4224;
#pragma unroll
                for (int i = 0; i < 8; i++) hsn[kkr * 66 + blr + 8 * i] = rg[i];
                __syncthreads();
            }
        }

        // ---------------- wait for rv_{t-1} (producer semaphore: 64 DNC arrivals) ----------------
        if (tid == 0) {
            while (*(volatile unsigned*)&g_rvCtr < 64u * (unsigned)t) { }
            __threadfence();
        }
        __syncthreads();

        // ---------------- phase RV: chunks 0..1 ----------------
#pragma unroll
        for (int i = 0; i < 8; i++) rg[i] = g_rv[(blr + 8 * i) * 128 + kkr];
#pragma unroll
        for (int i = 0; i < 8; i++) hs[kkr * 66 + blr + 8 * i] = rg[i];
        __syncthreads();
#pragma unroll
        for (int i = 0; i < 8; i++) rg[i] = g_rv[(blr + 8 * i) * 128 + 64 + kkr];
        if (isDnc) compute_chunk<2>(Wc, hs, lr0, kbase, kbase, bb, acc);
        else       compute_chunk<3>(Wc, hs, lr0, kbase, kbase, bb, acc);
#pragma unroll
        for (int i = 0; i < 8; i++) hs[4224 + kkr * 66 + blr + 8 * i] = rg[i];
        __syncthreads();
        if (isDnc) compute_chunk<2>(Wc, hs + 4224, lr0, 64 + kbase, kbase, bb, acc);
        else       compute_chunk<3>(Wc, hs + 4224, lr0, 64 + kbase, kbase, bb, acc);

#pragma unroll
        for (int i2 = 0; i2 < 2; i2++)
#pragma unroll
            for (int r = 0; r < 3; r++)
                if (r < NRv)
                    gsv[g * GS_STRIDE + (lr0 + r) * 65 + 2 * bb + i2] = acc[i2][r];
        __syncthreads();

        // ---------------- elementwise LSTM cell ----------------
        {
            int nelem = 64 * NJ;                 // 256 or 384
            if (tid < nelem) {
                int j = j0 + ejj;
                if (j < HC) {
                    float gi = gsv[(0 * NJ + ejj) * 65 + ebx] + gsv[GS_STRIDE + (0 * NJ + ejj) * 65 + ebx];
                    float gf = gsv[(1 * NJ + ejj) * 65 + ebx] + gsv[GS_STRIDE + (1 * NJ + ejj) * 65 + ebx];
                    float gg = gsv[(2 * NJ + ejj) * 65 + ebx] + gsv[GS_STRIDE + (2 * NJ + ejj) * 65 + ebx];
                    float go = gsv[(3 * NJ + ejj) * 65 + ebx] + gsv[GS_STRIDE + (3 * NJ + ejj) * 65 + ebx];
                    float cn = sigmf_(gf) * creg + sigmf_(gi) * tanhf(gg);
                    creg = cn;
                    float hn = sigmf_(go) * tanhf(cn);
                    hout[ebx * HC + j] = hn;
                    if (j < HH) out[((size_t)ebx * TT + t) * HH + j] = hn;
                }
            }
        }

        gbarF(&g_ctrC, &g_relC, gridDim.x, (unsigned)t);   // h_t visible
    }
}

// ---------------- launch ----------------
extern "C" void kernel_launch(void* const* d_in, const int* in_sizes, int n_in,
                              void* d_out, int out_size) {
    (void)in_sizes; (void)n_in; (void)out_size;
    const float* x     = (const float*)d_in[0];
    const float* Wih_e = (const float*)d_in[1];
    const float* Whh_e = (const float*)d_in[2];
    const float* b_e   = (const float*)d_in[3];
    const float* Wih_c = (const float*)d_in[4];
    const float* Whh_c = (const float*)d_in[5];
    const float* b_c   = (const float*)d_in[6];
    float* out = (float*)d_out;

    static int smem_set = 0;
    if (!smem_set) {
        cudaFuncSetAttribute(enc_persist, cudaFuncAttributeMaxDynamicSharedMemorySize, E_BYTES);
        cudaFuncSetAttribute(ctrl_persist, cudaFuncAttributeMaxDynamicSharedMemorySize, C_BYTES);
        smem_set = 1;
    }

    init_states<<<1024, 256>>>();

    // Phase A: x @ Wih_e^T + b_e — tensor cores (3xTF32)
    gemm_tc<<<dim3(128, 32), 256>>>(x, Wih_e, b_e, 0);

    // Encoder recurrence
    enc_persist<<<128, 512, E_BYTES>>>(Whh_e);

    // Phase C: enc @ Wih_c[:, :512]^T + b_c — tensor cores (3xTF32)
    gemm_tc<<<dim3(128, 48), 256>>>(nullptr, Wih_c, b_c, 1);

    // Controller + overlapped DNC recurrence — 148 blocks (64 DNC NJ=4, 84 NJ=6)
    ctrl_persist<<<148, 512, C_BYTES>>>(Whh_c, Wih_c, out);
}

// round 12
// speedup vs baseline: 3.0083x; 1.0064x over previous
#include <cuda_runtime.h>
#include <math.h>
#include <stdint.h>

// ---------------- problem constants ----------------
#define TT 256
#define BBATCH 64
#define HH 512
#define HC 759          // HID_C
#define G4C 3036        // 4*HID_C
#define G4E 2048        // 4*H
#define KCC 887         // HC + R*W
#define KPAD 896        // 14 * 64 ; K layout: [rv(128) | h(759) | pad]
#define EPSF 1e-6f

// ---------------- device scratch ----------------
__device__ float g_XWe[(size_t)TT * BBATCH * G4E];
__device__ float g_EWc[(size_t)TT * BBATCH * G4C];
__device__ float g_enc[(size_t)TT * BBATCH * HH];
__device__ float g_he[2][BBATCH * HH];
__device__ float g_hc[2][BBATCH * HC];
__device__ float g_rv[BBATCH * 128];
__device__ unsigned g_ctrE;
__device__ volatile unsigned g_relE;
__device__ unsigned g_ctrC;
__device__ volatile unsigned g_relC;
__device__ unsigned g_rvCtr;

__device__ __forceinline__ float sigmf_(float x) { return 1.f / (1.f + expf(-x)); }
__device__ __forceinline__ float softplusf_(float x) { return fmaxf(x, 0.f) + log1pf(expf(-fabsf(x))); }

// flag-release grid barrier (all blocks co-resident)
__device__ __forceinline__ void gbarF(unsigned* ctr, volatile unsigned* rel,
                                      unsigned nblk, unsigned epoch) {
    __syncthreads();
    if (threadIdx.x == 0) {
        __threadfence();
        unsigned a = atomicAdd(ctr, 1u);
        if (a == epoch * nblk + (nblk - 1u)) {
            *rel = epoch + 1u;
        } else {
            while (*rel < epoch + 1u) { }
        }
        __threadfence();
    }
    __syncthreads();
}

// ---------------- init ----------------
__global__ void init_states() {
    int i = blockIdx.x * blockDim.x + threadIdx.x;
    if (i == 0) { g_ctrE = 0u; g_relE = 0u; g_ctrC = 0u; g_relC = 0u; g_rvCtr = 0u; }
    if (i < 2 * BBATCH * HH) ((float*)g_he)[i] = 0.f;
    if (i < 2 * BBATCH * HC) ((float*)g_hc)[i] = 0.f;
    if (i < BBATCH * 128)    g_rv[i] = 0.f;
}

// ---------------- tf32 helpers ----------------
__device__ __forceinline__ uint32_t f2tf32(float x) {
    uint32_t r;
    asm("cvt.rna.tf32.f32 %0, %1;" : "=r"(r) : "f"(x));
    return r;
}
__device__ __forceinline__ void split_tf32(float x, uint32_t& hi, uint32_t& lo) {
    hi = f2tf32(x);
    lo = f2tf32(x - __uint_as_float(hi));
}
__device__ __forceinline__ void mma_tf32(float& c0, float& c1, float& c2, float& c3,
                                         uint32_t a0, uint32_t a1, uint32_t a2, uint32_t a3,
                                         uint32_t b0, uint32_t b1) {
    asm volatile(
        "mma.sync.aligned.m16n8k8.row.col.f32.tf32.tf32.f32 "
        "{%0,%1,%2,%3}, {%4,%5,%6,%7}, {%8,%9}, {%0,%1,%2,%3};"
        : "+f"(c0), "+f"(c1), "+f"(c2), "+f"(c3)
        : "r"(a0), "r"(a1), "r"(a2), "r"(a3), "r"(b0), "r"(b1));
}

// ---------------- tensor-core input-projection GEMM (3xTF32, unchanged) ----------------
#define GA_STRIDE 36
__global__ __launch_bounds__(256) void gemm_tc(const float* __restrict__ Ain,
                                               const float* __restrict__ Wt,
                                               const float* __restrict__ bias,
                                               int phase) {
    const int Ncols = phase ? G4C : G4E;
    const int ldw   = phase ? 640 : 512;
    float* C        = phase ? g_EWc : g_XWe;
    const float* A  = phase ? g_enc : Ain;

    __shared__ float As[128 * GA_STRIDE];
    __shared__ float Bs[64 * GA_STRIDE];

    int tid = threadIdx.x;
    int m0 = blockIdx.x * 128;
    int n0 = blockIdx.y * 64;
    int warp = tid >> 5, lane = tid & 31;
    int wm = warp & 3, wn = warp >> 2;

    const float* aptr[4];
    float* asmem[4];
#pragma unroll
    for (int i = 0; i < 4; i++) {
        int idx = tid + 256 * i;
        int row = idx >> 3, c4 = (idx & 7) * 4;
        int m = m0 + row;
        const float* arow;
        if (phase) arow = A + (size_t)m * 512;
        else { int t = m >> 6, b = m & 63; arow = A + ((size_t)b * TT + t) * 512; }
        aptr[i] = arow + c4;
        asmem[i] = As + row * GA_STRIDE + c4;
    }
    const float* bptr[2];
    float* bsmem[2];
    bool bok[2];
#pragma unroll
    for (int i = 0; i < 2; i++) {
        int idx = tid + 256 * i;
        int row = idx >> 3, c4 = (idx & 7) * 4;
        int n = n0 + row;
        bok[i] = (n < Ncols);
        bptr[i] = Wt + (size_t)(bok[i] ? n : 0) * ldw + c4;
        bsmem[i] = Bs + row * GA_STRIDE + c4;
    }

    float acc[2][4][4];
#pragma unroll
    for (int mf = 0; mf < 2; mf++)
#pragma unroll
        for (int nf = 0; nf < 4; nf++)
#pragma unroll
            for (int q = 0; q < 4; q++) acc[mf][nf][q] = 0.f;

    float4 ra[4], rb[2];
#pragma unroll
    for (int i = 0; i < 4; i++) ra[i] = *(const float4*)(aptr[i]);
#pragma unroll
    for (int i = 0; i < 2; i++)
        rb[i] = bok[i] ? *(const float4*)(bptr[i]) : make_float4(0.f, 0.f, 0.f, 0.f);

    int la = (lane >> 2);
    int lk = (lane & 3);

    for (int kc = 0; kc < 16; kc++) {
#pragma unroll
        for (int i = 0; i < 4; i++) *(float4*)(asmem[i]) = ra[i];
#pragma unroll
        for (int i = 0; i < 2; i++) *(float4*)(bsmem[i]) = rb[i];
        __syncthreads();

        if (kc < 15) {
            int k0 = (kc + 1) * 32;
#pragma unroll
            for (int i = 0; i < 4; i++) ra[i] = *(const float4*)(aptr[i] + k0);
#pragma unroll
            for (int i = 0; i < 2; i++)
                rb[i] = bok[i] ? *(const float4*)(bptr[i] + k0) : make_float4(0.f, 0.f, 0.f, 0.f);
        }

#pragma unroll
        for (int k8 = 0; k8 < 4; k8++) {
            int kcol = k8 * 8 + lk;
            uint32_t ah[2][4], al[2][4];
#pragma unroll
            for (int mf = 0; mf < 2; mf++) {
                int r = wm * 32 + mf * 16 + la;
                float v0 = As[r * GA_STRIDE + kcol];
                float v1 = As[(r + 8) * GA_STRIDE + kcol];
                float v2 = As[r * GA_STRIDE + kcol + 4];
                float v3 = As[(r + 8) * GA_STRIDE + kcol + 4];
                split_tf32(v0, ah[mf][0], al[mf][0]);
                split_tf32(v1, ah[mf][1], al[mf][1]);
                split_tf32(v2, ah[mf][2], al[mf][2]);
                split_tf32(v3, ah[mf][3], al[mf][3]);
            }
            uint32_t bh[4][2], bl[4][2];
#pragma unroll
            for (int nf = 0; nf < 4; nf++) {
                int bn = wn * 32 + nf * 8 + la;
                float v0 = Bs[bn * GA_STRIDE + k8 * 8 + lk];
                float v1 = Bs[bn * GA_STRIDE + k8 * 8 + lk + 4];
                split_tf32(v0, bh[nf][0], bl[nf][0]);
                split_tf32(v1, bh[nf][1], bl[nf][1]);
            }
#pragma unroll
            for (int mf = 0; mf < 2; mf++)
#pragma unroll
                for (int nf = 0; nf < 4; nf++) {
                    float* c = acc[mf][nf];
                    mma_tf32(c[0], c[1], c[2], c[3],
                             ah[mf][0], ah[mf][1], ah[mf][2], ah[mf][3],
                             bh[nf][0], bh[nf][1]);
                    mma_tf32(c[0], c[1], c[2], c[3],
                             ah[mf][0], ah[mf][1], ah[mf][2], ah[mf][3],
                             bl[nf][0], bl[nf][1]);
                    mma_tf32(c[0], c[1], c[2], c[3],
                             al[mf][0], al[mf][1], al[mf][2], al[mf][3],
                             bh[nf][0], bh[nf][1]);
                }
        }
        __syncthreads();
    }

#pragma unroll
    for (int mf = 0; mf < 2; mf++) {
        int r0 = m0 + wm * 32 + mf * 16 + la;
#pragma unroll
        for (int nf = 0; nf < 4; nf++) {
            int cb = n0 + wn * 32 + nf * 8 + lk * 2;
            float* c = acc[mf][nf];
            if (cb + 1 < Ncols) {
                float2 v0 = make_float2(c[0] + bias[cb], c[1] + bias[cb + 1]);
                float2 v1 = make_float2(c[2] + bias[cb], c[3] + bias[cb + 1]);
                *(float2*)&C[(size_t)r0 * Ncols + cb] = v0;
                *(float2*)&C[(size_t)(r0 + 8) * Ncols + cb] = v1;
            } else if (cb < Ncols) {
                C[(size_t)r0 * Ncols + cb] = c[0] + bias[cb];
                C[(size_t)(r0 + 8) * Ncols + cb] = c[2] + bias[cb];
            }
        }
    }
}

// ---------------- persistent encoder: 128 blocks x 512 threads (unchanged) ----------------
#define E_WC 0
#define E_HS 8192
#define E_GS 16640
#define E_FLOATS 18720
#define E_BYTES (E_FLOATS * 4)

__global__ __launch_bounds__(512, 1) void enc_persist(const float* __restrict__ Whh_e) {
    extern __shared__ float dyn[];
    float* Wc = dyn + E_WC;
    float* hs = dyn + E_HS;
    float* gs = dyn + E_GS;

    int tid = threadIdx.x;
    int j0 = blockIdx.x * 4;

    for (int i = tid; i < 16 * 512; i += 512) {
        int lr = i >> 9, k = i & 511;
        int gate = lr >> 2, jj = lr & 3;
        Wc[i] = Whh_e[(size_t)(gate * HH + j0 + jj) * HH + k];
    }

    int g = tid >> 8;
    int t256 = tid & 255;
    int bb = t256 & 31;
    int ry = t256 >> 5;
    int lr0 = ry * 2;
    int kbase = g * 32;
    int kkr = tid & 63, blr = tid >> 6;
    int ebx = tid & 63, ejj = tid >> 6;
    float creg = 0.f;
    __syncthreads();

    for (int t = 0; t < TT; t++) {
        int par = t & 1;
        const float* hin = g_he[par];
        float* hout = g_he[par ^ 1];

        float acc[2][2] = {{0.f, 0.f}, {0.f, 0.f}};
        if (g == 0) {
#pragma unroll
            for (int i2 = 0; i2 < 2; i2++)
#pragma unroll
                for (int r = 0; r < 2; r++) {
                    int lr = lr0 + r;
                    int gate = lr >> 2, jj = lr & 3;
                    acc[i2][r] = g_XWe[((size_t)t * BBATCH + 2 * bb + i2) * G4E + gate * HH + j0 + jj];
                }
        }

        float rg[8];
#pragma unroll
        for (int i = 0; i < 8; i++) rg[i] = hin[(blr + 8 * i) * HH + kkr];
#pragma unroll
        for (int i = 0; i < 8; i++) hs[kkr * 66 + blr + 8 * i] = rg[i];
        __syncthreads();

        for (int c = 0; c < 8; c++) {
            if (c < 7) {
#pragma unroll
                for (int i = 0; i < 8; i++)
                    rg[i] = hin[(blr + 8 * i) * HH + (c + 1) * 64 + kkr];
            }
            const float* hsb = hs + (c & 1) * 4224;
            const float* wp0 = Wc + lr0 * 512 + c * 64 + kbase;
            const float* wp1 = wp0 + 512;
#pragma unroll
            for (int k4 = 0; k4 < 32; k4 += 4) {
                float4 w0 = *(const float4*)(wp0 + k4);
                float4 w1 = *(const float4*)(wp1 + k4);
                float wa0[4] = {w0.x, w0.y, w0.z, w0.w};
                float wa1[4] = {w1.x, w1.y, w1.z, w1.w};
#pragma unroll
                for (int jq = 0; jq < 4; jq++) {
                    float2 h2 = *(const float2*)(hsb + (kbase + k4 + jq) * 66 + 2 * bb);
                    acc[0][0] += h2.x * wa0[jq]; acc[0][1] += h2.x * wa1[jq];
                    acc[1][0] += h2.y * wa0[jq]; acc[1][1] += h2.y * wa1[jq];
                }
            }
            if (c < 7) {
                float* hsn = hs + ((c + 1) & 1) * 4224;
#pragma unroll
                for (int i = 0; i < 8; i++) hsn[kkr * 66 + blr + 8 * i] = rg[i];
            }
            __syncthreads();
        }

#pragma unroll
        for (int i2 = 0; i2 < 2; i2++)
#pragma unroll
            for (int r = 0; r < 2; r++)
                gs[g * 1040 + (lr0 + r) * 65 + 2 * bb + i2] = acc[i2][r];
        __syncthreads();

        if (tid < 256) {
            int j = j0 + ejj;
            float gi = gs[ejj * 65 + ebx]        + gs[1040 + ejj * 65 + ebx];
            float gf = gs[(4 + ejj) * 65 + ebx]  + gs[1040 + (4 + ejj) * 65 + ebx];
            float gg = gs[(8 + ejj) * 65 + ebx]  + gs[1040 + (8 + ejj) * 65 + ebx];
            float go = gs[(12 + ejj) * 65 + ebx] + gs[1040 + (12 + ejj) * 65 + ebx];
            float cn = sigmf_(gf) * creg + sigmf_(gi) * tanhf(gg);
            creg = cn;
            float hn = sigmf_(go) * tanhf(cn);
            hout[ebx * HH + j] = hn;
            g_enc[((size_t)t * BBATCH + ebx) * HH + j] = hn;
        }

        gbarF(&g_ctrE, &g_relE, gridDim.x, (unsigned)t);
    }
}

// ---------------- persistent controller + overlapped DNC: 143 blocks x 512 threads ----------------
// Blocks 0-63 (DNC): NJ=2 (j0 = bid*2).  Blocks 64-142: NJ=8 (j0 = 128 + (bid-64)*8).
#define C_WC    0        // 32*896 = 28672 (max)
#define C_HS    28672    // 2*64*66 = 8448
#define C_GS    37120    // 2*32*65 = 4160
#define C_LS    41280    // 64*65 = 4160
#define C_MS    45440    // 64*33 = 2112
#define C_WRS   47552    // 256
#define C_WRT   47808    // 256
#define C_US    48064
#define C_PS    48128
#define C_WWS   48192
#define C_XI    48256    // 256
#define C_AVEC  48512
#define C_CWV   48576
#define C_WWN   48640
#define C_RNORM 48704
#define C_RKN   48768    // 128
#define C_WKN   48896    // 32
#define C_MODES 48928    // 16
#define C_RED   48944    // 64
#define C_KNORM 49008
#define C_SWW   49016
#define C_FLOATS 49024
#define C_BYTES (C_FLOATS * 4)
#define GS_STRIDE 2080   // 32*65

template<int NR>
__device__ __forceinline__ void compute_chunk(const float* __restrict__ Wc,
                                              const float* __restrict__ hsb,
                                              int lr0, int coff, int kbase, int bb,
                                              float (&acc)[2][4]) {
#pragma unroll
    for (int k4 = 0; k4 < 32; k4 += 4) {
        float wa[NR][4];
#pragma unroll
        for (int r = 0; r < NR; r++) {
            float4 w = *(const float4*)(Wc + (lr0 + r) * KPAD + coff + k4);
            wa[r][0] = w.x; wa[r][1] = w.y; wa[r][2] = w.z; wa[r][3] = w.w;
        }
#pragma unroll
        for (int jq = 0; jq < 4; jq++) {
            float2 h2 = *(const float2*)(hsb + (kbase + k4 + jq) * 66 + 2 * bb);
#pragma unroll
            for (int r = 0; r < NR; r++) {
                acc[0][r] += h2.x * wa[r][jq];
                acc[1][r] += h2.y * wa[r][jq];
            }
        }
    }
}

__global__ __launch_bounds__(512, 1) void ctrl_persist(const float* __restrict__ Whh_c,
                                                       const float* __restrict__ Wih_c,
                                                       float* __restrict__ out) {
    extern __shared__ float dyn[];
    float* Wc    = dyn + C_WC;
    float* hs    = dyn + C_HS;
    float* gsv   = dyn + C_GS;
    float* Ls    = dyn + C_LS;
    float* Ms    = dyn + C_MS;
    float* wrs   = dyn + C_WRS;
    float* wrtmp = dyn + C_WRT;
    float* us    = dyn + C_US;
    float* ps    = dyn + C_PS;
    float* wws   = dyn + C_WWS;
    float* xi    = dyn + C_XI;
    float* avec  = dyn + C_AVEC;
    float* cwv   = dyn + C_CWV;
    float* wwn   = dyn + C_WWN;
    float* rnorm = dyn + C_RNORM;
    float* rkn   = dyn + C_RKN;
    float* wkn   = dyn + C_WKN;
    float* modes = dyn + C_MODES;
    float* red   = dyn + C_RED;
    float* knorm = dyn + C_KNORM;
    float* sww   = dyn + C_SWW;

    int tid = threadIdx.x;
    bool isDnc = blockIdx.x < 64;
    int NJ = isDnc ? 2 : 8;
    int j0 = isDnc ? (int)blockIdx.x * 2 : 128 + ((int)blockIdx.x - 64) * 8;
    int rows = 4 * NJ;

    // one-time weight cache: k<128 -> Wih_c rv cols; k>=128 -> Whh_c (zero-padded)
    for (int i = tid; i < rows * KPAD; i += 512) {
        int lr = i / KPAD, k = i - lr * KPAD;
        int gate = lr / NJ, jj = lr - gate * NJ;
        int j = j0 + jj;
        float v = 0.f;
        if (j < HC) {
            int grow = gate * HC + j;
            if (k < 128) v = Wih_c[(size_t)grow * 640 + 512 + k];
            else { int kh = k - 128; if (kh < HC) v = Whh_c[(size_t)grow * HC + kh]; }
        }
        Wc[i] = v;
    }
    if (isDnc) {
        for (int i = tid; i < 64 * 65; i += 512) Ls[i] = 0.f;
        for (int i = tid; i < 64 * 33; i += 512) Ms[i] = 0.f;
        if (tid < 256) wrs[tid] = 0.f;
        if (tid < 64) { us[tid] = 0.f; ps[tid] = 0.f; wws[tid] = 0.f; }
    }

    int g = tid >> 8, t256 = tid & 255;
    int bb = t256 & 31, ry = t256 >> 5;
    int NRv = NJ >> 1;                 // 1 or 4 rows per ry
    int lr0 = ry * NRv;
    int kbase = g * 32;
    int kkr = tid & 63, blr = tid >> 6;
    int ebx = tid & 63, ejj = tid >> 6;
    float creg = 0.f;

    int growA[4], jA[4];
#pragma unroll
    for (int r = 0; r < 4; r++) {
        int lr = lr0 + r;
        int gate = lr / NJ, jj = lr - gate * NJ;
        jA[r] = j0 + jj;
        growA[r] = gate * HC + jA[r];
    }
    __syncthreads();

    for (int t = 0; t < TT; t++) {
        int par = t & 1;
        const float* hin = g_hc[par];       // h_{t-1}
        float* hout = g_hc[par ^ 1];

        // ---------------- DNC(t-1) on blocks 0..63 (overlapped with others' GEMM) ----------------
        if (isDnc && t > 0) {
            int b = blockIdx.x;
            const float* h = hin + b * HC;

            if (tid < 247) {
                float v = h[HH + tid];
                float a;
                if (tid < 128)      a = tanhf(v);
                else if (tid < 132) a = softplusf_(v);
                else if (tid < 164) a = tanhf(v);
                else if (tid < 165) a = softplusf_(v);
                else if (tid < 197) a = sigmf_(v);
                else if (tid < 229) a = tanhf(v);
                else if (tid < 235) a = sigmf_(v);
                else                a = v;
                xi[tid] = a;
            }
            __syncthreads();

            if (tid < 4) {
                float s = EPSF;
                for (int w = 0; w < 32; w++) { float k = xi[tid * 32 + w]; s += k * k; }
                knorm[tid] = rsqrtf(s);
            } else if (tid == 4) {
                float s = EPSF;
                for (int w = 0; w < 32; w++) { float k = xi[132 + w]; s += k * k; }
                knorm[4] = rsqrtf(s);
            } else if (tid >= 8 && tid < 12) {
                int r = tid - 8;
                float m0 = xi[235 + 3 * r], m1 = xi[236 + 3 * r], m2 = xi[237 + 3 * r];
                float mx = fmaxf(m0, fmaxf(m1, m2));
                float e0 = expf(m0 - mx), e1 = expf(m1 - mx), e2 = expf(m2 - mx);
                float inv = 1.f / (e0 + e1 + e2);
                modes[r * 4 + 0] = e0 * inv; modes[r * 4 + 1] = e1 * inv; modes[r * 4 + 2] = e2 * inv;
            }
            if (tid >= 64 && tid < 128) {   // old-M row norms
                int n = tid - 64;
                float s = EPSF;
                for (int w = 0; w < 32; w++) { float m = Ms[n * 33 + w]; s += m * m; }
                rnorm[n] = rsqrtf(s);
            }
            __syncthreads();
            if (tid < 128)      { int r = tid >> 5, w = tid & 31; rkn[r * 32 + w] = xi[r * 32 + w] * knorm[r]; }
            else if (tid < 160) { int w = tid - 128; wkn[w] = xi[132 + w] * knorm[4]; }
            __syncthreads();

            // warp 0: usage update + register bitonic sort (64 elems, 2/lane) + cumprod
            if (tid < 32) {
                int lane = tid;
                float psi0 = 1.f, psi1 = 1.f;
#pragma unroll
                for (int r = 0; r < 4; r++) {
                    psi0 *= (1.f - xi[229 + r] * wrs[r * 64 + lane]);
                    psi1 *= (1.f - xi[229 + r] * wrs[r * 64 + lane + 32]);
                }
                float u0 = us[lane], u1 = us[lane + 32];
                float w0 = wws[lane], w1 = wws[lane + 32];
                float av = (u0 + w0 - u0 * w0) * psi0;
                float bv = (u1 + w1 - u1 * w1) * psi1;
                us[lane] = av; us[lane + 32] = bv;
                int ai = lane, bi = lane + 32;
                // stable bitonic sort ascending on (value, index); pos(a)=lane, pos(b)=lane+32
#pragma unroll
                for (int k = 2; k <= 64; k <<= 1) {
#pragma unroll
                    for (int j = k >> 1; j > 0; j >>= 1) {
                        if (j >= 32) {
                            // k==64, j==32: pair (lane, lane+32), ascending
                            bool gt = (av > bv) || (av == bv && ai > bi);
                            if (gt) { float tv = av; av = bv; bv = tv; int ti = ai; ai = bi; bi = ti; }
                        } else {
                            float pav = __shfl_xor_sync(0xffffffffu, av, j);
                            int   pai = __shfl_xor_sync(0xffffffffu, ai, j);
                            float pbv = __shfl_xor_sync(0xffffffffu, bv, j);
                            int   pbi = __shfl_xor_sync(0xffffffffu, bi, j);
                            bool lower = ((lane & j) == 0);
                            bool upA = ((lane & k) == 0);
                            bool gtA = (av > pav) || (av == pav && ai > pai);
                            if ((lower == upA) ? gtA : !gtA) { av = pav; ai = pai; }
                            bool upB = (((lane + 32) & k) == 0);
                            bool gtB = (bv > pbv) || (bv == pbv && bi > pbi);
                            if ((lower == upB) ? gtB : !gtB) { bv = pbv; bi = pbi; }
                        }
                    }
                }
                // exclusive cumprod over sorted values
                float sa = av;
#pragma unroll
                for (int s = 1; s < 32; s <<= 1) {
                    float o = __shfl_up_sync(0xffffffffu, sa, s);
                    if (lane >= s) sa *= o;
                }
                float totA = __shfl_sync(0xffffffffu, sa, 31);
                float sb = bv;
#pragma unroll
                for (int s = 1; s < 32; s <<= 1) {
                    float o = __shfl_up_sync(0xffffffffu, sb, s);
                    if (lane >= s) sb *= o;
                }
                float prevA = __shfl_up_sync(0xffffffffu, sa, 1);
                float prevB = __shfl_up_sync(0xffffffffu, sb, 1);
                float exA = (lane == 0) ? 1.f : prevA;
                float exB = ((lane == 0) ? 1.f : prevB) * totA;
                avec[ai] = (1.f - av) * exA;
                avec[bi] = (1.f - bv) * exB;
            }
            // warps 4,5: content write scores (concurrent with sort)
            float wstr = xi[164];
            if (tid >= 128 && tid < 192) {
                int n = tid - 128;
                float d = 0.f;
                for (int w = 0; w < 32; w++) d += wkn[w] * Ms[n * 33 + w];
                cwv[n] = d * rnorm[n] * wstr;
            }
            __syncthreads();

            // softmax over 64 (write content weights)
            if (tid < 32) {
                float x = fmaxf(cwv[tid], cwv[tid + 32]);
                for (int s = 16; s; s >>= 1) x = fmaxf(x, __shfl_xor_sync(0xffffffffu, x, s));
                if (tid == 0) red[0] = x;
            }
            __syncthreads();
            float cmx = red[0];
            __syncthreads();
            float ev = (tid < 64) ? expf(cwv[tid] - cmx) : 0.f;
            if (tid < 64) red[tid] = ev;
            __syncthreads();
            if (tid < 32) {
                float x = red[tid] + red[tid + 32];
                for (int s = 16; s; s >>= 1) x += __shfl_xor_sync(0xffffffffu, x, s);
                if (tid == 0) red[0] = x;
            }
            __syncthreads();
            if (tid < 64) cwv[tid] = ev / red[0];
            __syncthreads();

            float ag = xi[233], wg = xi[234];
            if (tid < 64) wwn[tid] = wg * (ag * avec[tid] + (1.f - ag) * cwv[tid]);
            __syncthreads();

            if (tid < 32) {
                float x = wwn[tid] + wwn[tid + 32];
                for (int s = 16; s; s >>= 1) x += __shfl_xor_sync(0xffffffffu, x, s);
                if (tid == 0) sww[0] = x;
            }

            for (int i = tid; i < 2048; i += 512) {
                int n = i >> 5, w = i & 31;
                float m = Ms[n * 33 + w];
                Ms[n * 33 + w] = m * (1.f - wwn[n] * xi[165 + w]) + wwn[n] * xi[197 + w];
            }
            for (int i = tid; i < 4096; i += 512) {
                int ii = i >> 6, jj = i & 63;
                float lv = (ii == jj) ? 0.f
                         : ((1.f - wwn[ii] - wwn[jj]) * Ls[ii * 65 + jj] + wwn[ii] * ps[jj]);
                Ls[ii * 65 + jj] = lv;
            }
            __syncthreads();

            if (tid < 64) ps[tid] = (1.f - sww[0]) * ps[tid] + wwn[tid];
            if (tid >= 64 && tid < 128) {       // new-M row norms
                int n = tid - 64;
                float s = EPSF;
                for (int w = 0; w < 32; w++) { float m = Ms[n * 33 + w]; s += m * m; }
                rnorm[n] = rsqrtf(s);
            }
            __syncthreads();

            int rr = (tid >> 6) & 3, nn = tid & 63;
            float pre = 0.f;
            {
                float d = 0.f;
                for (int w = 0; w < 32; w++) d += rkn[rr * 32 + w] * Ms[nn * 33 + w];
                pre = d * rnorm[nn] * xi[128 + rr];
            }
            float x = pre;
            for (int s = 16; s; s >>= 1) x = fmaxf(x, __shfl_xor_sync(0xffffffffu, x, s));
            if (tid < 256 && (tid & 31) == 0) red[tid >> 5] = x;
            __syncthreads();
            float gmx = fmaxf(red[rr * 2], red[rr * 2 + 1]);
            float e = expf(pre - gmx);
            __syncthreads();
            x = e;
            for (int s = 16; s; s >>= 1) x += __shfl_xor_sync(0xffffffffu, x, s);
            if (tid < 256 && (tid & 31) == 0) red[tid >> 5] = x;
            __syncthreads();
            float crv = e / (red[rr * 2] + red[rr * 2 + 1]);

            if (tid < 256) {
                float fwv = 0.f, bwv = 0.f;
                const float* wrow = wrs + rr * 64;
                for (int m = 0; m < 64; m++) {
                    float wv = wrow[m];
                    fwv += Ls[nn * 65 + m] * wv;
                    bwv += Ls[m * 65 + nn] * wv;
                }
                wrtmp[rr * 64 + nn] = modes[rr * 4 + 0] * bwv + modes[rr * 4 + 1] * crv + modes[rr * 4 + 2] * fwv;
            }
            __syncthreads();

            if (tid < 256) wrs[tid] = wrtmp[tid];
            if (tid < 64) wws[tid] = wwn[tid];
            if (tid >= 256 && tid < 384) {
                int r = (tid - 256) >> 5, w = tid & 31;
                float s = 0.f;
                for (int n = 0; n < 64; n++) s += wrtmp[r * 64 + n] * Ms[n * 33 + w];
                g_rv[b * 128 + r * 32 + w] = s;   // rv_{t-1}
            }
            __syncthreads();
            if (tid == 0) { __threadfence(); atomicAdd(&g_rvCtr, 1u); }  // rv publish
        }

        // ---------------- phase H: chunks 2..13 (needs only h_{t-1}) ----------------
        float acc[2][4] = {{0.f,0.f,0.f,0.f},{0.f,0.f,0.f,0.f}};
        if (g == 0) {
#pragma unroll
            for (int i2 = 0; i2 < 2; i2++)
#pragma unroll
                for (int r = 0; r < 4; r++)
                    if (r < NRv && jA[r] < HC)
                        acc[i2][r] = g_EWc[((size_t)t * BBATCH + 2 * bb + i2) * G4C + growA[r]];
        }

        float rg[8];
        {
            int kh = kkr;
#pragma unroll
            for (int i = 0; i < 8; i++) rg[i] = hin[(blr + 8 * i) * HC + kh];
        }
#pragma unroll
        for (int i = 0; i < 8; i++) hs[kkr * 66 + blr + 8 * i] = rg[i];
        __syncthreads();

        for (int c = 2; c < 14; c++) {
            if (c < 13) {
                int kh = (c - 1) * 64 + kkr;
#pragma unroll
                for (int i = 0; i < 8; i++) {
                    int bl = blr + 8 * i;
                    rg[i] = (kh < HC) ? hin[bl * HC + kh] : 0.f;
                }
            }
            const float* hsb = hs + (c & 1) * 4224;
            if (isDnc) compute_chunk<1>(Wc, hsb, lr0, c * 64 + kbase, kbase, bb, acc);
            else       compute_chunk<4>(Wc, hsb, lr0, c * 64 + kbase, kbase, bb, acc);
            if (c < 13) {
                float* hsn = hs + ((c + 1) & 1) * 4224;
#pragma unroll
                for (int i = 0; i < 8; i++) hsn[kkr * 66 + blr + 8 * i] = rg[i];
                __syncthreads();
            }
        }

        // ---------------- wait for rv_{t-1} (producer semaphore: 64 DNC arrivals) ----------------
        if (tid == 0) {
            while (*(volatile unsigned*)&g_rvCtr < 64u * (unsigned)t) { }
            __threadfence();
        }
        __syncthreads();

        // ---------------- phase RV: chunks 0..1 ----------------
#pragma unroll
        for (int i = 0; i < 8; i++) rg[i] = g_rv[(blr + 8 * i) * 128 + kkr];
#pragma unroll
        for (int i = 0; i < 8; i++) hs[kkr * 66 + blr + 8 * i] = rg[i];
        __syncthreads();
#pragma unroll
        for (int i = 0; i < 8; i++) rg[i] = g_rv[(blr + 8 * i) * 128 + 64 + kkr];
        if (isDnc) compute_chunk<1>(Wc, hs, lr0, kbase, kbase, bb, acc);
        else       compute_chunk<4>(Wc, hs, lr0, kbase, kbase, bb, acc);
#pragma unroll
        for (int i = 0; i < 8; i++) hs[4224 + kkr * 66 + blr + 8 * i] = rg[i];
        __syncthreads();
        if (isDnc) compute_chunk<1>(Wc, hs + 4224, lr0, 64 + kbase, kbase, bb, acc);
        else       compute_chunk<4>(Wc, hs + 4224, lr0, 64 + kbase, kbase, bb, acc);

#pragma unroll
        for (int i2 = 0; i2 < 2; i2++)
#pragma unroll
            for (int r = 0; r < 4; r++)
                if (r < NRv)
                    gsv[g * GS_STRIDE + (lr0 + r) * 65 + 2 * bb + i2] = acc[i2][r];
        __syncthreads();

        // ---------------- elementwise LSTM cell ----------------
        {
            int nelem = 64 * NJ;                 // 128 or 512
            if (tid < nelem) {
                int j = j0 + ejj;
                if (j < HC) {
                    float gi = gsv[(0 * NJ + ejj) * 65 + ebx] + gsv[GS_STRIDE + (0 * NJ + ejj) * 65 + ebx];
                    float gf = gsv[(1 * NJ + ejj) * 65 + ebx] + gsv[GS_STRIDE + (1 * NJ + ejj) * 65 + ebx];
                    float gg = gsv[(2 * NJ + ejj) * 65 + ebx] + gsv[GS_STRIDE + (2 * NJ + ejj) * 65 + ebx];
                    float go = gsv[(3 * NJ + ejj) * 65 + ebx] + gsv[GS_STRIDE + (3 * NJ + ejj) * 65 + ebx];
                    float cn = sigmf_(gf) * creg + sigmf_(gi) * tanhf(gg);
                    creg = cn;
                    float hn = sigmf_(go) * tanhf(cn);
                    hout[ebx * HC + j] = hn;
                    if (j < HH) out[((size_t)ebx * TT + t) * HH + j] = hn;
                }
            }
        }

        gbarF(&g_ctrC, &g_relC, gridDim.x, (unsigned)t);   // h_t visible
    }
}

// ---------------- launch ----------------
extern "C" void kernel_launch(void* const* d_in, const int* in_sizes, int n_in,
                              void* d_out, int out_size) {
    (void)in_sizes; (void)n_in; (void)out_size;
    const float* x     = (const float*)d_in[0];
    const float* Wih_e = (const float*)d_in[1];
    const float* Whh_e = (const float*)d_in[2];
    const float* b_e   = (const float*)d_in[3];
    const float* Wih_c = (const float*)d_in[4];
    const float* Whh_c = (const float*)d_in[5];
    const float* b_c   = (const float*)d_in[6];
    float* out = (float*)d_out;

    static int smem_set = 0;
    if (!smem_set) {
        cudaFuncSetAttribute(enc_persist, cudaFuncAttributeMaxDynamicSharedMemorySize, E_BYTES);
        cudaFuncSetAttribute(ctrl_persist, cudaFuncAttributeMaxDynamicSharedMemorySize, C_BYTES);
        smem_set = 1;
    }

    init_states<<<1024, 256>>>();

    // Phase A: x @ Wih_e^T + b_e — tensor cores (3xTF32)
    gemm_tc<<<dim3(128, 32), 256>>>(x, Wih_e, b_e, 0);

    // Encoder recurrence
    enc_persist<<<128, 512, E_BYTES>>>(Whh_e);

    // Phase C: enc @ Wih_c[:, :512]^T + b_c — tensor cores (3xTF32)
    gemm_tc<<<dim3(128, 48), 256>>>(nullptr, Wih_c, b_c, 1);

    // Controller + overlapped DNC recurrence — 143 blocks (64 DNC NJ=2, 79 NJ=8)
    ctrl_persist<<<143, 512, C_BYTES>>>(Whh_c, Wih_c, out);
}

// round 13
// speedup vs baseline: 3.2477x; 1.0796x over previous
#include <cuda_runtime.h>
#include <math.h>
#include <stdint.h>

// ---------------- problem constants ----------------
#define TT 256
#define BBATCH 64
#define HH 512
#define HC 759          // HID_C
#define G4C 3036        // 4*HID_C
#define G4E 2048        // 4*H
#define KCC 887         // HC + R*W
#define KPAD 896        // 28 * 32 ; K layout: [rv(128) | h(759) | pad]
#define WSTRIDE 900     // weight smem row stride (900 % 32 == 4 -> conflict-free B frags)
#define EPSF 1e-6f

// ---------------- device scratch ----------------
__device__ float g_XWe[(size_t)TT * BBATCH * G4E];
__device__ float g_EWc[(size_t)TT * BBATCH * G4C];
__device__ float g_enc[(size_t)TT * BBATCH * HH];
__device__ float g_he[2][BBATCH * HH];
__device__ float g_hc[2][BBATCH * HC];
__device__ float g_rv[BBATCH * 128];
__device__ unsigned g_ctrE;
__device__ volatile unsigned g_relE;
__device__ unsigned g_ctrC;
__device__ volatile unsigned g_relC;
__device__ unsigned g_rvCtr;

__device__ __forceinline__ float sigmf_(float x) { return 1.f / (1.f + expf(-x)); }
__device__ __forceinline__ float softplusf_(float x) { return fmaxf(x, 0.f) + log1pf(expf(-fabsf(x))); }

// flag-release grid barrier (all blocks co-resident)
__device__ __forceinline__ void gbarF(unsigned* ctr, volatile unsigned* rel,
                                      unsigned nblk, unsigned epoch) {
    __syncthreads();
    if (threadIdx.x == 0) {
        __threadfence();
        unsigned a = atomicAdd(ctr, 1u);
        if (a == epoch * nblk + (nblk - 1u)) {
            *rel = epoch + 1u;
        } else {
            while (*rel < epoch + 1u) { }
        }
        __threadfence();
    }
    __syncthreads();
}

// ---------------- init ----------------
__global__ void init_states() {
    int i = blockIdx.x * blockDim.x + threadIdx.x;
    if (i == 0) { g_ctrE = 0u; g_relE = 0u; g_ctrC = 0u; g_relC = 0u; g_rvCtr = 0u; }
    if (i < 2 * BBATCH * HH) ((float*)g_he)[i] = 0.f;
    if (i < 2 * BBATCH * HC) ((float*)g_hc)[i] = 0.f;
    if (i < BBATCH * 128)    g_rv[i] = 0.f;
}

// ---------------- tf32 helpers ----------------
__device__ __forceinline__ uint32_t f2tf32(float x) {
    uint32_t r;
    asm("cvt.rna.tf32.f32 %0, %1;" : "=r"(r) : "f"(x));
    return r;
}
__device__ __forceinline__ void split_tf32(float x, uint32_t& hi, uint32_t& lo) {
    hi = f2tf32(x);
    lo = f2tf32(x - __uint_as_float(hi));
}
__device__ __forceinline__ void mma_tf32(float& c0, float& c1, float& c2, float& c3,
                                         uint32_t a0, uint32_t a1, uint32_t a2, uint32_t a3,
                                         uint32_t b0, uint32_t b1) {
    asm volatile(
        "mma.sync.aligned.m16n8k8.row.col.f32.tf32.tf32.f32 "
        "{%0,%1,%2,%3}, {%4,%5,%6,%7}, {%8,%9}, {%0,%1,%2,%3};"
        : "+f"(c0), "+f"(c1), "+f"(c2), "+f"(c3)
        : "r"(a0), "r"(a1), "r"(a2), "r"(a3), "r"(b0), "r"(b1));
}

// ---------------- tensor-core input-projection GEMM (3xTF32, unchanged) ----------------
#define GA_STRIDE 36
__global__ __launch_bounds__(256) void gemm_tc(const float* __restrict__ Ain,
                                               const float* __restrict__ Wt,
                                               const float* __restrict__ bias,
                                               int phase) {
    const int Ncols = phase ? G4C : G4E;
    const int ldw   = phase ? 640 : 512;
    float* C        = phase ? g_EWc : g_XWe;
    const float* A  = phase ? g_enc : Ain;

    __shared__ float As[128 * GA_STRIDE];
    __shared__ float Bs[64 * GA_STRIDE];

    int tid = threadIdx.x;
    int m0 = blockIdx.x * 128;
    int n0 = blockIdx.y * 64;
    int warp = tid >> 5, lane = tid & 31;
    int wm = warp & 3, wn = warp >> 2;

    const float* aptr[4];
    float* asmem[4];
#pragma unroll
    for (int i = 0; i < 4; i++) {
        int idx = tid + 256 * i;
        int row = idx >> 3, c4 = (idx & 7) * 4;
        int m = m0 + row;
        const float* arow;
        if (phase) arow = A + (size_t)m * 512;
        else { int t = m >> 6, b = m & 63; arow = A + ((size_t)b * TT + t) * 512; }
        aptr[i] = arow + c4;
        asmem[i] = As + row * GA_STRIDE + c4;
    }
    const float* bptr[2];
    float* bsmem[2];
    bool bok[2];
#pragma unroll
    for (int i = 0; i < 2; i++) {
        int idx = tid + 256 * i;
        int row = idx >> 3, c4 = (idx & 7) * 4;
        int n = n0 + row;
        bok[i] = (n < Ncols);
        bptr[i] = Wt + (size_t)(bok[i] ? n : 0) * ldw + c4;
        bsmem[i] = Bs + row * GA_STRIDE + c4;
    }

    float acc[2][4][4];
#pragma unroll
    for (int mf = 0; mf < 2; mf++)
#pragma unroll
        for (int nf = 0; nf < 4; nf++)
#pragma unroll
            for (int q = 0; q < 4; q++) acc[mf][nf][q] = 0.f;

    float4 ra[4], rb[2];
#pragma unroll
    for (int i = 0; i < 4; i++) ra[i] = *(const float4*)(aptr[i]);
#pragma unroll
    for (int i = 0; i < 2; i++)
        rb[i] = bok[i] ? *(const float4*)(bptr[i]) : make_float4(0.f, 0.f, 0.f, 0.f);

    int la = (lane >> 2);
    int lk = (lane & 3);

    for (int kc = 0; kc < 16; kc++) {
#pragma unroll
        for (int i = 0; i < 4; i++) *(float4*)(asmem[i]) = ra[i];
#pragma unroll
        for (int i = 0; i < 2; i++) *(float4*)(bsmem[i]) = rb[i];
        __syncthreads();

        if (kc < 15) {
            int k0 = (kc + 1) * 32;
#pragma unroll
            for (int i = 0; i < 4; i++) ra[i] = *(const float4*)(aptr[i] + k0);
#pragma unroll
            for (int i = 0; i < 2; i++)
                rb[i] = bok[i] ? *(const float4*)(bptr[i] + k0) : make_float4(0.f, 0.f, 0.f, 0.f);
        }

#pragma unroll
        for (int k8 = 0; k8 < 4; k8++) {
            int kcol = k8 * 8 + lk;
            uint32_t ah[2][4], al[2][4];
#pragma unroll
            for (int mf = 0; mf < 2; mf++) {
                int r = wm * 32 + mf * 16 + la;
                float v0 = As[r * GA_STRIDE + kcol];
                float v1 = As[(r + 8) * GA_STRIDE + kcol];
                float v2 = As[r * GA_STRIDE + kcol + 4];
                float v3 = As[(r + 8) * GA_STRIDE + kcol + 4];
                split_tf32(v0, ah[mf][0], al[mf][0]);
                split_tf32(v1, ah[mf][1], al[mf][1]);
                split_tf32(v2, ah[mf][2], al[mf][2]);
                split_tf32(v3, ah[mf][3], al[mf][3]);
            }
            uint32_t bh[4][2], bl[4][2];
#pragma unroll
            for (int nf = 0; nf < 4; nf++) {
                int bn = wn * 32 + nf * 8 + la;
                float v0 = Bs[bn * GA_STRIDE + k8 * 8 + lk];
                float v1 = Bs[bn * GA_STRIDE + k8 * 8 + lk + 4];
                split_tf32(v0, bh[nf][0], bl[nf][0]);
                split_tf32(v1, bh[nf][1], bl[nf][1]);
            }
#pragma unroll
            for (int mf = 0; mf < 2; mf++)
#pragma unroll
                for (int nf = 0; nf < 4; nf++) {
                    float* c = acc[mf][nf];
                    mma_tf32(c[0], c[1], c[2], c[3],
                             ah[mf][0], ah[mf][1], ah[mf][2], ah[mf][3],
                             bh[nf][0], bh[nf][1]);
                    mma_tf32(c[0], c[1], c[2], c[3],
                             ah[mf][0], ah[mf][1], ah[mf][2], ah[mf][3],
                             bl[nf][0], bl[nf][1]);
                    mma_tf32(c[0], c[1], c[2], c[3],
                             al[mf][0], al[mf][1], al[mf][2], al[mf][3],
                             bh[nf][0], bh[nf][1]);
                }
        }
        __syncthreads();
    }

#pragma unroll
    for (int mf = 0; mf < 2; mf++) {
        int r0 = m0 + wm * 32 + mf * 16 + la;
#pragma unroll
        for (int nf = 0; nf < 4; nf++) {
            int cb = n0 + wn * 32 + nf * 8 + lk * 2;
            float* c = acc[mf][nf];
            if (cb + 1 < Ncols) {
                float2 v0 = make_float2(c[0] + bias[cb], c[1] + bias[cb + 1]);
                float2 v1 = make_float2(c[2] + bias[cb], c[3] + bias[cb + 1]);
                *(float2*)&C[(size_t)r0 * Ncols + cb] = v0;
                *(float2*)&C[(size_t)(r0 + 8) * Ncols + cb] = v1;
            } else if (cb < Ncols) {
                C[(size_t)r0 * Ncols + cb] = c[0] + bias[cb];
                C[(size_t)(r0 + 8) * Ncols + cb] = c[2] + bias[cb];
            }
        }
    }
}

// ---------------- persistent encoder: 128 blocks x 512 threads (unchanged) ----------------
#define E_WC 0
#define E_HS 8192
#define E_GS 16640
#define E_FLOATS 18720
#define E_BYTES (E_FLOATS * 4)

__global__ __launch_bounds__(512, 1) void enc_persist(const float* __restrict__ Whh_e) {
    extern __shared__ float dyn[];
    float* Wc = dyn + E_WC;
    float* hs = dyn + E_HS;
    float* gs = dyn + E_GS;

    int tid = threadIdx.x;
    int j0 = blockIdx.x * 4;

    for (int i = tid; i < 16 * 512; i += 512) {
        int lr = i >> 9, k = i & 511;
        int gate = lr >> 2, jj = lr & 3;
        Wc[i] = Whh_e[(size_t)(gate * HH + j0 + jj) * HH + k];
    }

    int g = tid >> 8;
    int t256 = tid & 255;
    int bb = t256 & 31;
    int ry = t256 >> 5;
    int lr0 = ry * 2;
    int kbase = g * 32;
    int kkr = tid & 63, blr = tid >> 6;
    int ebx = tid & 63, ejj = tid >> 6;
    float creg = 0.f;
    __syncthreads();

    for (int t = 0; t < TT; t++) {
        int par = t & 1;
        const float* hin = g_he[par];
        float* hout = g_he[par ^ 1];

        float acc[2][2] = {{0.f, 0.f}, {0.f, 0.f}};
        if (g == 0) {
#pragma unroll
            for (int i2 = 0; i2 < 2; i2++)
#pragma unroll
                for (int r = 0; r < 2; r++) {
                    int lr = lr0 + r;
                    int gate = lr >> 2, jj = lr & 3;
                    acc[i2][r] = g_XWe[((size_t)t * BBATCH + 2 * bb + i2) * G4E + gate * HH + j0 + jj];
                }
        }

        float rg[8];
#pragma unroll
        for (int i = 0; i < 8; i++) rg[i] = hin[(blr + 8 * i) * HH + kkr];
#pragma unroll
        for (int i = 0; i < 8; i++) hs[kkr * 66 + blr + 8 * i] = rg[i];
        __syncthreads();

        for (int c = 0; c < 8; c++) {
            if (c < 7) {
#pragma unroll
                for (int i = 0; i < 8; i++)
                    rg[i] = hin[(blr + 8 * i) * HH + (c + 1) * 64 + kkr];
            }
            const float* hsb = hs + (c & 1) * 4224;
            const float* wp0 = Wc + lr0 * 512 + c * 64 + kbase;
            const float* wp1 = wp0 + 512;
#pragma unroll
            for (int k4 = 0; k4 < 32; k4 += 4) {
                float4 w0 = *(const float4*)(wp0 + k4);
                float4 w1 = *(const float4*)(wp1 + k4);
                float wa0[4] = {w0.x, w0.y, w0.z, w0.w};
                float wa1[4] = {w1.x, w1.y, w1.z, w1.w};
#pragma unroll
                for (int jq = 0; jq < 4; jq++) {
                    float2 h2 = *(const float2*)(hsb + (kbase + k4 + jq) * 66 + 2 * bb);
                    acc[0][0] += h2.x * wa0[jq]; acc[0][1] += h2.x * wa1[jq];
                    acc[1][0] += h2.y * wa0[jq]; acc[1][1] += h2.y * wa1[jq];
                }
            }
            if (c < 7) {
                float* hsn = hs + ((c + 1) & 1) * 4224;
#pragma unroll
                for (int i = 0; i < 8; i++) hsn[kkr * 66 + blr + 8 * i] = rg[i];
            }
            __syncthreads();
        }

#pragma unroll
        for (int i2 = 0; i2 < 2; i2++)
#pragma unroll
            for (int r = 0; r < 2; r++)
                gs[g * 1040 + (lr0 + r) * 65 + 2 * bb + i2] = acc[i2][r];
        __syncthreads();

        if (tid < 256) {
            int j = j0 + ejj;
            float gi = gs[ejj * 65 + ebx]        + gs[1040 + ejj * 65 + ebx];
            float gf = gs[(4 + ejj) * 65 + ebx]  + gs[1040 + (4 + ejj) * 65 + ebx];
            float gg = gs[(8 + ejj) * 65 + ebx]  + gs[1040 + (8 + ejj) * 65 + ebx];
            float go = gs[(12 + ejj) * 65 + ebx] + gs[1040 + (12 + ejj) * 65 + ebx];
            float cn = sigmf_(gf) * creg + sigmf_(gi) * tanhf(gg);
            creg = cn;
            float hn = sigmf_(go) * tanhf(cn);
            hout[ebx * HH + j] = hn;
            g_enc[((size_t)t * BBATCH + ebx) * HH + j] = hn;
        }

        gbarF(&g_ctrE, &g_relE, gridDim.x, (unsigned)t);
    }
}

// ---------------- persistent controller (tensor-core GEMM) + overlapped DNC ----------------
// 143 blocks x 512 threads. Blocks 0-63 (DNC): NJ=2. Blocks 64-142: NJ=8.
// hs: tf32 hi/lo, layout [buf][hilo][b*36 + k], chunk = 32 k.
#define C_WC    0        // 32*900 = 28800
#define C_HS    28800    // 2 buf * 2 (hi,lo) * 64*36 = 9216
#define C_GS    38016    // 4160 (nonDNC: 2 groups x 32x65 ; DNC: 4 groups x 8x65)
#define C_LS    42176    // 64*65 = 4160
#define C_MS    46336    // 64*33 = 2112
#define C_WRS   48448
#define C_WRT   48704
#define C_US    48960
#define C_PS    49024
#define C_WWS   49088
#define C_XI    49152    // 256
#define C_AVEC  49408
#define C_CWV   49472
#define C_WWN   49536
#define C_RNORM 49600
#define C_RKN   49664    // 128
#define C_WKN   49792
#define C_MODES 49824
#define C_RED   49840
#define C_KNORM 49904
#define C_SWW   49912
#define C_FLOATS 49920
#define C_BYTES (C_FLOATS * 4)
#define HS_HALF 2304     // 64*36

// one m16n8k8 k-slab (k8 = 8 wide) for nnt n-tiles
__device__ __forceinline__ void mma_slab(const uint32_t* __restrict__ Hh,
                                         const uint32_t* __restrict__ Hl,
                                         const float* __restrict__ Wc,
                                         int kloc, int kg, int m0, int la, int lk,
                                         int ntbase, int nnt, float* acc) {
    uint32_t ah[4], al4[4];
    int r0 = (m0 + la) * 36 + kloc + lk;
    int r1 = (m0 + la + 8) * 36 + kloc + lk;
    ah[0] = Hh[r0];     ah[1] = Hh[r1];
    ah[2] = Hh[r0 + 4]; ah[3] = Hh[r1 + 4];
    al4[0] = Hl[r0];     al4[1] = Hl[r1];
    al4[2] = Hl[r0 + 4]; al4[3] = Hl[r1 + 4];
#pragma unroll
    for (int nt = 0; nt < 2; nt++) {
        if (nt >= nnt) break;
        int nr = ntbase + nt * 8 + la;
        float w0 = Wc[nr * WSTRIDE + kg + lk];
        float w1 = Wc[nr * WSTRIDE + kg + lk + 4];
        uint32_t bh0, bl0, bh1, bl1;
        split_tf32(w0, bh0, bl0);
        split_tf32(w1, bh1, bl1);
        float* c = acc + nt * 4;
        mma_tf32(c[0], c[1], c[2], c[3], ah[0], ah[1], ah[2], ah[3], bh0, bh1);
        mma_tf32(c[0], c[1], c[2], c[3], ah[0], ah[1], ah[2], ah[3], bl0, bl1);
        mma_tf32(c[0], c[1], c[2], c[3], al4[0], al4[1], al4[2], al4[3], bh0, bh1);
    }
}

__global__ __launch_bounds__(512, 1) void ctrl_persist(const float* __restrict__ Whh_c,
                                                       const float* __restrict__ Wih_c,
                                                       float* __restrict__ out) {
    extern __shared__ float dyn[];
    float* Wc    = dyn + C_WC;
    float* gsv   = dyn + C_GS;
    float* Ls    = dyn + C_LS;
    float* Ms    = dyn + C_MS;
    float* wrs   = dyn + C_WRS;
    float* wrtmp = dyn + C_WRT;
    float* us    = dyn + C_US;
    float* ps    = dyn + C_PS;
    float* wws   = dyn + C_WWS;
    float* xi    = dyn + C_XI;
    float* avec  = dyn + C_AVEC;
    float* cwv   = dyn + C_CWV;
    float* wwn   = dyn + C_WWN;
    float* rnorm = dyn + C_RNORM;
    float* rkn   = dyn + C_RKN;
    float* wkn   = dyn + C_WKN;
    float* modes = dyn + C_MODES;
    float* red   = dyn + C_RED;
    float* knorm = dyn + C_KNORM;
    float* sww   = dyn + C_SWW;

    int tid = threadIdx.x;
    bool isDnc = blockIdx.x < 64;
    int NJ = isDnc ? 2 : 8;
    int j0 = isDnc ? (int)blockIdx.x * 2 : 128 + ((int)blockIdx.x - 64) * 8;
    int rows = 4 * NJ;

    // one-time weight cache: k<128 -> Wih_c rv cols; k>=128 -> Whh_c (zero-padded)
    for (int i = tid; i < rows * WSTRIDE; i += 512) {
        int lr = i / WSTRIDE, k = i - lr * WSTRIDE;
        int gate = lr / NJ, jj = lr - gate * NJ;
        int j = j0 + jj;
        float v = 0.f;
        if (j < HC && k < KPAD) {
            int grow = gate * HC + j;
            if (k < 128) v = Wih_c[(size_t)grow * 640 + 512 + k];
            else { int kh = k - 128; if (kh < HC) v = Whh_c[(size_t)grow * HC + kh]; }
        }
        Wc[i] = v;
    }
    if (isDnc) {
        for (int i = tid; i < 64 * 65; i += 512) Ls[i] = 0.f;
        for (int i = tid; i < 64 * 33; i += 512) Ms[i] = 0.f;
        if (tid < 256) wrs[tid] = 0.f;
        if (tid < 64) { us[tid] = 0.f; ps[tid] = 0.f; wws[tid] = 0.f; }
    }

    int warp = tid >> 5, lane = tid & 31;
    int la = lane >> 2, lk = lane & 3;
    // GEMM warp tiling
    int wm = warp & 3;
    int m0 = wm * 16;
    int wn2 = (warp >> 2) & 1;        // non-DNC only
    int wkN = warp >> 3;              // non-DNC k-split (0,1)
    int wkD = warp >> 2;              // DNC k-split (0..3)
    int ntbase = isDnc ? 0 : wn2 * 16;
    int nnt = isDnc ? 1 : 2;
    // staging mapping
    int kk2 = tid & 31, brow = tid >> 5;   // brow 0..15 ; b = brow + 16*i
    // elementwise mapping
    int ebx = tid & 63, ejj = tid >> 6;
    float creg = 0.f;
    __syncthreads();

    for (int t = 0; t < TT; t++) {
        int par = t & 1;
        const float* hin = g_hc[par];       // h_{t-1}
        float* hout = g_hc[par ^ 1];

        // ---------------- DNC(t-1) on blocks 0..63 (overlapped with others' GEMM) ----------------
        if (isDnc && t > 0) {
            int b = blockIdx.x;
            const float* h = hin + b * HC;

            if (tid < 247) {
                float v = h[HH + tid];
                float a;
                if (tid < 128)      a = tanhf(v);
                else if (tid < 132) a = softplusf_(v);
                else if (tid < 164) a = tanhf(v);
                else if (tid < 165) a = softplusf_(v);
                else if (tid < 197) a = sigmf_(v);
                else if (tid < 229) a = tanhf(v);
                else if (tid < 235) a = sigmf_(v);
                else                a = v;
                xi[tid] = a;
            }
            __syncthreads();

            if (tid < 4) {
                float s = EPSF;
                for (int w = 0; w < 32; w++) { float k = xi[tid * 32 + w]; s += k * k; }
                knorm[tid] = rsqrtf(s);
            } else if (tid == 4) {
                float s = EPSF;
                for (int w = 0; w < 32; w++) { float k = xi[132 + w]; s += k * k; }
                knorm[4] = rsqrtf(s);
            } else if (tid >= 8 && tid < 12) {
                int r = tid - 8;
                float m0v = xi[235 + 3 * r], m1 = xi[236 + 3 * r], m2 = xi[237 + 3 * r];
                float mx = fmaxf(m0v, fmaxf(m1, m2));
                float e0 = expf(m0v - mx), e1 = expf(m1 - mx), e2 = expf(m2 - mx);
                float inv = 1.f / (e0 + e1 + e2);
                modes[r * 4 + 0] = e0 * inv; modes[r * 4 + 1] = e1 * inv; modes[r * 4 + 2] = e2 * inv;
            }
            if (tid >= 64 && tid < 128) {   // old-M row norms
                int n = tid - 64;
                float s = EPSF;
                for (int w = 0; w < 32; w++) { float m = Ms[n * 33 + w]; s += m * m; }
                rnorm[n] = rsqrtf(s);
            }
            __syncthreads();
            if (tid < 128)      { int r = tid >> 5, w = tid & 31; rkn[r * 32 + w] = xi[r * 32 + w] * knorm[r]; }
            else if (tid < 160) { int w = tid - 128; wkn[w] = xi[132 + w] * knorm[4]; }
            __syncthreads();

            // warp 0: usage update + register bitonic sort (64 elems, 2/lane) + cumprod
            if (tid < 32) {
                int ln = tid;
                float psi0 = 1.f, psi1 = 1.f;
#pragma unroll
                for (int r = 0; r < 4; r++) {
                    psi0 *= (1.f - xi[229 + r] * wrs[r * 64 + ln]);
                    psi1 *= (1.f - xi[229 + r] * wrs[r * 64 + ln + 32]);
                }
                float u0 = us[ln], u1 = us[ln + 32];
                float w0 = wws[ln], w1 = wws[ln + 32];
                float av = (u0 + w0 - u0 * w0) * psi0;
                float bv = (u1 + w1 - u1 * w1) * psi1;
                us[ln] = av; us[ln + 32] = bv;
                int ai = ln, bi = ln + 32;
#pragma unroll
                for (int k = 2; k <= 64; k <<= 1) {
#pragma unroll
                    for (int j = k >> 1; j > 0; j >>= 1) {
                        if (j >= 32) {
                            bool gt = (av > bv) || (av == bv && ai > bi);
                            if (gt) { float tv = av; av = bv; bv = tv; int ti = ai; ai = bi; bi = ti; }
                        } else {
                            float pav = __shfl_xor_sync(0xffffffffu, av, j);
                            int   pai = __shfl_xor_sync(0xffffffffu, ai, j);
                            float pbv = __shfl_xor_sync(0xffffffffu, bv, j);
                            int   pbi = __shfl_xor_sync(0xffffffffu, bi, j);
                            bool lower = ((ln & j) == 0);
                            bool upA = ((ln & k) == 0);
                            bool gtA = (av > pav) || (av == pav && ai > pai);
                            if ((lower == upA) ? gtA : !gtA) { av = pav; ai = pai; }
                            bool upB = (((ln + 32) & k) == 0);
                            bool gtB = (bv > pbv) || (bv == pbv && bi > pbi);
                            if ((lower == upB) ? gtB : !gtB) { bv = pbv; bi = pbi; }
                        }
                    }
                }
                float sa = av;
#pragma unroll
                for (int s = 1; s < 32; s <<= 1) {
                    float o = __shfl_up_sync(0xffffffffu, sa, s);
                    if (ln >= s) sa *= o;
                }
                float totA = __shfl_sync(0xffffffffu, sa, 31);
                float sb = bv;
#pragma unroll
                for (int s = 1; s < 32; s <<= 1) {
                    float o = __shfl_up_sync(0xffffffffu, sb, s);
                    if (ln >= s) sb *= o;
                }
                float prevA = __shfl_up_sync(0xffffffffu, sa, 1);
                float prevB = __shfl_up_sync(0xffffffffu, sb, 1);
                float exA = (ln == 0) ? 1.f : prevA;
                float exB = ((ln == 0) ? 1.f : prevB) * totA;
                avec[ai] = (1.f - av) * exA;
                avec[bi] = (1.f - bv) * exB;
            }
            float wstr = xi[164];
            if (tid >= 128 && tid < 192) {
                int n = tid - 128;
                float d = 0.f;
                for (int w = 0; w < 32; w++) d += wkn[w] * Ms[n * 33 + w];
                cwv[n] = d * rnorm[n] * wstr;
            }
            __syncthreads();

            if (tid < 32) {
                float x = fmaxf(cwv[tid], cwv[tid + 32]);
                for (int s = 16; s; s >>= 1) x = fmaxf(x, __shfl_xor_sync(0xffffffffu, x, s));
                if (tid == 0) red[0] = x;
            }
            __syncthreads();
            float cmx = red[0];
            __syncthreads();
            float ev = (tid < 64) ? expf(cwv[tid] - cmx) : 0.f;
            if (tid < 64) red[tid] = ev;
            __syncthreads();
            if (tid < 32) {
                float x = red[tid] + red[tid + 32];
                for (int s = 16; s; s >>= 1) x += __shfl_xor_sync(0xffffffffu, x, s);
                if (tid == 0) red[0] = x;
            }
            __syncthreads();
            if (tid < 64) cwv[tid] = ev / red[0];
            __syncthreads();

            float ag = xi[233], wg = xi[234];
            if (tid < 64) wwn[tid] = wg * (ag * avec[tid] + (1.f - ag) * cwv[tid]);
            __syncthreads();

            if (tid < 32) {
                float x = wwn[tid] + wwn[tid + 32];
                for (int s = 16; s; s >>= 1) x += __shfl_xor_sync(0xffffffffu, x, s);
                if (tid == 0) sww[0] = x;
            }

            for (int i = tid; i < 2048; i += 512) {
                int n = i >> 5, w = i & 31;
                float m = Ms[n * 33 + w];
                Ms[n * 33 + w] = m * (1.f - wwn[n] * xi[165 + w]) + wwn[n] * xi[197 + w];
            }
            for (int i = tid; i < 4096; i += 512) {
                int ii = i >> 6, jj = i & 63;
                float lv = (ii == jj) ? 0.f
                         : ((1.f - wwn[ii] - wwn[jj]) * Ls[ii * 65 + jj] + wwn[ii] * ps[jj]);
                Ls[ii * 65 + jj] = lv;
            }
            __syncthreads();

            if (tid < 64) ps[tid] = (1.f - sww[0]) * ps[tid] + wwn[tid];
            if (tid >= 64 && tid < 128) {       // new-M row norms
                int n = tid - 64;
                float s = EPSF;
                for (int w = 0; w < 32; w++) { float m = Ms[n * 33 + w]; s += m * m; }
                rnorm[n] = rsqrtf(s);
            }
            __syncthreads();

            int rr = (tid >> 6) & 3, nn = tid & 63;
            float pre = 0.f;
            {
                float d = 0.f;
                for (int w = 0; w < 32; w++) d += rkn[rr * 32 + w] * Ms[nn * 33 + w];
                pre = d * rnorm[nn] * xi[128 + rr];
            }
            float x = pre;
            for (int s = 16; s; s >>= 1) x = fmaxf(x, __shfl_xor_sync(0xffffffffu, x, s));
            if (tid < 256 && (tid & 31) == 0) red[tid >> 5] = x;
            __syncthreads();
            float gmx = fmaxf(red[rr * 2], red[rr * 2 + 1]);
            float e = expf(pre - gmx);
            __syncthreads();
            x = e;
            for (int s = 16; s; s >>= 1) x += __shfl_xor_sync(0xffffffffu, x, s);
            if (tid < 256 && (tid & 31) == 0) red[tid >> 5] = x;
            __syncthreads();
            float crv = e / (red[rr * 2] + red[rr * 2 + 1]);

            if (tid < 256) {
                float fwv = 0.f, bwv = 0.f;
                const float* wrow = wrs + rr * 64;
                for (int m = 0; m < 64; m++) {
                    float wv = wrow[m];
                    fwv += Ls[nn * 65 + m] * wv;
                    bwv += Ls[m * 65 + nn] * wv;
                }
                wrtmp[rr * 64 + nn] = modes[rr * 4 + 0] * bwv + modes[rr * 4 + 1] * crv + modes[rr * 4 + 2] * fwv;
            }
            __syncthreads();

            if (tid < 256) wrs[tid] = wrtmp[tid];
            if (tid < 64) wws[tid] = wwn[tid];
            if (tid >= 256 && tid < 384) {
                int r = (tid - 256) >> 5, w = tid & 31;
                float s = 0.f;
                for (int n = 0; n < 64; n++) s += wrtmp[r * 64 + n] * Ms[n * 33 + w];
                g_rv[b * 128 + r * 32 + w] = s;   // rv_{t-1}
            }
            __syncthreads();
            if (tid == 0) { __threadfence(); atomicAdd(&g_rvCtr, 1u); }  // rv publish
        }

        // ---------------- EWc prefetch (consumed in elementwise) ----------------
        float ew[4] = {0.f, 0.f, 0.f, 0.f};
        {
            bool act = (!isDnc) || (tid < 128);
            int j = j0 + ejj;
            if (act && j < HC) {
#pragma unroll
                for (int gate = 0; gate < 4; gate++)
                    ew[gate] = g_EWc[((size_t)t * BBATCH + ebx) * G4C + gate * HC + j];
            }
        }

        // ---------------- phase H: chunks 4..27 (needs only h_{t-1}) ----------------
        float acc[8];
#pragma unroll
        for (int q = 0; q < 8; q++) acc[q] = 0.f;

        float sv[4];
        {
            int kh = 4 * 32 + kk2 - 128;      // chunk 4 -> h index
#pragma unroll
            for (int i = 0; i < 4; i++) {
                int b = brow + 16 * i;
                sv[i] = (kh < HC) ? hin[b * HC + kh] : 0.f;
            }
        }
        {
            float* Hb = dyn + C_HS + (4 & 1) * (2 * HS_HALF);
#pragma unroll
            for (int i = 0; i < 4; i++) {
                uint32_t hb, lb;
                split_tf32(sv[i], hb, lb);
                Hb[(brow + 16 * i) * 36 + kk2] = __uint_as_float(hb);
                Hb[HS_HALF + (brow + 16 * i) * 36 + kk2] = __uint_as_float(lb);
            }
        }
        __syncthreads();

        for (int c = 4; c < 28; c++) {
            if (c < 27) {
                int kh = (c + 1) * 32 + kk2 - 128;
#pragma unroll
                for (int i = 0; i < 4; i++) {
                    int b = brow + 16 * i;
                    sv[i] = (kh < HC) ? hin[b * HC + kh] : 0.f;
                }
            }
            const uint32_t* Hh = (const uint32_t*)(dyn + C_HS + (c & 1) * (2 * HS_HALF));
            const uint32_t* Hl = Hh + HS_HALF;
            int kg0 = c * 32;
            if (isDnc) {
                mma_slab(Hh, Hl, Wc, wkD * 8, kg0 + wkD * 8, m0, la, lk, 0, 1, acc);
            } else {
                mma_slab(Hh, Hl, Wc, wkN * 16,     kg0 + wkN * 16,     m0, la, lk, ntbase, 2, acc);
                mma_slab(Hh, Hl, Wc, wkN * 16 + 8, kg0 + wkN * 16 + 8, m0, la, lk, ntbase, 2, acc);
            }
            if (c < 27) {
                float* Hb = dyn + C_HS + ((c + 1) & 1) * (2 * HS_HALF);
#pragma unroll
                for (int i = 0; i < 4; i++) {
                    uint32_t hb, lb;
                    split_tf32(sv[i], hb, lb);
                    Hb[(brow + 16 * i) * 36 + kk2] = __uint_as_float(hb);
                    Hb[HS_HALF + (brow + 16 * i) * 36 + kk2] = __uint_as_float(lb);
                }
            }
            __syncthreads();
        }

        // ---------------- wait for rv_{t-1} ----------------
        if (tid == 0) {
            while (*(volatile unsigned*)&g_rvCtr < 64u * (unsigned)t) { }
            __threadfence();
        }
        __syncthreads();

        // ---------------- phase RV: chunks 0..3 ----------------
        {
#pragma unroll
            for (int i = 0; i < 4; i++)
                sv[i] = g_rv[(brow + 16 * i) * 128 + kk2];
            float* Hb = dyn + C_HS;
#pragma unroll
            for (int i = 0; i < 4; i++) {
                uint32_t hb, lb;
                split_tf32(sv[i], hb, lb);
                Hb[(brow + 16 * i) * 36 + kk2] = __uint_as_float(hb);
                Hb[HS_HALF + (brow + 16 * i) * 36 + kk2] = __uint_as_float(lb);
            }
        }
        __syncthreads();
        for (int c = 0; c < 4; c++) {
            if (c < 3) {
#pragma unroll
                for (int i = 0; i < 4; i++)
                    sv[i] = g_rv[(brow + 16 * i) * 128 + (c + 1) * 32 + kk2];
            }
            const uint32_t* Hh = (const uint32_t*)(dyn + C_HS + (c & 1) * (2 * HS_HALF));
            const uint32_t* Hl = Hh + HS_HALF;
            int kg0 = c * 32;
            if (isDnc) {
                mma_slab(Hh, Hl, Wc, wkD * 8, kg0 + wkD * 8, m0, la, lk, 0, 1, acc);
            } else {
                mma_slab(Hh, Hl, Wc, wkN * 16,     kg0 + wkN * 16,     m0, la, lk, ntbase, 2, acc);
                mma_slab(Hh, Hl, Wc, wkN * 16 + 8, kg0 + wkN * 16 + 8, m0, la, lk, ntbase, 2, acc);
            }
            if (c < 3) {
                float* Hb = dyn + C_HS + ((c + 1) & 1) * (2 * HS_HALF);
#pragma unroll
                for (int i = 0; i < 4; i++) {
                    uint32_t hb, lb;
                    split_tf32(sv[i], hb, lb);
                    Hb[(brow + 16 * i) * 36 + kk2] = __uint_as_float(hb);
                    Hb[HS_HALF + (brow + 16 * i) * 36 + kk2] = __uint_as_float(lb);
                }
            }
            __syncthreads();
        }

        // ---------------- epilogue: C frags -> gsv ----------------
        {
            int kg = isDnc ? wkD : wkN;
            int gstride = isDnc ? 520 : 2080;
            float* gs = gsv + kg * gstride;
#pragma unroll
            for (int nt = 0; nt < 2; nt++) {
                if (nt >= nnt) break;
                int nrow0 = ntbase + nt * 8 + 2 * lk;
                float* c = acc + nt * 4;
                gs[nrow0 * 65 + m0 + la]           = c[0];
                gs[(nrow0 + 1) * 65 + m0 + la]     = c[1];
                gs[nrow0 * 65 + m0 + la + 8]       = c[2];
                gs[(nrow0 + 1) * 65 + m0 + la + 8] = c[3];
            }
        }
        __syncthreads();

        // ---------------- elementwise LSTM cell ----------------
        {
            bool act = (!isDnc) || (tid < 128);
            int j = j0 + ejj;
            if (act && j < HC) {
                float gv[4];
#pragma unroll
                for (int gate = 0; gate < 4; gate++) {
                    int row = gate * NJ + ejj;
                    float s = ew[gate];
                    if (isDnc)
                        s += gsv[row * 65 + ebx] + gsv[520 + row * 65 + ebx]
                           + gsv[1040 + row * 65 + ebx] + gsv[1560 + row * 65 + ebx];
                    else
                        s += gsv[row * 65 + ebx] + gsv[2080 + row * 65 + ebx];
                    gv[gate] = s;
                }
                float cn = sigmf_(gv[1]) * creg + sigmf_(gv[0]) * tanhf(gv[2]);
                creg = cn;
                float hn = sigmf_(gv[3]) * tanhf(cn);
                hout[ebx * HC + j] = hn;
                if (j < HH) out[((size_t)ebx * TT + t) * HH + j] = hn;
            }
        }

        gbarF(&g_ctrC, &g_relC, gridDim.x, (unsigned)t);   // h_t visible
    }
}

// ---------------- launch ----------------
extern "C" void kernel_launch(void* const* d_in, const int* in_sizes, int n_in,
                              void* d_out, int out_size) {
    (void)in_sizes; (void)n_in; (void)out_size;
    const float* x     = (const float*)d_in[0];
    const float* Wih_e = (const float*)d_in[1];
    const float* Whh_e = (const float*)d_in[2];
    const float* b_e   = (const float*)d_in[3];
    const float* Wih_c = (const float*)d_in[4];
    const float* Whh_c = (const float*)d_in[5];
    const float* b_c   = (const float*)d_in[6];
    float* out = (float*)d_out;

    static int smem_set = 0;
    if (!smem_set) {
        cudaFuncSetAttribute(enc_persist, cudaFuncAttributeMaxDynamicSharedMemorySize, E_BYTES);
        cudaFuncSetAttribute(ctrl_persist, cudaFuncAttributeMaxDynamicSharedMemorySize, C_BYTES);
        smem_set = 1;
    }

    init_states<<<1024, 256>>>();

    // Phase A: x @ Wih_e^T + b_e — tensor cores (3xTF32)
    gemm_tc<<<dim3(128, 32), 256>>>(x, Wih_e, b_e, 0);

    // Encoder recurrence
    enc_persist<<<128, 512, E_BYTES>>>(Whh_e);

    // Phase C: enc @ Wih_c[:, :512]^T + b_c — tensor cores (3xTF32)
    gemm_tc<<<dim3(128, 48), 256>>>(nullptr, Wih_c, b_c, 1);

    // Controller (tensor-core GEMM) + overlapped DNC — 143 blocks (64 DNC NJ=2, 79 NJ=8)
    ctrl_persist<<<143, 512, C_BYTES>>>(Whh_c, Wih_c, out);
}

// round 15
// speedup vs baseline: 3.3251x; 1.0238x over previous
#include <cuda_runtime.h>
#include <math.h>
#include <stdint.h>

// ---------------- problem constants ----------------
#define TT 256
#define BBATCH 64
#define HH 512
#define HC 759          // HID_C
#define G4C 3036        // 4*HID_C
#define G4E 2048        // 4*H
#define KCC 887         // HC + R*W
#define KPAD 896        // 28 * 32 ; K layout: [rv(128) | h(759) | pad]
#define WSTRIDE 900     // weight smem row stride
#define EPSF 1e-6f

// ---------------- device scratch ----------------
__device__ float g_XWe[(size_t)TT * BBATCH * G4E];
__device__ float g_EWc[(size_t)TT * BBATCH * G4C];
__device__ float g_enc[(size_t)TT * BBATCH * HH];
__device__ float g_he[2][BBATCH * HH];
__device__ float g_hc[2][BBATCH * HC];
__device__ float g_rv[BBATCH * 128];
__device__ unsigned g_ctrE;
__device__ volatile unsigned g_relE;
__device__ unsigned g_ctrC;
__device__ volatile unsigned g_relC;
__device__ unsigned g_rvCtr;
__device__ unsigned g_cnt0[128];        // gemm0 per-t-pair completion (32 n-blocks each)

__device__ __forceinline__ float sigmf_(float x) { return 1.f / (1.f + expf(-x)); }
__device__ __forceinline__ float softplusf_(float x) { return fmaxf(x, 0.f) + log1pf(expf(-fabsf(x))); }

// flag-release grid barrier (all blocks co-resident)
__device__ __forceinline__ void gbarF(unsigned* ctr, volatile unsigned* rel,
                                      unsigned nblk, unsigned epoch) {
    __syncthreads();
    if (threadIdx.x == 0) {
        __threadfence();
        unsigned a = atomicAdd(ctr, 1u);
        if (a == epoch * nblk + (nblk - 1u)) {
            *rel = epoch + 1u;
        } else {
            while (*rel < epoch + 1u) { }
        }
        __threadfence();
    }
    __syncthreads();
}

// ---------------- init ----------------
__global__ void init_states() {
    int i = blockIdx.x * blockDim.x + threadIdx.x;
    if (i == 0) { g_ctrE = 0u; g_relE = 0u; g_ctrC = 0u; g_relC = 0u; g_rvCtr = 0u; }
    if (i < 128) g_cnt0[i] = 0u;
    if (i < 2 * BBATCH * HH) ((float*)g_he)[i] = 0.f;
    if (i < 2 * BBATCH * HC) ((float*)g_hc)[i] = 0.f;
    if (i < BBATCH * 128)    g_rv[i] = 0.f;
}

// ---------------- tf32 helpers ----------------
__device__ __forceinline__ uint32_t f2tf32(float x) {
    uint32_t r;
    asm("cvt.rna.tf32.f32 %0, %1;" : "=r"(r) : "f"(x));
    return r;
}
__device__ __forceinline__ void split_tf32(float x, uint32_t& hi, uint32_t& lo) {
    hi = f2tf32(x);
    lo = f2tf32(x - __uint_as_float(hi));
}
__device__ __forceinline__ void mma_tf32(float& c0, float& c1, float& c2, float& c3,
                                         uint32_t a0, uint32_t a1, uint32_t a2, uint32_t a3,
                                         uint32_t b0, uint32_t b1) {
    asm volatile(
        "mma.sync.aligned.m16n8k8.row.col.f32.tf32.tf32.f32 "
        "{%0,%1,%2,%3}, {%4,%5,%6,%7}, {%8,%9}, {%0,%1,%2,%3};"
        : "+f"(c0), "+f"(c1), "+f"(c2), "+f"(c3)
        : "r"(a0), "r"(a1), "r"(a2), "r"(a3), "r"(b0), "r"(b1));
}

// ---------------- tensor-core input-projection GEMM (3xTF32) ----------------
// Grid: (n_blocks, 128). blockIdx.y = t-pair (m-block) so t-pairs complete in
// dispatch order. phase 1 spin-waits on encoder progress (g_relE) per t-pair.
#define GA_STRIDE 36
__global__ __launch_bounds__(256) void gemm_tc(const float* __restrict__ Ain,
                                               const float* __restrict__ Wt,
                                               const float* __restrict__ bias,
                                               int phase) {
    const int Ncols = phase ? G4C : G4E;
    const int ldw   = phase ? 640 : 512;
    float* C        = phase ? g_EWc : g_XWe;
    const float* A  = phase ? g_enc : Ain;

    __shared__ float As[128 * GA_STRIDE];
    __shared__ float Bs[64 * GA_STRIDE];

    int tid = threadIdx.x;
    int m0 = blockIdx.y * 128;
    int n0 = blockIdx.x * 64;
    int warp = tid >> 5, lane = tid & 31;
    int wm = warp & 3, wn = warp >> 2;

    // phase 1: wait until encoder has produced h for both t's of this m-block
    if (phase) {
        if (tid == 0) {
            unsigned need = 2u * blockIdx.y + 2u;
            while (g_relE < need) { }
        }
        __syncthreads();
    }

    const float* aptr[4];
    float* asmem[4];
#pragma unroll
    for (int i = 0; i < 4; i++) {
        int idx = tid + 256 * i;
        int row = idx >> 3, c4 = (idx & 7) * 4;
        int m = m0 + row;
        const float* arow;
        if (phase) arow = A + (size_t)m * 512;
        else { int t = m >> 6, b = m & 63; arow = A + ((size_t)b * TT + t) * 512; }
        aptr[i] = arow + c4;
        asmem[i] = As + row * GA_STRIDE + c4;
    }
    const float* bptr[2];
    float* bsmem[2];
    bool bok[2];
#pragma unroll
    for (int i = 0; i < 2; i++) {
        int idx = tid + 256 * i;
        int row = idx >> 3, c4 = (idx & 7) * 4;
        int n = n0 + row;
        bok[i] = (n < Ncols);
        bptr[i] = Wt + (size_t)(bok[i] ? n : 0) * ldw + c4;
        bsmem[i] = Bs + row * GA_STRIDE + c4;
    }

    float acc[2][4][4];
#pragma unroll
    for (int mf = 0; mf < 2; mf++)
#pragma unroll
        for (int nf = 0; nf < 4; nf++)
#pragma unroll
            for (int q = 0; q < 4; q++) acc[mf][nf][q] = 0.f;

    float4 ra[4], rb[2];
#pragma unroll
    for (int i = 0; i < 4; i++) ra[i] = *(const float4*)(aptr[i]);
#pragma unroll
    for (int i = 0; i < 2; i++)
        rb[i] = bok[i] ? *(const float4*)(bptr[i]) : make_float4(0.f, 0.f, 0.f, 0.f);

    int la = (lane >> 2);
    int lk = (lane & 3);

    for (int kc = 0; kc < 16; kc++) {
#pragma unroll
        for (int i = 0; i < 4; i++) *(float4*)(asmem[i]) = ra[i];
#pragma unroll
        for (int i = 0; i < 2; i++) *(float4*)(bsmem[i]) = rb[i];
        __syncthreads();

        if (kc < 15) {
            int k0 = (kc + 1) * 32;
#pragma unroll
            for (int i = 0; i < 4; i++) ra[i] = *(const float4*)(aptr[i] + k0);
#pragma unroll
            for (int i = 0; i < 2; i++)
                rb[i] = bok[i] ? *(const float4*)(bptr[i] + k0) : make_float4(0.f, 0.f, 0.f, 0.f);
        }

#pragma unroll
        for (int k8 = 0; k8 < 4; k8++) {
            int kcol = k8 * 8 + lk;
            uint32_t ah[2][4], al[2][4];
#pragma unroll
            for (int mf = 0; mf < 2; mf++) {
                int r = wm * 32 + mf * 16 + la;
                float v0 = As[r * GA_STRIDE + kcol];
                float v1 = As[(r + 8) * GA_STRIDE + kcol];
                float v2 = As[r * GA_STRIDE + kcol + 4];
                float v3 = As[(r + 8) * GA_STRIDE + kcol + 4];
                split_tf32(v0, ah[mf][0], al[mf][0]);
                split_tf32(v1, ah[mf][1], al[mf][1]);
                split_tf32(v2, ah[mf][2], al[mf][2]);
                split_tf32(v3, ah[mf][3], al[mf][3]);
            }
            uint32_t bh[4][2], bl[4][2];
#pragma unroll
            for (int nf = 0; nf < 4; nf++) {
                int bn = wn * 32 + nf * 8 + la;
                float v0 = Bs[bn * GA_STRIDE + k8 * 8 + lk];
                float v1 = Bs[bn * GA_STRIDE + k8 * 8 + lk + 4];
                split_tf32(v0, bh[nf][0], bl[nf][0]);
                split_tf32(v1, bh[nf][1], bl[nf][1]);
            }
#pragma unroll
            for (int mf = 0; mf < 2; mf++)
#pragma unroll
                for (int nf = 0; nf < 4; nf++) {
                    float* c = acc[mf][nf];
                    mma_tf32(c[0], c[1], c[2], c[3],
                             ah[mf][0], ah[mf][1], ah[mf][2], ah[mf][3],
                             bh[nf][0], bh[nf][1]);
                    mma_tf32(c[0], c[1], c[2], c[3],
                             ah[mf][0], ah[mf][1], ah[mf][2], ah[mf][3],
                             bl[nf][0], bl[nf][1]);
                    mma_tf32(c[0], c[1], c[2], c[3],
                             al[mf][0], al[mf][1], al[mf][2], al[mf][3],
                             bh[nf][0], bh[nf][1]);
                }
        }
        __syncthreads();
    }

#pragma unroll
    for (int mf = 0; mf < 2; mf++) {
        int r0 = m0 + wm * 32 + mf * 16 + la;
#pragma unroll
        for (int nf = 0; nf < 4; nf++) {
            int cb = n0 + wn * 32 + nf * 8 + lk * 2;
            float* c = acc[mf][nf];
            if (cb + 1 < Ncols) {
                float2 v0 = make_float2(c[0] + bias[cb], c[1] + bias[cb + 1]);
                float2 v1 = make_float2(c[2] + bias[cb], c[3] + bias[cb + 1]);
                *(float2*)&C[(size_t)r0 * Ncols + cb] = v0;
                *(float2*)&C[(size_t)(r0 + 8) * Ncols + cb] = v1;
            } else if (cb < Ncols) {
                C[(size_t)r0 * Ncols + cb] = c[0] + bias[cb];
                C[(size_t)(r0 + 8) * Ncols + cb] = c[2] + bias[cb];
            }
        }
    }

    // phase 0: publish per-t-pair completion for the encoder
    if (!phase) {
        __threadfence();
        __syncthreads();
        if (tid == 0) atomicAdd(&g_cnt0[blockIdx.y], 1u);
    }
}

// ---------------- persistent encoder: 128 blocks x 512 threads ----------------
#define E_WC 0
#define E_HS 8192
#define E_GS 16640
#define E_FLOATS 18720
#define E_BYTES (E_FLOATS * 4)

__global__ __launch_bounds__(512, 1) void enc_persist(const float* __restrict__ Whh_e) {
    extern __shared__ float dyn[];
    float* Wc = dyn + E_WC;
    float* hs = dyn + E_HS;
    float* gs = dyn + E_GS;

    int tid = threadIdx.x;
    int j0 = blockIdx.x * 4;

    for (int i = tid; i < 16 * 512; i += 512) {
        int lr = i >> 9, k = i & 511;
        int gate = lr >> 2, jj = lr & 3;
        Wc[i] = Whh_e[(size_t)(gate * HH + j0 + jj) * HH + k];
    }

    int g = tid >> 8;
    int t256 = tid & 255;
    int bb = t256 & 31;
    int ry = t256 >> 5;
    int lr0 = ry * 2;
    int kbase = g * 32;
    int kkr = tid & 63, blr = tid >> 6;
    int ebx = tid & 63, ejj = tid >> 6;
    float creg = 0.f;
    __syncthreads();

    for (int t = 0; t < TT; t++) {
        int par = t & 1;
        const float* hin = g_he[par];
        float* hout = g_he[par ^ 1];

        // wait until gemm0 finished this t-pair (overlapped producer)
        if (tid == 0) {
            while (*(volatile unsigned*)&g_cnt0[t >> 1] < 32u) { }
            __threadfence();
        }
        __syncthreads();

        float acc[2][2] = {{0.f, 0.f}, {0.f, 0.f}};
        if (g == 0) {
#pragma unroll
            for (int i2 = 0; i2 < 2; i2++)
#pragma unroll
                for (int r = 0; r < 2; r++) {
                    int lr = lr0 + r;
                    int gate = lr >> 2, jj = lr & 3;
                    acc[i2][r] = g_XWe[((size_t)t * BBATCH + 2 * bb + i2) * G4E + gate * HH + j0 + jj];
                }
        }

        float rg[8];
#pragma unroll
        for (int i = 0; i < 8; i++) rg[i] = hin[(blr + 8 * i) * HH + kkr];
#pragma unroll
        for (int i = 0; i < 8; i++) hs[kkr * 66 + blr + 8 * i] = rg[i];
        __syncthreads();

        for (int c = 0; c < 8; c++) {
            if (c < 7) {
#pragma unroll
                for (int i = 0; i < 8; i++)
                    rg[i] = hin[(blr + 8 * i) * HH + (c + 1) * 64 + kkr];
            }
            const float* hsb = hs + (c & 1) * 4224;
            const float* wp0 = Wc + lr0 * 512 + c * 64 + kbase;
            const float* wp1 = wp0 + 512;
#pragma unroll
            for (int k4 = 0; k4 < 32; k4 += 4) {
                float4 w0 = *(const float4*)(wp0 + k4);
                float4 w1 = *(const float4*)(wp1 + k4);
                float wa0[4] = {w0.x, w0.y, w0.z, w0.w};
                float wa1[4] = {w1.x, w1.y, w1.z, w1.w};
#pragma unroll
                for (int jq = 0; jq < 4; jq++) {
                    float2 h2 = *(const float2*)(hsb + (kbase + k4 + jq) * 66 + 2 * bb);
                    acc[0][0] += h2.x * wa0[jq]; acc[0][1] += h2.x * wa1[jq];
                    acc[1][0] += h2.y * wa0[jq]; acc[1][1] += h2.y * wa1[jq];
                }
            }
            if (c < 7) {
                float* hsn = hs + ((c + 1) & 1) * 4224;
#pragma unroll
                for (int i = 0; i < 8; i++) hsn[kkr * 66 + blr + 8 * i] = rg[i];
            }
            __syncthreads();
        }

#pragma unroll
        for (int i2 = 0; i2 < 2; i2++)
#pragma unroll
            for (int r = 0; r < 2; r++)
                gs[g * 1040 + (lr0 + r) * 65 + 2 * bb + i2] = acc[i2][r];
        __syncthreads();

        if (tid < 256) {
            int j = j0 + ejj;
            float gi = gs[ejj * 65 + ebx]        + gs[1040 + ejj * 65 + ebx];
            float gf = gs[(4 + ejj) * 65 + ebx]  + gs[1040 + (4 + ejj) * 65 + ebx];
            float gg = gs[(8 + ejj) * 65 + ebx]  + gs[1040 + (8 + ejj) * 65 + ebx];
            float go = gs[(12 + ejj) * 65 + ebx] + gs[1040 + (12 + ejj) * 65 + ebx];
            float cn = sigmf_(gf) * creg + sigmf_(gi) * tanhf(gg);
            creg = cn;
            float hn = sigmf_(go) * tanhf(cn);
            hout[ebx * HH + j] = hn;
            g_enc[((size_t)t * BBATCH + ebx) * HH + j] = hn;
        }

        gbarF(&g_ctrE, &g_relE, gridDim.x, (unsigned)t);
    }
}

// ---------------- persistent controller (tensor-core GEMM) + overlapped DNC ----------------
// 143 blocks x 512 threads. Blocks 0-63 (DNC): NJ=2. Blocks 64-142: NJ=8.
#define C_WC    0        // 32*900 = 28800
#define C_HS    28800    // 2 buf * 2 (hi,lo) * 64*36 = 9216
#define C_GS    38016    // 4160
#define C_LS    42176    // 64*65 = 4160
#define C_MS    46336    // 64*33 = 2112
#define C_WRS   48448
#define C_WRT   48704
#define C_US    48960
#define C_PS    49024
#define C_WWS   49088
#define C_XI    49152
#define C_AVEC  49408
#define C_CWV   49472
#define C_WWN   49536
#define C_RNORM 49600
#define C_RKN   49664
#define C_WKN   49792
#define C_MODES 49824
#define C_RED   49840
#define C_KNORM 49904
#define C_SWW   49912
#define C_FLOATS 49920
#define C_BYTES (C_FLOATS * 4)
#define HS_HALF 2304     // 64*36

__device__ __forceinline__ void mma_slab(const uint32_t* __restrict__ Hh,
                                         const uint32_t* __restrict__ Hl,
                                         const float* __restrict__ Wc,
                                         int kloc, int kg, int m0, int la, int lk,
                                         int ntbase, int nnt, float* acc) {
    uint32_t ah[4], al4[4];
    int r0 = (m0 + la) * 36 + kloc + lk;
    int r1 = (m0 + la + 8) * 36 + kloc + lk;
    ah[0] = Hh[r0];     ah[1] = Hh[r1];
    ah[2] = Hh[r0 + 4]; ah[3] = Hh[r1 + 4];
    al4[0] = Hl[r0];     al4[1] = Hl[r1];
    al4[2] = Hl[r0 + 4]; al4[3] = Hl[r1 + 4];
#pragma unroll
    for (int nt = 0; nt < 2; nt++) {
        if (nt >= nnt) break;
        int nr = ntbase + nt * 8 + la;
        float w0 = Wc[nr * WSTRIDE + kg + lk];
        float w1 = Wc[nr * WSTRIDE + kg + lk + 4];
        uint32_t bh0, bl0, bh1, bl1;
        split_tf32(w0, bh0, bl0);
        split_tf32(w1, bh1, bl1);
        float* c = acc + nt * 4;
        mma_tf32(c[0], c[1], c[2], c[3], ah[0], ah[1], ah[2], ah[3], bh0, bh1);
        mma_tf32(c[0], c[1], c[2], c[3], ah[0], ah[1], ah[2], ah[3], bl0, bl1);
        mma_tf32(c[0], c[1], c[2], c[3], al4[0], al4[1], al4[2], al4[3], bh0, bh1);
    }
}

__global__ __launch_bounds__(512, 1) void ctrl_persist(const float* __restrict__ Whh_c,
                                                       const float* __restrict__ Wih_c,
                                                       float* __restrict__ out) {
    extern __shared__ float dyn[];
    float* Wc    = dyn + C_WC;
    float* gsv   = dyn + C_GS;
    float* Ls    = dyn + C_LS;
    float* Ms    = dyn + C_MS;
    float* wrs   = dyn + C_WRS;
    float* wrtmp = dyn + C_WRT;
    float* us    = dyn + C_US;
    float* ps    = dyn + C_PS;
    float* wws   = dyn + C_WWS;
    float* xi    = dyn + C_XI;
    float* avec  = dyn + C_AVEC;
    float* cwv   = dyn + C_CWV;
    float* wwn   = dyn + C_WWN;
    float* rnorm = dyn + C_RNORM;
    float* rkn   = dyn + C_RKN;
    float* wkn   = dyn + C_WKN;
    float* modes = dyn + C_MODES;
    float* red   = dyn + C_RED;
    float* knorm = dyn + C_KNORM;
    float* sww   = dyn + C_SWW;

    int tid = threadIdx.x;
    bool isDnc = blockIdx.x < 64;
    int NJ = isDnc ? 2 : 8;
    int j0 = isDnc ? (int)blockIdx.x * 2 : 128 + ((int)blockIdx.x - 64) * 8;
    int rows = 4 * NJ;

    for (int i = tid; i < rows * WSTRIDE; i += 512) {
        int lr = i / WSTRIDE, k = i - lr * WSTRIDE;
        int gate = lr / NJ, jj = lr - gate * NJ;
        int j = j0 + jj;
        float v = 0.f;
        if (j < HC && k < KPAD) {
            int grow = gate * HC + j;
            if (k < 128) v = Wih_c[(size_t)grow * 640 + 512 + k];
            else { int kh = k - 128; if (kh < HC) v = Whh_c[(size_t)grow * HC + kh]; }
        }
        Wc[i] = v;
    }
    if (isDnc) {
        for (int i = tid; i < 64 * 65; i += 512) Ls[i] = 0.f;
        for (int i = tid; i < 64 * 33; i += 512) Ms[i] = 0.f;
        if (tid < 256) wrs[tid] = 0.f;
        if (tid < 64) { us[tid] = 0.f; ps[tid] = 0.f; wws[tid] = 0.f; }
    }

    int warp = tid >> 5, lane = tid & 31;
    int la = lane >> 2, lk = lane & 3;
    int wm = warp & 3;
    int m0 = wm * 16;
    int wn2 = (warp >> 2) & 1;
    int wkN = warp >> 3;
    int wkD = warp >> 2;
    int ntbase = isDnc ? 0 : wn2 * 16;
    int nnt = isDnc ? 1 : 2;
    int kk2 = tid & 31, brow = tid >> 5;
    int ebx = tid & 63, ejj = tid >> 6;
    float creg = 0.f;
    __syncthreads();

    for (int t = 0; t < TT; t++) {
        int par = t & 1;
        const float* hin = g_hc[par];
        float* hout = g_hc[par ^ 1];

        // ---------------- DNC(t-1) on blocks 0..63 ----------------
        if (isDnc && t > 0) {
            int b = blockIdx.x;
            const float* h = hin + b * HC;

            if (tid < 247) {
                float v = h[HH + tid];
                float a;
                if (tid < 128)      a = tanhf(v);
                else if (tid < 132) a = softplusf_(v);
                else if (tid < 164) a = tanhf(v);
                else if (tid < 165) a = softplusf_(v);
                else if (tid < 197) a = sigmf_(v);
                else if (tid < 229) a = tanhf(v);
                else if (tid < 235) a = sigmf_(v);
                else                a = v;
                xi[tid] = a;
            }
            __syncthreads();

            if (tid < 4) {
                float s = EPSF;
                for (int w = 0; w < 32; w++) { float k = xi[tid * 32 + w]; s += k * k; }
                knorm[tid] = rsqrtf(s);
            } else if (tid == 4) {
                float s = EPSF;
                for (int w = 0; w < 32; w++) { float k = xi[132 + w]; s += k * k; }
                knorm[4] = rsqrtf(s);
            } else if (tid >= 8 && tid < 12) {
                int r = tid - 8;
                float m0v = xi[235 + 3 * r], m1 = xi[236 + 3 * r], m2 = xi[237 + 3 * r];
                float mx = fmaxf(m0v, fmaxf(m1, m2));
                float e0 = expf(m0v - mx), e1 = expf(m1 - mx), e2 = expf(m2 - mx);
                float inv = 1.f / (e0 + e1 + e2);
                modes[r * 4 + 0] = e0 * inv; modes[r * 4 + 1] = e1 * inv; modes[r * 4 + 2] = e2 * inv;
            }
            if (tid >= 64 && tid < 128) {
                int n = tid - 64;
                float s = EPSF;
                for (int w = 0; w < 32; w++) { float m = Ms[n * 33 + w]; s += m * m; }
                rnorm[n] = rsqrtf(s);
            }
            __syncthreads();
            if (tid < 128)      { int r = tid >> 5, w = tid & 31; rkn[r * 32 + w] = xi[r * 32 + w] * knorm[r]; }
            else if (tid < 160) { int w = tid - 128; wkn[w] = xi[132 + w] * knorm[4]; }
            __syncthreads();

            if (tid < 32) {
                int ln = tid;
                float psi0 = 1.f, psi1 = 1.f;
#pragma unroll
                for (int r = 0; r < 4; r++) {
                    psi0 *= (1.f - xi[229 + r] * wrs[r * 64 + ln]);
                    psi1 *= (1.f - xi[229 + r] * wrs[r * 64 + ln + 32]);
                }
                float u0 = us[ln], u1 = us[ln + 32];
                float w0 = wws[ln], w1 = wws[ln + 32];
                float av = (u0 + w0 - u0 * w0) * psi0;
                float bv = (u1 + w1 - u1 * w1) * psi1;
                us[ln] = av; us[ln + 32] = bv;
                int ai = ln, bi = ln + 32;
#pragma unroll
                for (int k = 2; k <= 64; k <<= 1) {
#pragma unroll
                    for (int j = k >> 1; j > 0; j >>= 1) {
                        if (j >= 32) {
                            bool gt = (av > bv) || (av == bv && ai > bi);
                            if (gt) { float tv = av; av = bv; bv = tv; int ti = ai; ai = bi; bi = ti; }
                        } else {
                            float pav = __shfl_xor_sync(0xffffffffu, av, j);
                            int   pai = __shfl_xor_sync(0xffffffffu, ai, j);
                            float pbv = __shfl_xor_sync(0xffffffffu, bv, j);
                            int   pbi = __shfl_xor_sync(0xffffffffu, bi, j);
                            bool lower = ((ln & j) == 0);
                            bool upA = ((ln & k) == 0);
                            bool gtA = (av > pav) || (av == pav && ai > pai);
                            if ((lower == upA) ? gtA : !gtA) { av = pav; ai = pai; }
                            bool upB = (((ln + 32) & k) == 0);
                            bool gtB = (bv > pbv) || (bv == pbv && bi > pbi);
                            if ((lower == upB) ? gtB : !gtB) { bv = pbv; bi = pbi; }
                        }
                    }
                }
                float sa = av;
#pragma unroll
                for (int s = 1; s < 32; s <<= 1) {
                    float o = __shfl_up_sync(0xffffffffu, sa, s);
                    if (ln >= s) sa *= o;
                }
                float totA = __shfl_sync(0xffffffffu, sa, 31);
                float sb = bv;
#pragma unroll
                for (int s = 1; s < 32; s <<= 1) {
                    float o = __shfl_up_sync(0xffffffffu, sb, s);
                    if (ln >= s) sb *= o;
                }
                float prevA = __shfl_up_sync(0xffffffffu, sa, 1);
                float prevB = __shfl_up_sync(0xffffffffu, sb, 1);
                float exA = (ln == 0) ? 1.f : prevA;
                float exB = ((ln == 0) ? 1.f : prevB) * totA;
                avec[ai] = (1.f - av) * exA;
                avec[bi] = (1.f - bv) * exB;
            }
            float wstr = xi[164];
            if (tid >= 128 && tid < 192) {
                int n = tid - 128;
                float d = 0.f;
                for (int w = 0; w < 32; w++) d += wkn[w] * Ms[n * 33 + w];
                cwv[n] = d * rnorm[n] * wstr;
            }
            __syncthreads();

            if (tid < 32) {
                float x = fmaxf(cwv[tid], cwv[tid + 32]);
                for (int s = 16; s; s >>= 1) x = fmaxf(x, __shfl_xor_sync(0xffffffffu, x, s));
                if (tid == 0) red[0] = x;
            }
            __syncthreads();
            float cmx = red[0];
            __syncthreads();
            float ev = (tid < 64) ? expf(cwv[tid] - cmx) : 0.f;
            if (tid < 64) red[tid] = ev;
            __syncthreads();
            if (tid < 32) {
                float x = red[tid] + red[tid + 32];
                for (int s = 16; s; s >>= 1) x += __shfl_xor_sync(0xffffffffu, x, s);
                if (tid == 0) red[0] = x;
            }
            __syncthreads();
            if (tid < 64) cwv[tid] = ev / red[0];
            __syncthreads();

            float ag = xi[233], wg = xi[234];
            if (tid < 64) wwn[tid] = wg * (ag * avec[tid] + (1.f - ag) * cwv[tid]);
            __syncthreads();

            if (tid < 32) {
                float x = wwn[tid] + wwn[tid + 32];
                for (int s = 16; s; s >>= 1) x += __shfl_xor_sync(0xffffffffu, x, s);
                if (tid == 0) sww[0] = x;
            }

            for (int i = tid; i < 2048; i += 512) {
                int n = i >> 5, w = i & 31;
                float m = Ms[n * 33 + w];
                Ms[n * 33 + w] = m * (1.f - wwn[n] * xi[165 + w]) + wwn[n] * xi[197 + w];
            }
            for (int i = tid; i < 4096; i += 512) {
                int ii = i >> 6, jj = i & 63;
                float lv = (ii == jj) ? 0.f
                         : ((1.f - wwn[ii] - wwn[jj]) * Ls[ii * 65 + jj] + wwn[ii] * ps[jj]);
                Ls[ii * 65 + jj] = lv;
            }
            __syncthreads();

            if (tid < 64) ps[tid] = (1.f - sww[0]) * ps[tid] + wwn[tid];
            if (tid >= 64 && tid < 128) {
                int n = tid - 64;
                float s = EPSF;
                for (int w = 0; w < 32; w++) { float m = Ms[n * 33 + w]; s += m * m; }
                rnorm[n] = rsqrtf(s);
            }
            __syncthreads();

            int rr = (tid >> 6) & 3, nn = tid & 63;
            float pre = 0.f;
            {
                float d = 0.f;
                for (int w = 0; w < 32; w++) d += rkn[rr * 32 + w] * Ms[nn * 33 + w];
                pre = d * rnorm[nn] * xi[128 + rr];
            }
            float x = pre;
            for (int s = 16; s; s >>= 1) x = fmaxf(x, __shfl_xor_sync(0xffffffffu, x, s));
            if (tid < 256 && (tid & 31) == 0) red[tid >> 5] = x;
            __syncthreads();
            float gmx = fmaxf(red[rr * 2], red[rr * 2 + 1]);
            float e = expf(pre - gmx);
            __syncthreads();
            x = e;
            for (int s = 16; s; s >>= 1) x += __shfl_xor_sync(0xffffffffu, x, s);
            if (tid < 256 && (tid & 31) == 0) red[tid >> 5] = x;
            __syncthreads();
            float crv = e / (red[rr * 2] + red[rr * 2 + 1]);

            if (tid < 256) {
                float fwv = 0.f, bwv = 0.f;
                const float* wrow = wrs + rr * 64;
                for (int m = 0; m < 64; m++) {
                    float wv = wrow[m];
                    fwv += Ls[nn * 65 + m] * wv;
                    bwv += Ls[m * 65 + nn] * wv;
                }
                wrtmp[rr * 64 + nn] = modes[rr * 4 + 0] * bwv + modes[rr * 4 + 1] * crv + modes[rr * 4 + 2] * fwv;
            }
            __syncthreads();

            if (tid < 256) wrs[tid] = wrtmp[tid];
            if (tid < 64) wws[tid] = wwn[tid];
            if (tid >= 256 && tid < 384) {
                int r = (tid - 256) >> 5, w = tid & 31;
                float s = 0.f;
                for (int n = 0; n < 64; n++) s += wrtmp[r * 64 + n] * Ms[n * 33 + w];
                g_rv[b * 128 + r * 32 + w] = s;
            }
            __syncthreads();
            if (tid == 0) { __threadfence(); atomicAdd(&g_rvCtr, 1u); }
        }

        // ---------------- EWc prefetch ----------------
        float ew[4] = {0.f, 0.f, 0.f, 0.f};
        {
            bool act = (!isDnc) || (tid < 128);
            int j = j0 + ejj;
            if (act && j < HC) {
#pragma unroll
                for (int gate = 0; gate < 4; gate++)
                    ew[gate] = g_EWc[((size_t)t * BBATCH + ebx) * G4C + gate * HC + j];
            }
        }

        // ---------------- phase H: chunks 4..27 ----------------
        float acc[8];
#pragma unroll
        for (int q = 0; q < 8; q++) acc[q] = 0.f;

        float sv[4];
        {
            int kh = 4 * 32 + kk2 - 128;
#pragma unroll
            for (int i = 0; i < 4; i++) {
                int b = brow + 16 * i;
                sv[i] = (kh < HC) ? hin[b * HC + kh] : 0.f;
            }
        }
        {
            float* Hb = dyn + C_HS + (4 & 1) * (2 * HS_HALF);
#pragma unroll
            for (int i = 0; i < 4; i++) {
                uint32_t hb, lb;
                split_tf32(sv[i], hb, lb);
                Hb[(brow + 16 * i) * 36 + kk2] = __uint_as_float(hb);
                Hb[HS_HALF + (brow + 16 * i) * 36 + kk2] = __uint_as_float(lb);
            }
        }
        __syncthreads();

        for (int c = 4; c < 28; c++) {
            if (c < 27) {
                int kh = (c + 1) * 32 + kk2 - 128;
#pragma unroll
                for (int i = 0; i < 4; i++) {
                    int b = brow + 16 * i;
                    sv[i] = (kh < HC) ? hin[b * HC + kh] : 0.f;
                }
            }
            const uint32_t* Hh = (const uint32_t*)(dyn + C_HS + (c & 1) * (2 * HS_HALF));
            const uint32_t* Hl = Hh + HS_HALF;
            int kg0 = c * 32;
            if (isDnc) {
                mma_slab(Hh, Hl, Wc, wkD * 8, kg0 + wkD * 8, m0, la, lk, 0, 1, acc);
            } else {
                mma_slab(Hh, Hl, Wc, wkN * 16,     kg0 + wkN * 16,     m0, la, lk, ntbase, 2, acc);
                mma_slab(Hh, Hl, Wc, wkN * 16 + 8, kg0 + wkN * 16 + 8, m0, la, lk, ntbase, 2, acc);
            }
            if (c < 27) {
                float* Hb = dyn + C_HS + ((c + 1) & 1) * (2 * HS_HALF);
#pragma unroll
                for (int i = 0; i < 4; i++) {
                    uint32_t hb, lb;
                    split_tf32(sv[i], hb, lb);
                    Hb[(brow + 16 * i) * 36 + kk2] = __uint_as_float(hb);
                    Hb[HS_HALF + (brow + 16 * i) * 36 + kk2] = __uint_as_float(lb);
                }
            }
            __syncthreads();
        }

        // ---------------- wait for rv_{t-1} ----------------
        if (tid == 0) {
            while (*(volatile unsigned*)&g_rvCtr < 64u * (unsigned)t) { }
            __threadfence();
        }
        __syncthreads();

        // ---------------- phase RV: chunks 0..3 ----------------
        {
#pragma unroll
            for (int i = 0; i < 4; i++)
                sv[i] = g_rv[(brow + 16 * i) * 128 + kk2];
            float* Hb = dyn + C_HS;
#pragma unroll
            for (int i = 0; i < 4; i++) {
                uint32_t hb, lb;
                split_tf32(sv[i], hb, lb);
                Hb[(brow + 16 * i) * 36 + kk2] = __uint_as_float(hb);
                Hb[HS_HALF + (brow + 16 * i) * 36 + kk2] = __uint_as_float(lb);
            }
        }
        __syncthreads();
        for (int c = 0; c < 4; c++) {
            if (c < 3) {
#pragma unroll
                for (int i = 0; i < 4; i++)
                    sv[i] = g_rv[(brow + 16 * i) * 128 + (c + 1) * 32 + kk2];
            }
            const uint32_t* Hh = (const uint32_t*)(dyn + C_HS + (c & 1) * (2 * HS_HALF));
            const uint32_t* Hl = Hh + HS_HALF;
            int kg0 = c * 32;
            if (isDnc) {
                mma_slab(Hh, Hl, Wc, wkD * 8, kg0 + wkD * 8, m0, la, lk, 0, 1, acc);
            } else {
                mma_slab(Hh, Hl, Wc, wkN * 16,     kg0 + wkN * 16,     m0, la, lk, ntbase, 2, acc);
                mma_slab(Hh, Hl, Wc, wkN * 16 + 8, kg0 + wkN * 16 + 8, m0, la, lk, ntbase, 2, acc);
            }
            if (c < 3) {
                float* Hb = dyn + C_HS + ((c + 1) & 1) * (2 * HS_HALF);
#pragma unroll
                for (int i = 0; i < 4; i++) {
                    uint32_t hb, lb;
                    split_tf32(sv[i], hb, lb);
                    Hb[(brow + 16 * i) * 36 + kk2] = __uint_as_float(hb);
                    Hb[HS_HALF + (brow + 16 * i) * 36 + kk2] = __uint_as_float(lb);
                }
            }
            __syncthreads();
        }

        // ---------------- epilogue: C frags -> gsv ----------------
        {
            int kg = isDnc ? wkD : wkN;
            int gstride = isDnc ? 520 : 2080;
            float* gs = gsv + kg * gstride;
#pragma unroll
            for (int nt = 0; nt < 2; nt++) {
                if (nt >= nnt) break;
                int nrow0 = ntbase + nt * 8 + 2 * lk;
                float* c = acc + nt * 4;
                gs[nrow0 * 65 + m0 + la]           = c[0];
                gs[(nrow0 + 1) * 65 + m0 + la]     = c[1];
                gs[nrow0 * 65 + m0 + la + 8]       = c[2];
                gs[(nrow0 + 1) * 65 + m0 + la + 8] = c[3];
            }
        }
        __syncthreads();

        // ---------------- elementwise LSTM cell ----------------
        {
            bool act = (!isDnc) || (tid < 128);
            int j = j0 + ejj;
            if (act && j < HC) {
                float gv[4];
#pragma unroll
                for (int gate = 0; gate < 4; gate++) {
                    int row = gate * NJ + ejj;
                    float s = ew[gate];
                    if (isDnc)
                        s += gsv[row * 65 + ebx] + gsv[520 + row * 65 + ebx]
                           + gsv[1040 + row * 65 + ebx] + gsv[1560 + row * 65 + ebx];
                    else
                        s += gsv[row * 65 + ebx] + gsv[2080 + row * 65 + ebx];
                    gv[gate] = s;
                }
                float cn = sigmf_(gv[1]) * creg + sigmf_(gv[0]) * tanhf(gv[2]);
                creg = cn;
                float hn = sigmf_(gv[3]) * tanhf(cn);
                hout[ebx * HC + j] = hn;
                if (j < HH) out[((size_t)ebx * TT + t) * HH + j] = hn;
            }
        }

        gbarF(&g_ctrC, &g_relC, gridDim.x, (unsigned)t);
    }
}

// ---------------- launch ----------------
extern "C" void kernel_launch(void* const* d_in, const int* in_sizes, int n_in,
                              void* d_out, int out_size) {
    (void)in_sizes; (void)n_in; (void)out_size;
    const float* x     = (const float*)d_in[0];
    const float* Wih_e = (const float*)d_in[1];
    const float* Whh_e = (const float*)d_in[2];
    const float* b_e   = (const float*)d_in[3];
    const float* Wih_c = (const float*)d_in[4];
    const float* Whh_c = (const float*)d_in[5];
    const float* b_c   = (const float*)d_in[6];
    float* out = (float*)d_out;

    static int once = 0;
    static cudaStream_t s2;
    static cudaEvent_t evA, evC;
    if (!once) {
        cudaFuncSetAttribute(enc_persist, cudaFuncAttributeMaxDynamicSharedMemorySize, E_BYTES);
        cudaFuncSetAttribute(ctrl_persist, cudaFuncAttributeMaxDynamicSharedMemorySize, C_BYTES);
        cudaStreamCreateWithFlags(&s2, cudaStreamNonBlocking);
        cudaEventCreateWithFlags(&evA, cudaEventDisableTiming);
        cudaEventCreateWithFlags(&evC, cudaEventDisableTiming);
        once = 1;
    }

    init_states<<<1024, 256>>>();

    // fork: side stream starts after init
    cudaEventRecord(evA, 0);
    cudaStreamWaitEvent(s2, evA, 0);

    // Phase A on s2: x @ Wih_e^T + b_e (publishes per-t-pair counters)
    gemm_tc<<<dim3(32, 128), 256, 0, s2>>>(x, Wih_e, b_e, 0);

    // Encoder recurrence on default — spin-waits on gemm0 per t-pair
    enc_persist<<<128, 512, E_BYTES>>>(Whh_e);

    // Phase C on s2 (after gemm0 in-stream): enc @ Wih_c[:, :512]^T + b_c
    // — spin-waits on encoder progress (g_relE), so it overlaps enc's tail.
    gemm_tc<<<dim3(48, 128), 256, 0, s2>>>(nullptr, Wih_c, b_c, 1);

    // join: ctrl must start only after gemm1 fully done
    cudaEventRecord(evC, s2);
    cudaStreamWaitEvent(0, evC, 0);

    // Controller (tensor-core GEMM) + overlapped DNC
    ctrl_persist<<<143, 512, C_BYTES>>>(Whh_c, Wih_c, out);
}